// round 2
// baseline (speedup 1.0000x reference)
#include <cuda_runtime.h>
#include <math.h>

#define NN   8192
#define DIN  256
#define KC   8

// ---------------- scratch (device globals; no allocation allowed) ----------
__device__ float g_inp[NN * 256];     // F_ @ X
__device__ float g_h0 [NN * 256];
__device__ float g_h1 [NN * 128];
__device__ float g_n2 [NN];
__device__ float g_Fg [NN * KC];      // 65536
__device__ float g_part[256 * 1024];  // split-K partials for W_d0 GEMV
__device__ float g_d0 [1024];
__device__ float g_d1 [256];

// ---------------- generic tiled fp32 GEMM: C = act(A@B + bias) -------------
// A row-major [M,Kd], B row-major [Kd,Nn], C row-major [M,Nn]
// ACT: 0 = identity, 1 = tanh
template<int BM, int BN, int BK, int TM, int TN, int ACT>
__global__ void gemm_bias_act(const float* __restrict__ A,
                              const float* __restrict__ B,
                              const float* __restrict__ bias,
                              float* __restrict__ C,
                              int M, int Nn, int Kd)
{
    constexpr int THREADS = (BM / TM) * (BN / TN);
    __shared__ float As[BK][BM + 4];
    __shared__ float Bs[BK][BN];

    const int tid  = threadIdx.x;
    const int tcol = tid % (BN / TN);
    const int trow = tid / (BN / TN);
    const long bm = blockIdx.y, bn = blockIdx.x;

    float acc[TM][TN];
#pragma unroll
    for (int i = 0; i < TM; i++)
#pragma unroll
        for (int j = 0; j < TN; j++) acc[i][j] = 0.f;

    const float* Ab = A + (long)bm * BM * Kd;
    const float* Bb = B + bn * BN;

    for (int k0 = 0; k0 < Kd; k0 += BK) {
        // A tile: BM x BK, stored transposed As[k][row]
#pragma unroll
        for (int i = tid; i < BM * BK / 4; i += THREADS) {
            int r  = i / (BK / 4);
            int c4 = i % (BK / 4);
            float4 v = *(const float4*)(Ab + (long)r * Kd + k0 + c4 * 4);
            As[c4 * 4 + 0][r] = v.x;
            As[c4 * 4 + 1][r] = v.y;
            As[c4 * 4 + 2][r] = v.z;
            As[c4 * 4 + 3][r] = v.w;
        }
        // B tile: BK x BN
#pragma unroll
        for (int i = tid; i < BK * BN / 4; i += THREADS) {
            int r  = i / (BN / 4);
            int c4 = i % (BN / 4);
            *(float4*)&Bs[r][c4 * 4] =
                *(const float4*)(Bb + (long)(k0 + r) * Nn + c4 * 4);
        }
        __syncthreads();

#pragma unroll
        for (int k = 0; k < BK; k++) {
            float a[TM], b[TN];
#pragma unroll
            for (int i = 0; i < TM; i++) a[i] = As[k][trow * TM + i];
#pragma unroll
            for (int j = 0; j < TN; j++) b[j] = Bs[k][tcol * TN + j];
#pragma unroll
            for (int i = 0; i < TM; i++)
#pragma unroll
                for (int j = 0; j < TN; j++)
                    acc[i][j] = fmaf(a[i], b[j], acc[i][j]);
        }
        __syncthreads();
    }

#pragma unroll
    for (int i = 0; i < TM; i++) {
        long row = bm * BM + trow * TM + i;
#pragma unroll
        for (int j = 0; j < TN; j++) {
            int col = (int)bn * BN + tcol * TN + j;
            float v = acc[i][j];
            if (bias) v += bias[col];
            if (ACT == 1) v = tanhf(v);
            C[row * Nn + col] = v;
        }
    }
}

// ---------------- row-wise squared norms of E [NN,64] -----------------------
__global__ void n2_kernel(const float* __restrict__ E, float* __restrict__ n2)
{
    int row  = blockIdx.x * 8 + threadIdx.x / 32;
    int lane = threadIdx.x % 32;
    const float* e = E + (long)row * 64;
    float a = e[lane], b = e[lane + 32];
    float v = a * a + b * b;
#pragma unroll
    for (int off = 16; off; off >>= 1)
        v += __shfl_down_sync(0xffffffffu, v, off);
    if (lane == 0) n2[row] = v;
}

// ---------------- fused pairwise dist * path_forces -------------------------
// 128x128 output tile per block; D=64 in two 32-chunks. Exactly replicates:
//   sq = n2_i + n2_j - 2*G ; out = (sq>0 ? sqrt(sq) : 0) * pf
__global__ void dist_force_kernel(const float* __restrict__ E,
                                  const float* __restrict__ n2,
                                  const float* __restrict__ pf,
                                  float* __restrict__ Fo)
{
    __shared__ float Ei[32][132];
    __shared__ float Ej[32][132];

    const int tid  = threadIdx.x;
    const int tcol = tid % 16;
    const int trow = tid / 16;
    const int bi = blockIdx.y, bj = blockIdx.x;

    float acc[8][8];
#pragma unroll
    for (int i = 0; i < 8; i++)
#pragma unroll
        for (int j = 0; j < 8; j++) acc[i][j] = 0.f;

    for (int kc = 0; kc < 64; kc += 32) {
#pragma unroll
        for (int i = tid; i < 128 * 8; i += 256) {
            int r = i / 8, c4 = i % 8;
            float4 v = *(const float4*)(E + (long)(bi * 128 + r) * 64 + kc + c4 * 4);
            Ei[c4 * 4 + 0][r] = v.x; Ei[c4 * 4 + 1][r] = v.y;
            Ei[c4 * 4 + 2][r] = v.z; Ei[c4 * 4 + 3][r] = v.w;
        }
#pragma unroll
        for (int i = tid; i < 128 * 8; i += 256) {
            int r = i / 8, c4 = i % 8;
            float4 v = *(const float4*)(E + (long)(bj * 128 + r) * 64 + kc + c4 * 4);
            Ej[c4 * 4 + 0][r] = v.x; Ej[c4 * 4 + 1][r] = v.y;
            Ej[c4 * 4 + 2][r] = v.z; Ej[c4 * 4 + 3][r] = v.w;
        }
        __syncthreads();
#pragma unroll
        for (int k = 0; k < 32; k++) {
            float a[8], b[8];
#pragma unroll
            for (int i = 0; i < 8; i++) a[i] = Ei[k][trow * 8 + i];
#pragma unroll
            for (int j = 0; j < 8; j++) b[j] = Ej[k][tcol * 8 + j];
#pragma unroll
            for (int i = 0; i < 8; i++)
#pragma unroll
                for (int j = 0; j < 8; j++)
                    acc[i][j] = fmaf(a[i], b[j], acc[i][j]);
        }
        __syncthreads();
    }

    const int i0 = bi * 128 + trow * 8;
    const int j0 = bj * 128 + tcol * 8;
    float n2i[8], n2j[8];
#pragma unroll
    for (int ii = 0; ii < 8; ii++) n2i[ii] = n2[i0 + ii];
#pragma unroll
    for (int jj = 0; jj < 8; jj++) n2j[jj] = n2[j0 + jj];

#pragma unroll
    for (int ii = 0; ii < 8; ii++) {
        long i = i0 + ii;
        const float* pfr = pf + i * (long)NN + j0;
        float*       Fr  = Fo + i * (long)NN + j0;
        float o[8];
#pragma unroll
        for (int jj = 0; jj < 8; jj++) {
            float sq = n2i[ii] + n2j[jj] - 2.f * acc[ii][jj];
            float d  = (sq > 0.f) ? sqrtf(sq) : 0.f;
            o[jj] = d * pfr[jj];
        }
        *(float4*)(Fr)     = make_float4(o[0], o[1], o[2], o[3]);
        *(float4*)(Fr + 4) = make_float4(o[4], o[5], o[6], o[7]);
    }
}

// ---------------- Fg[i,k] = sum_j force[i,j] * members[j,k] -----------------
__global__ void fg_kernel(const float* __restrict__ Fo,
                          const float* __restrict__ members,
                          float* __restrict__ Fg)
{
    __shared__ float s[256 * 8];
    const int i = blockIdx.x;
    const float* Fr = Fo + (long)i * NN;
    float acc[8];
#pragma unroll
    for (int k = 0; k < 8; k++) acc[k] = 0.f;

    for (int j = threadIdx.x; j < NN; j += 256) {
        float f = Fr[j];
        float4 m0 = *(const float4*)(members + (long)j * 8);
        float4 m1 = *(const float4*)(members + (long)j * 8 + 4);
        acc[0] = fmaf(f, m0.x, acc[0]); acc[1] = fmaf(f, m0.y, acc[1]);
        acc[2] = fmaf(f, m0.z, acc[2]); acc[3] = fmaf(f, m0.w, acc[3]);
        acc[4] = fmaf(f, m1.x, acc[4]); acc[5] = fmaf(f, m1.y, acc[5]);
        acc[6] = fmaf(f, m1.z, acc[6]); acc[7] = fmaf(f, m1.w, acc[7]);
    }
#pragma unroll
    for (int k = 0; k < 8; k++) s[threadIdx.x * 8 + k] = acc[k];
    __syncthreads();
    for (int st = 128; st > 0; st >>= 1) {
        if (threadIdx.x < st) {
#pragma unroll
            for (int k = 0; k < 8; k++)
                s[threadIdx.x * 8 + k] += s[(threadIdx.x + st) * 8 + k];
        }
        __syncthreads();
    }
    if (threadIdx.x < 8) Fg[(long)i * 8 + threadIdx.x] = s[threadIdx.x];
}

// ---------------- d0 GEMV split-K: part[c][1024] = sum over 256-row chunk ---
__global__ void d0_partial_kernel(const float* __restrict__ Fg,
                                  const float* __restrict__ W,
                                  float* __restrict__ part)
{
    __shared__ float sF[256];
    const int c = blockIdx.x;           // 256 chunks of 256 rows
    const int t = threadIdx.x;          // 256 threads, 4 cols each (float4)
    sF[t] = Fg[c * 256 + t];
    __syncthreads();

    float4 acc = make_float4(0.f, 0.f, 0.f, 0.f);
    const float4* Wv = (const float4*)W + (long)(c * 256) * 256 + t;
    for (int r = 0; r < 256; r++) {
        float f = sF[r];
        float4 w = Wv[(long)r * 256];
        acc.x = fmaf(f, w.x, acc.x);
        acc.y = fmaf(f, w.y, acc.y);
        acc.z = fmaf(f, w.z, acc.z);
        acc.w = fmaf(f, w.w, acc.w);
    }
    ((float4*)part)[c * 256 + t] = acc;
}

__global__ void d0_reduce_kernel(const float* __restrict__ part,
                                 const float* __restrict__ bias,
                                 float* __restrict__ d0)
{
    const int col = threadIdx.x;        // 1024 threads
    float v = 0.f;
    for (int c = 0; c < 256; c++) v += part[c * 1024 + col];
    v += bias[col];
    d0[col] = fmaxf(v, 0.f);
}

// ---------------- d1 = relu(d0 @ W_d1 + b_d1): [1024] -> [256] --------------
__global__ void d1_kernel(const float* __restrict__ d0,
                          const float* __restrict__ W,
                          const float* __restrict__ bias,
                          float* __restrict__ d1)
{
    const int col = blockIdx.x * 32 + threadIdx.x % 32;
    const int rg  = threadIdx.x / 32;   // 8 row-groups
    float acc = 0.f;
    for (int r = rg; r < 1024; r += 8)
        acc = fmaf(d0[r], W[r * 256 + col], acc);
    __shared__ float s[8][32];
    s[rg][threadIdx.x % 32] = acc;
    __syncthreads();
    if (rg == 0) {
        float v = acc;
#pragma unroll
        for (int g = 1; g < 8; g++) v += s[g][threadIdx.x];
        v += bias[col];
        d1[col] = fmaxf(v, 0.f);
    }
}

// ---------------- final: softmax(d1 @ W_d2) -> out[8] -----------------------
__global__ void final_kernel(const float* __restrict__ d1,
                             const float* __restrict__ W,
                             float* __restrict__ out)
{
    const int lane = threadIdx.x;       // 32 threads
    float acc[8];
#pragma unroll
    for (int k = 0; k < 8; k++) acc[k] = 0.f;
    for (int r = lane; r < 256; r += 32) {
        float v = d1[r];
        const float* w = W + r * 8;
#pragma unroll
        for (int k = 0; k < 8; k++) acc[k] = fmaf(v, w[k], acc[k]);
    }
#pragma unroll
    for (int k = 0; k < 8; k++)
#pragma unroll
        for (int off = 16; off; off >>= 1)
            acc[k] += __shfl_down_sync(0xffffffffu, acc[k], off);
    if (lane == 0) {
        float mx = acc[0];
#pragma unroll
        for (int k = 1; k < 8; k++) mx = fmaxf(mx, acc[k]);
        float e[8], s = 0.f;
#pragma unroll
        for (int k = 0; k < 8; k++) { e[k] = expf(acc[k] - mx); s += e[k]; }
#pragma unroll
        for (int k = 0; k < 8; k++) out[k] = e[k] / s;
    }
}

// ---------------- launch ----------------------------------------------------
extern "C" void kernel_launch(void* const* d_in, const int* in_sizes, int n_in,
                              void* d_out, int out_size)
{
    const float* F_    = (const float*)d_in[0];
    const float* X     = (const float*)d_in[1];
    const float* W_e0  = (const float*)d_in[2];
    const float* b_e0  = (const float*)d_in[3];
    const float* W_e1  = (const float*)d_in[4];
    const float* b_e1  = (const float*)d_in[5];
    const float* W_e2  = (const float*)d_in[6];
    const float* b_e2  = (const float*)d_in[7];
    const float* W_d0  = (const float*)d_in[8];
    const float* b_d0  = (const float*)d_in[9];
    const float* W_d1  = (const float*)d_in[10];
    const float* b_d1  = (const float*)d_in[11];
    const float* W_d2  = (const float*)d_in[12];
    const float* pf    = (const float*)d_in[13];
    const float* memb  = (const float*)d_in[14];

    float* out    = (float*)d_out;
    float* E_out  = out;                                   // [8192,64]
    float* F_out  = out + (long)NN * 64;                   // [8192,8192]
    float* O_out  = out + (long)NN * 64 + (long)NN * NN;   // [8]

    float *p_inp, *p_h0, *p_h1, *p_n2, *p_Fg, *p_part, *p_d0, *p_d1;
    cudaGetSymbolAddress((void**)&p_inp,  g_inp);
    cudaGetSymbolAddress((void**)&p_h0,   g_h0);
    cudaGetSymbolAddress((void**)&p_h1,   g_h1);
    cudaGetSymbolAddress((void**)&p_n2,   g_n2);
    cudaGetSymbolAddress((void**)&p_Fg,   g_Fg);
    cudaGetSymbolAddress((void**)&p_part, g_part);
    cudaGetSymbolAddress((void**)&p_d0,   g_d0);
    cudaGetSymbolAddress((void**)&p_d1,   g_d1);

    // 1) inp = F_ @ X                      [8192,8192]x[8192,256]
    gemm_bias_act<128,128,16,8,8,0><<<dim3(256/128, NN/128), 256>>>(
        F_, X, nullptr, p_inp, NN, 256, NN);
    // 2) h0 = tanh(inp @ W_e0 + b_e0)      [8192,256]x[256,256]
    gemm_bias_act<128,128,16,8,8,1><<<dim3(256/128, NN/128), 256>>>(
        p_inp, W_e0, b_e0, p_h0, NN, 256, 256);
    // 3) h1 = tanh(h0 @ W_e1 + b_e1)       [8192,256]x[256,128]
    gemm_bias_act<128,128,16,8,8,1><<<dim3(128/128, NN/128), 256>>>(
        p_h0, W_e1, b_e1, p_h1, NN, 128, 256);
    // 4) E = h1 @ W_e2 + b_e2              [8192,128]x[128,64] -> d_out
    gemm_bias_act<128,64,16,8,4,0><<<dim3(64/64, NN/128), 256>>>(
        p_h1, W_e2, b_e2, E_out, NN, 64, 128);
    // 5) row norms
    n2_kernel<<<NN / 8, 256>>>(E_out, p_n2);
    // 6) new_force = dist(E) * pf          -> d_out
    dist_force_kernel<<<dim3(NN / 128, NN / 128), 256>>>(E_out, p_n2, pf, F_out);
    // 7) Fg = new_force @ members          [8192,8]
    fg_kernel<<<NN, 256>>>(F_out, memb, p_Fg);
    // 8) d0 = relu(Fg @ W_d0 + b_d0)       split-K GEMV
    d0_partial_kernel<<<256, 256>>>(p_Fg, W_d0, p_part);
    d0_reduce_kernel<<<1, 1024>>>(p_part, b_d0, p_d0);
    // 9) d1 = relu(d0 @ W_d1 + b_d1)
    d1_kernel<<<8, 256>>>(p_d0, W_d1, b_d1, p_d1);
    // 10) out = softmax(d1 @ W_d2)
    final_kernel<<<1, 32>>>(p_d1, W_d2, O_out);
}

// round 6
// speedup vs baseline: 1.7913x; 1.7913x over previous
#include <cuda_runtime.h>
#include <cuda_bf16.h>
#include <math.h>
#include <stdint.h>

#define NN   8192
#define KC   8

// ---------------- scratch (device globals; no allocation allowed) ----------
__device__ float g_inp[NN * 256];     // F_ @ X
__device__ float g_h0 [NN * 256];
__device__ float g_h1 [NN * 128];
__device__ float g_n2 [NN];
__device__ float g_Fg [NN * KC];
__device__ float g_part[256 * 1024];
__device__ float g_d0 [1024];
__device__ float g_d1 [256];
// bf16 hi/lo splits
__device__ __nv_bfloat16 g_Fh[(long)NN * NN];
__device__ __nv_bfloat16 g_Fl[(long)NN * NN];
__device__ __nv_bfloat16 g_Xth[256 * NN];   // X^T hi  [256, 8192]
__device__ __nv_bfloat16 g_Xtl[256 * NN];   // X^T lo
__device__ __nv_bfloat16 g_Eh[NN * 64];
__device__ __nv_bfloat16 g_El[NN * 64];

// ================= PTX helpers (baseline PTX only, no 'a' features) ========
__device__ __forceinline__ uint32_t smem_to_u32(const void* p) {
    uint32_t a;
    asm("{ .reg .u64 t; cvta.to.shared.u64 t, %1; cvt.u32.u64 %0, t; }"
        : "=r"(a) : "l"(p));
    return a;
}
__device__ __forceinline__ void cpasync16(uint32_t dst, const void* src) {
    asm volatile("cp.async.cg.shared.global [%0], [%1], 16;" :: "r"(dst), "l"(src));
}
#define CPASYNC_COMMIT()    asm volatile("cp.async.commit_group;" ::: "memory")
#define CPASYNC_WAIT(n)     asm volatile("cp.async.wait_group %0;" :: "n"(n) : "memory")

__device__ __forceinline__ void ldsm_x4(uint32_t* r, uint32_t addr) {
    asm volatile("ldmatrix.sync.aligned.m8n8.x4.shared.b16 {%0,%1,%2,%3}, [%4];"
                 : "=r"(r[0]), "=r"(r[1]), "=r"(r[2]), "=r"(r[3]) : "r"(addr));
}
__device__ __forceinline__ void ldsm_x2(uint32_t* r, uint32_t addr) {
    asm volatile("ldmatrix.sync.aligned.m8n8.x2.shared.b16 {%0,%1}, [%2];"
                 : "=r"(r[0]), "=r"(r[1]) : "r"(addr));
}
// D = A@B + D ; A row-major frag (4 regs), B col-major frag (2 regs), f32 acc
__device__ __forceinline__ void mma16816(float* c, const uint32_t* a, const uint32_t* b) {
    asm volatile("mma.sync.aligned.m16n8k16.row.col.f32.bf16.bf16.f32 "
                 "{%0,%1,%2,%3}, {%4,%5,%6,%7}, {%8,%9}, {%0,%1,%2,%3};"
                 : "+f"(c[0]), "+f"(c[1]), "+f"(c[2]), "+f"(c[3])
                 : "r"(a[0]), "r"(a[1]), "r"(a[2]), "r"(a[3]), "r"(b[0]), "r"(b[1]));
}

// ================= split pre-pass kernels ===================================
__global__ void fsplit_kernel(const float4* __restrict__ F,
                              uint2* __restrict__ Fh, uint2* __restrict__ Fl)
{
    long i = (long)blockIdx.x * 256 + threadIdx.x;   // 16,777,216 float4s
    float4 v = F[i];
    __nv_bfloat162 h01 = __floats2bfloat162_rn(v.x, v.y);
    __nv_bfloat162 h23 = __floats2bfloat162_rn(v.z, v.w);
    float2 f01 = __bfloat1622float2(h01);
    float2 f23 = __bfloat1622float2(h23);
    __nv_bfloat162 l01 = __floats2bfloat162_rn(v.x - f01.x, v.y - f01.y);
    __nv_bfloat162 l23 = __floats2bfloat162_rn(v.z - f23.x, v.w - f23.y);
    uint2 ho, lo;
    ho.x = *(uint32_t*)&h01; ho.y = *(uint32_t*)&h23;
    lo.x = *(uint32_t*)&l01; lo.y = *(uint32_t*)&l23;
    Fh[i] = ho; Fl[i] = lo;
}

// X [8192,256] -> Xt hi/lo [256,8192]
__global__ void xsplit_kernel(const float* __restrict__ X,
                              __nv_bfloat16* __restrict__ Xh,
                              __nv_bfloat16* __restrict__ Xl)
{
    __shared__ float t[32][33];
    int bx = blockIdx.x * 32;   // din
    int by = blockIdx.y * 32;   // n
    for (int i = threadIdx.y; i < 32; i += 8)
        t[i][threadIdx.x] = X[(long)(by + i) * 256 + bx + threadIdx.x];
    __syncthreads();
    for (int i = threadIdx.y; i < 32; i += 8) {
        float v = t[threadIdx.x][i];            // = X[by+tx][bx+i]
        __nv_bfloat16 h = __float2bfloat16(v);
        __nv_bfloat16 l = __float2bfloat16(v - __bfloat162float(h));
        long o = (long)(bx + i) * NN + by + threadIdx.x;
        Xh[o] = h; Xl[o] = l;
    }
}

// E [8192,64] fp32 -> Eh/El bf16
__global__ void esplit_kernel(const float2* __restrict__ E,
                              uint32_t* __restrict__ Eh, uint32_t* __restrict__ El)
{
    long i = (long)blockIdx.x * 256 + threadIdx.x;   // 262,144 float2s
    float2 v = E[i];
    __nv_bfloat162 h = __floats2bfloat162_rn(v.x, v.y);
    float2 hf = __bfloat1622float2(h);
    __nv_bfloat162 l = __floats2bfloat162_rn(v.x - hf.x, v.y - hf.y);
    Eh[i] = *(uint32_t*)&h;
    El[i] = *(uint32_t*)&l;
}

// ================= GEMM1 (HMMA): C[8192,256] = F_ @ X, bf16x3 ==============
// 128x128 tile, BK=32, 4-stage cp.async pipeline, 8 warps (2m x 4n), warp 64x32.
#define G1_SA     80                      // smem row stride bytes (32 bf16 + pad), 5*16
#define G1_BUF    (128 * G1_SA)           // 10240 B per operand buffer
#define G1_STAGE  (4 * G1_BUF)            // Ah | Al | Bh | Bl
#define G1_SMEM   (4 * G1_STAGE)          // 4 stages = 163840 B

__global__ void __launch_bounds__(256, 1) gemm1_mma(
    const __nv_bfloat16* __restrict__ Ah_, const __nv_bfloat16* __restrict__ Al_,
    const __nv_bfloat16* __restrict__ Bh_, const __nv_bfloat16* __restrict__ Bl_,
    float* __restrict__ C)
{
    extern __shared__ char smem[];
    const uint32_t sb = smem_to_u32(smem);
    const int tid = threadIdx.x, lane = tid & 31, wid = tid >> 5;
    const int wm = wid >> 2, wn = wid & 3;
    const int mg0 = blockIdx.y * 128, ng0 = blockIdx.x * 128;

    // ldmatrix lane address components
    const uint32_t aRow = wm * 64 + (lane & 7) + ((lane >> 3) & 1) * 8; // + mt*16
    const uint32_t aCol = (lane >> 4) * 16;                             // + ks*32
    const uint32_t bRow = wn * 32 + (lane & 7);                         // + nt*8
    const uint32_t bCol = ((lane >> 3) & 1) * 16;                       // + ks*32

    float acc[4][4][4];
#pragma unroll
    for (int mt = 0; mt < 4; mt++)
#pragma unroll
        for (int nt = 0; nt < 4; nt++)
#pragma unroll
            for (int q = 0; q < 4; q++) acc[mt][nt][q] = 0.f;

    auto load_stage = [&](int s) {
        uint32_t base = sb + (s & 3) * G1_STAGE;
        long k0 = (long)s * 32;
#pragma unroll
        for (int h = 0; h < 2; h++) {
            int c = tid + h * 256;          // 512 16B chunks per buffer
            int row = c >> 2, seg = c & 3;
            uint32_t d = base + row * G1_SA + seg * 16;
            long ga = (long)(mg0 + row) * NN + k0 + seg * 8;
            long gb = (long)(ng0 + row) * NN + k0 + seg * 8;
            cpasync16(d,              Ah_ + ga);
            cpasync16(d + G1_BUF,     Al_ + ga);
            cpasync16(d + 2 * G1_BUF, Bh_ + gb);
            cpasync16(d + 3 * G1_BUF, Bl_ + gb);
        }
        CPASYNC_COMMIT();
    };

    load_stage(0); load_stage(1); load_stage(2);

    const int nStages = NN / 32;            // 256
    for (int it = 0; it < nStages; it++) {
        CPASYNC_WAIT(2);                     // stage `it` complete
        __syncthreads();
        if (it + 3 < nStages) load_stage(it + 3);   // buffer (it-1)&3, free

        const uint32_t base = sb + (it & 3) * G1_STAGE;
#pragma unroll
        for (int ks = 0; ks < 2; ks++) {
            uint32_t bh[4][2], bl[4][2];
#pragma unroll
            for (int nt = 0; nt < 4; nt++) {
                uint32_t bo = base + 2 * G1_BUF + (bRow + nt * 8) * G1_SA + ks * 32 + bCol;
                ldsm_x2(bh[nt], bo);
                ldsm_x2(bl[nt], bo + G1_BUF);
            }
#pragma unroll
            for (int mt = 0; mt < 4; mt++) {
                uint32_t ah[4], al[4];
                uint32_t ao = base + (aRow + mt * 16) * G1_SA + ks * 32 + aCol;
                ldsm_x4(ah, ao);
                ldsm_x4(al, ao + G1_BUF);
#pragma unroll
                for (int nt = 0; nt < 4; nt++) {
                    mma16816(acc[mt][nt], ah, bh[nt]);
                    mma16816(acc[mt][nt], ah, bl[nt]);
                    mma16816(acc[mt][nt], al, bh[nt]);
                }
            }
        }
    }

    // epilogue
    const int r0 = mg0 + wm * 64 + (lane >> 2);
    const int c0 = ng0 + wn * 32 + (lane & 3) * 2;
#pragma unroll
    for (int mt = 0; mt < 4; mt++) {
#pragma unroll
        for (int nt = 0; nt < 4; nt++) {
            long r = r0 + mt * 16;
            int  col = c0 + nt * 8;
            *(float2*)&C[r * 256 + col]       = make_float2(acc[mt][nt][0], acc[mt][nt][1]);
            *(float2*)&C[(r + 8) * 256 + col] = make_float2(acc[mt][nt][2], acc[mt][nt][3]);
        }
    }
}

// ================= dist (HMMA): force = sqrt(n2i+n2j-2*E@E^T)+ * pf =========
// 128x128 tile, K=64 single shot, bf16x3.
#define DS_SA    144                      // 64 bf16 (128B) + 16B pad  (9*16 -> aligned)
#define DS_BUF   (128 * DS_SA)            // 18432
#define DS_SMEM  (4 * DS_BUF)             // EhI | ElI | EhJ | ElJ = 73728

__global__ void __launch_bounds__(256, 1) dist_mma(
    const __nv_bfloat16* __restrict__ Eh, const __nv_bfloat16* __restrict__ El,
    const float* __restrict__ n2, const float* __restrict__ pf,
    float* __restrict__ Fo)
{
    extern __shared__ char smem[];
    const uint32_t sb = smem_to_u32(smem);
    const int tid = threadIdx.x, lane = tid & 31, wid = tid >> 5;
    const int wm = wid >> 2, wn = wid & 3;
    const int i0 = blockIdx.y * 128, j0 = blockIdx.x * 128;

#pragma unroll
    for (int h = 0; h < 4; h++) {
        int c = tid + h * 256;              // 1024 16B chunks per buffer
        int row = c >> 3, seg = c & 7;
        uint32_t d = sb + row * DS_SA + seg * 16;
        long gi = (long)(i0 + row) * 64 + seg * 8;
        long gj = (long)(j0 + row) * 64 + seg * 8;
        cpasync16(d,              Eh + gi);
        cpasync16(d + DS_BUF,     El + gi);
        cpasync16(d + 2 * DS_BUF, Eh + gj);
        cpasync16(d + 3 * DS_BUF, El + gj);
    }
    CPASYNC_COMMIT();
    CPASYNC_WAIT(0);
    __syncthreads();

    const uint32_t aRow = wm * 64 + (lane & 7) + ((lane >> 3) & 1) * 8;
    const uint32_t aCol = (lane >> 4) * 16;
    const uint32_t bRow = wn * 32 + (lane & 7);
    const uint32_t bCol = ((lane >> 3) & 1) * 16;

    float acc[4][4][4];
#pragma unroll
    for (int mt = 0; mt < 4; mt++)
#pragma unroll
        for (int nt = 0; nt < 4; nt++)
#pragma unroll
            for (int q = 0; q < 4; q++) acc[mt][nt][q] = 0.f;

#pragma unroll
    for (int ks = 0; ks < 4; ks++) {
        uint32_t bh[4][2], bl[4][2];
#pragma unroll
        for (int nt = 0; nt < 4; nt++) {
            uint32_t bo = sb + 2 * DS_BUF + (bRow + nt * 8) * DS_SA + ks * 32 + bCol;
            ldsm_x2(bh[nt], bo);
            ldsm_x2(bl[nt], bo + DS_BUF);
        }
#pragma unroll
        for (int mt = 0; mt < 4; mt++) {
            uint32_t ah[4], al[4];
            uint32_t ao = sb + (aRow + mt * 16) * DS_SA + ks * 32 + aCol;
            ldsm_x4(ah, ao);
            ldsm_x4(al, ao + DS_BUF);
#pragma unroll
            for (int nt = 0; nt < 4; nt++) {
                mma16816(acc[mt][nt], ah, bh[nt]);
                mma16816(acc[mt][nt], ah, bl[nt]);
                mma16816(acc[mt][nt], al, bh[nt]);
            }
        }
    }

    // epilogue: sq = n2i + n2j - 2*dot ; d = sq>0 ? sqrt(sq) : 0 ; out = d*pf
    const int ri = i0 + wm * 64 + (lane >> 2);
    const int cj = j0 + wn * 32 + (lane & 3) * 2;
#pragma unroll
    for (int mt = 0; mt < 4; mt++) {
        int ia = ri + mt * 16;
        float n2a = n2[ia], n2b = n2[ia + 8];
#pragma unroll
        for (int nt = 0; nt < 4; nt++) {
            int j = cj + nt * 8;
            float nj0 = n2[j], nj1 = n2[j + 1];
            float2 p0 = *(const float2*)&pf[(long)ia * NN + j];
            float2 p1 = *(const float2*)&pf[(long)(ia + 8) * NN + j];
            float* a = acc[mt][nt];
            float s00 = n2a + nj0 - 2.f * a[0];
            float s01 = n2a + nj1 - 2.f * a[1];
            float s10 = n2b + nj0 - 2.f * a[2];
            float s11 = n2b + nj1 - 2.f * a[3];
            float d00 = (s00 > 0.f) ? sqrtf(s00) : 0.f;
            float d01 = (s01 > 0.f) ? sqrtf(s01) : 0.f;
            float d10 = (s10 > 0.f) ? sqrtf(s10) : 0.f;
            float d11 = (s11 > 0.f) ? sqrtf(s11) : 0.f;
            *(float2*)&Fo[(long)ia * NN + j]       = make_float2(d00 * p0.x, d01 * p0.y);
            *(float2*)&Fo[(long)(ia + 8) * NN + j] = make_float2(d10 * p1.x, d11 * p1.y);
        }
    }
}

// ---------------- generic tiled fp32 GEMM: C = act(A@B + bias) -------------
template<int BM, int BN, int BK, int TM, int TN, int ACT>
__global__ void gemm_bias_act(const float* __restrict__ A,
                              const float* __restrict__ B,
                              const float* __restrict__ bias,
                              float* __restrict__ C,
                              int M, int Nn, int Kd)
{
    constexpr int THREADS = (BM / TM) * (BN / TN);
    __shared__ float As[BK][BM + 4];
    __shared__ float Bs[BK][BN];

    const int tid  = threadIdx.x;
    const int tcol = tid % (BN / TN);
    const int trow = tid / (BN / TN);
    const long bm = blockIdx.y, bn = blockIdx.x;

    float acc[TM][TN];
#pragma unroll
    for (int i = 0; i < TM; i++)
#pragma unroll
        for (int j = 0; j < TN; j++) acc[i][j] = 0.f;

    const float* Ab = A + (long)bm * BM * Kd;
    const float* Bb = B + bn * BN;

    for (int k0 = 0; k0 < Kd; k0 += BK) {
#pragma unroll
        for (int i = tid; i < BM * BK / 4; i += THREADS) {
            int r  = i / (BK / 4);
            int c4 = i % (BK / 4);
            float4 v = *(const float4*)(Ab + (long)r * Kd + k0 + c4 * 4);
            As[c4 * 4 + 0][r] = v.x;
            As[c4 * 4 + 1][r] = v.y;
            As[c4 * 4 + 2][r] = v.z;
            As[c4 * 4 + 3][r] = v.w;
        }
#pragma unroll
        for (int i = tid; i < BK * BN / 4; i += THREADS) {
            int r  = i / (BN / 4);
            int c4 = i % (BN / 4);
            *(float4*)&Bs[r][c4 * 4] =
                *(const float4*)(Bb + (long)(k0 + r) * Nn + c4 * 4);
        }
        __syncthreads();

#pragma unroll
        for (int k = 0; k < BK; k++) {
            float a[TM], b[TN];
#pragma unroll
            for (int i = 0; i < TM; i++) a[i] = As[k][trow * TM + i];
#pragma unroll
            for (int j = 0; j < TN; j++) b[j] = Bs[k][tcol * TN + j];
#pragma unroll
            for (int i = 0; i < TM; i++)
#pragma unroll
                for (int j = 0; j < TN; j++)
                    acc[i][j] = fmaf(a[i], b[j], acc[i][j]);
        }
        __syncthreads();
    }

#pragma unroll
    for (int i = 0; i < TM; i++) {
        long row = bm * BM + trow * TM + i;
#pragma unroll
        for (int j = 0; j < TN; j++) {
            int col = (int)bn * BN + tcol * TN + j;
            float v = acc[i][j];
            if (bias) v += bias[col];
            if (ACT == 1) v = tanhf(v);
            C[row * Nn + col] = v;
        }
    }
}

// ---------------- row-wise squared norms of E [NN,64] -----------------------
__global__ void n2_kernel(const float* __restrict__ E, float* __restrict__ n2)
{
    int row  = blockIdx.x * 8 + threadIdx.x / 32;
    int lane = threadIdx.x % 32;
    const float* e = E + (long)row * 64;
    float a = e[lane], b = e[lane + 32];
    float v = a * a + b * b;
#pragma unroll
    for (int off = 16; off; off >>= 1)
        v += __shfl_down_sync(0xffffffffu, v, off);
    if (lane == 0) n2[row] = v;
}

// ---------------- Fg[i,k] = sum_j force[i,j] * members[j,k] -----------------
__global__ void fg_kernel(const float* __restrict__ Fo,
                          const float* __restrict__ members,
                          float* __restrict__ Fg)
{
    __shared__ float s[256 * 8];
    const int i = blockIdx.x;
    const float* Fr = Fo + (long)i * NN;
    float acc[8];
#pragma unroll
    for (int k = 0; k < 8; k++) acc[k] = 0.f;

    for (int j = threadIdx.x; j < NN; j += 256) {
        float f = Fr[j];
        float4 m0 = *(const float4*)(members + (long)j * 8);
        float4 m1 = *(const float4*)(members + (long)j * 8 + 4);
        acc[0] = fmaf(f, m0.x, acc[0]); acc[1] = fmaf(f, m0.y, acc[1]);
        acc[2] = fmaf(f, m0.z, acc[2]); acc[3] = fmaf(f, m0.w, acc[3]);
        acc[4] = fmaf(f, m1.x, acc[4]); acc[5] = fmaf(f, m1.y, acc[5]);
        acc[6] = fmaf(f, m1.z, acc[6]); acc[7] = fmaf(f, m1.w, acc[7]);
    }
#pragma unroll
    for (int k = 0; k < 8; k++) s[threadIdx.x * 8 + k] = acc[k];
    __syncthreads();
    for (int st = 128; st > 0; st >>= 1) {
        if (threadIdx.x < st) {
#pragma unroll
            for (int k = 0; k < 8; k++)
                s[threadIdx.x * 8 + k] += s[(threadIdx.x + st) * 8 + k];
        }
        __syncthreads();
    }
    if (threadIdx.x < 8) Fg[(long)i * 8 + threadIdx.x] = s[threadIdx.x];
}

// ---------------- d0 GEMV split-K -------------------------------------------
__global__ void d0_partial_kernel(const float* __restrict__ Fg,
                                  const float* __restrict__ W,
                                  float* __restrict__ part)
{
    __shared__ float sF[256];
    const int c = blockIdx.x;
    const int t = threadIdx.x;
    sF[t] = Fg[c * 256 + t];
    __syncthreads();

    float4 acc = make_float4(0.f, 0.f, 0.f, 0.f);
    const float4* Wv = (const float4*)W + (long)(c * 256) * 256 + t;
    for (int r = 0; r < 256; r++) {
        float f = sF[r];
        float4 w = Wv[(long)r * 256];
        acc.x = fmaf(f, w.x, acc.x);
        acc.y = fmaf(f, w.y, acc.y);
        acc.z = fmaf(f, w.z, acc.z);
        acc.w = fmaf(f, w.w, acc.w);
    }
    ((float4*)part)[c * 256 + t] = acc;
}

__global__ void d0_reduce_kernel(const float* __restrict__ part,
                                 const float* __restrict__ bias,
                                 float* __restrict__ d0)
{
    const int col = threadIdx.x;
    float v = 0.f;
    for (int c = 0; c < 256; c++) v += part[c * 1024 + col];
    v += bias[col];
    d0[col] = fmaxf(v, 0.f);
}

// ---------------- d1 = relu(d0 @ W_d1 + b_d1) --------------------------------
__global__ void d1_kernel(const float* __restrict__ d0,
                          const float* __restrict__ W,
                          const float* __restrict__ bias,
                          float* __restrict__ d1)
{
    const int col = blockIdx.x * 32 + threadIdx.x % 32;
    const int rg  = threadIdx.x / 32;
    float acc = 0.f;
    for (int r = rg; r < 1024; r += 8)
        acc = fmaf(d0[r], W[r * 256 + col], acc);
    __shared__ float s[8][32];
    s[rg][threadIdx.x % 32] = acc;
    __syncthreads();
    if (rg == 0) {
        float v = acc;
#pragma unroll
        for (int g = 1; g < 8; g++) v += s[g][threadIdx.x];
        v += bias[col];
        d1[col] = fmaxf(v, 0.f);
    }
}

// ---------------- final: softmax(d1 @ W_d2) ----------------------------------
__global__ void final_kernel(const float* __restrict__ d1,
                             const float* __restrict__ W,
                             float* __restrict__ out)
{
    const int lane = threadIdx.x;
    float acc[8];
#pragma unroll
    for (int k = 0; k < 8; k++) acc[k] = 0.f;
    for (int r = lane; r < 256; r += 32) {
        float v = d1[r];
        const float* w = W + r * 8;
#pragma unroll
        for (int k = 0; k < 8; k++) acc[k] = fmaf(v, w[k], acc[k]);
    }
#pragma unroll
    for (int k = 0; k < 8; k++)
#pragma unroll
        for (int off = 16; off; off >>= 1)
            acc[k] += __shfl_down_sync(0xffffffffu, acc[k], off);
    if (lane == 0) {
        float mx = acc[0];
#pragma unroll
        for (int k = 1; k < 8; k++) mx = fmaxf(mx, acc[k]);
        float e[8], s = 0.f;
#pragma unroll
        for (int k = 0; k < 8; k++) { e[k] = expf(acc[k] - mx); s += e[k]; }
#pragma unroll
        for (int k = 0; k < 8; k++) out[k] = e[k] / s;
    }
}

// ---------------- launch ----------------------------------------------------
extern "C" void kernel_launch(void* const* d_in, const int* in_sizes, int n_in,
                              void* d_out, int out_size)
{
    const float* F_    = (const float*)d_in[0];
    const float* X     = (const float*)d_in[1];
    const float* W_e0  = (const float*)d_in[2];
    const float* b_e0  = (const float*)d_in[3];
    const float* W_e1  = (const float*)d_in[4];
    const float* b_e1  = (const float*)d_in[5];
    const float* W_e2  = (const float*)d_in[6];
    const float* b_e2  = (const float*)d_in[7];
    const float* W_d0  = (const float*)d_in[8];
    const float* b_d0  = (const float*)d_in[9];
    const float* W_d1  = (const float*)d_in[10];
    const float* b_d1  = (const float*)d_in[11];
    const float* W_d2  = (const float*)d_in[12];
    const float* pf    = (const float*)d_in[13];
    const float* memb  = (const float*)d_in[14];

    float* out    = (float*)d_out;
    float* E_out  = out;
    float* F_out  = out + (long)NN * 64;
    float* O_out  = out + (long)NN * 64 + (long)NN * NN;

    float *p_inp, *p_h0, *p_h1, *p_n2, *p_Fg, *p_part, *p_d0, *p_d1;
    __nv_bfloat16 *p_Fh, *p_Fl, *p_Xth, *p_Xtl, *p_Eh, *p_El;
    cudaGetSymbolAddress((void**)&p_inp,  g_inp);
    cudaGetSymbolAddress((void**)&p_h0,   g_h0);
    cudaGetSymbolAddress((void**)&p_h1,   g_h1);
    cudaGetSymbolAddress((void**)&p_n2,   g_n2);
    cudaGetSymbolAddress((void**)&p_Fg,   g_Fg);
    cudaGetSymbolAddress((void**)&p_part, g_part);
    cudaGetSymbolAddress((void**)&p_d0,   g_d0);
    cudaGetSymbolAddress((void**)&p_d1,   g_d1);
    cudaGetSymbolAddress((void**)&p_Fh,   g_Fh);
    cudaGetSymbolAddress((void**)&p_Fl,   g_Fl);
    cudaGetSymbolAddress((void**)&p_Xth,  g_Xth);
    cudaGetSymbolAddress((void**)&p_Xtl,  g_Xtl);
    cudaGetSymbolAddress((void**)&p_Eh,   g_Eh);
    cudaGetSymbolAddress((void**)&p_El,   g_El);

    cudaFuncSetAttribute(gemm1_mma, cudaFuncAttributeMaxDynamicSharedMemorySize, G1_SMEM);
    cudaFuncSetAttribute(dist_mma,  cudaFuncAttributeMaxDynamicSharedMemorySize, DS_SMEM);

    // 0) bf16 hi/lo splits
    fsplit_kernel<<<65536, 256>>>((const float4*)F_, (uint2*)p_Fh, (uint2*)p_Fl);
    xsplit_kernel<<<dim3(8, 256), dim3(32, 8)>>>(X, p_Xth, p_Xtl);

    // 1) inp = F_ @ X via HMMA (bf16x3, fp32 accum)
    gemm1_mma<<<dim3(2, 64), 256, G1_SMEM>>>(p_Fh, p_Fl, p_Xth, p_Xtl, p_inp);

    // 2) h0 = tanh(inp @ W_e0 + b_e0)
    gemm_bias_act<128,128,16,8,8,1><<<dim3(256/128, NN/128), 256>>>(
        p_inp, W_e0, b_e0, p_h0, NN, 256, 256);
    // 3) h1 = tanh(h0 @ W_e1 + b_e1)
    gemm_bias_act<128,128,16,8,8,1><<<dim3(128/128, NN/128), 256>>>(
        p_h0, W_e1, b_e1, p_h1, NN, 128, 256);
    // 4) E = h1 @ W_e2 + b_e2 -> d_out
    gemm_bias_act<128,64,16,8,4,0><<<dim3(64/64, NN/128), 256>>>(
        p_h1, W_e2, b_e2, E_out, NN, 64, 128);
    // 5) row norms + E split
    n2_kernel<<<NN / 8, 256>>>(E_out, p_n2);
    esplit_kernel<<<1024, 256>>>((const float2*)E_out, (uint32_t*)p_Eh, (uint32_t*)p_El);
    // 6) new_force = dist(E) * pf via HMMA -> d_out
    dist_mma<<<dim3(NN / 128, NN / 128), 256, DS_SMEM>>>(p_Eh, p_El, p_n2, pf, F_out);
    // 7) Fg = new_force @ members
    fg_kernel<<<NN, 256>>>(F_out, memb, p_Fg);
    // 8) d0 = relu(Fg @ W_d0 + b_d0)
    d0_partial_kernel<<<256, 256>>>(p_Fg, W_d0, p_part);
    d0_reduce_kernel<<<1, 1024>>>(p_part, b_d0, p_d0);
    // 9) d1 = relu(d0 @ W_d1 + b_d1)
    d1_kernel<<<8, 256>>>(p_d0, W_d1, b_d1, p_d1);
    // 10) out = softmax(d1 @ W_d2)
    final_kernel<<<1, 32>>>(p_d1, W_d2, O_out);
}

// round 10
// speedup vs baseline: 2.0935x; 1.1687x over previous
#include <cuda_runtime.h>
#include <cuda_bf16.h>
#include <math.h>
#include <stdint.h>

#define NN   8192
#define KC   8

// ---------------- scratch (device globals; no allocation allowed) ----------
__device__ float g_inp[NN * 256];     // F_ @ X (fp32)
__device__ float g_n2 [NN];
__device__ float g_Fg [NN * KC];
__device__ float g_part[256 * 1024];
__device__ float g_d0 [1024];
__device__ float g_d1 [256];
// bf16 hi/lo splits
__device__ __nv_bfloat16 g_Fh[(long)NN * NN];
__device__ __nv_bfloat16 g_Fl[(long)NN * NN];
__device__ __nv_bfloat16 g_Xth[256 * NN];   // X^T hi  [256, 8192]
__device__ __nv_bfloat16 g_Xtl[256 * NN];   // X^T lo
__device__ __nv_bfloat16 g_ih [NN * 256];   // inp splits
__device__ __nv_bfloat16 g_il [NN * 256];
__device__ __nv_bfloat16 g_h0h[NN * 256];
__device__ __nv_bfloat16 g_h0l[NN * 256];
__device__ __nv_bfloat16 g_h1h[NN * 128];
__device__ __nv_bfloat16 g_h1l[NN * 128];
__device__ __nv_bfloat16 g_Eh [NN * 64];
__device__ __nv_bfloat16 g_El [NN * 64];
// transposed weight splits [N,K]
__device__ __nv_bfloat16 g_W0h[256 * 256], g_W0l[256 * 256];
__device__ __nv_bfloat16 g_W1h[128 * 256], g_W1l[128 * 256];
__device__ __nv_bfloat16 g_W2h[64 * 128],  g_W2l[64 * 128];

// ================= PTX helpers (baseline PTX only) ==========================
__device__ __forceinline__ uint32_t smem_to_u32(const void* p) {
    uint32_t a;
    asm("{ .reg .u64 t; cvta.to.shared.u64 t, %1; cvt.u32.u64 %0, t; }"
        : "=r"(a) : "l"(p));
    return a;
}
__device__ __forceinline__ void cpasync16(uint32_t dst, const void* src) {
    asm volatile("cp.async.cg.shared.global [%0], [%1], 16;" :: "r"(dst), "l"(src));
}
#define CPASYNC_COMMIT()    asm volatile("cp.async.commit_group;" ::: "memory")
#define CPASYNC_WAIT(n)     asm volatile("cp.async.wait_group %0;" :: "n"(n) : "memory")

__device__ __forceinline__ void ldsm_x4(uint32_t* r, uint32_t addr) {
    asm volatile("ldmatrix.sync.aligned.m8n8.x4.shared.b16 {%0,%1,%2,%3}, [%4];"
                 : "=r"(r[0]), "=r"(r[1]), "=r"(r[2]), "=r"(r[3]) : "r"(addr));
}
__device__ __forceinline__ void ldsm_x2(uint32_t* r, uint32_t addr) {
    asm volatile("ldmatrix.sync.aligned.m8n8.x2.shared.b16 {%0,%1}, [%2];"
                 : "=r"(r[0]), "=r"(r[1]) : "r"(addr));
}
__device__ __forceinline__ void mma16816(float* c, const uint32_t* a, const uint32_t* b) {
    asm volatile("mma.sync.aligned.m16n8k16.row.col.f32.bf16.bf16.f32 "
                 "{%0,%1,%2,%3}, {%4,%5,%6,%7}, {%8,%9}, {%0,%1,%2,%3};"
                 : "+f"(c[0]), "+f"(c[1]), "+f"(c[2]), "+f"(c[3])
                 : "r"(a[0]), "r"(a[1]), "r"(a[2]), "r"(a[3]), "r"(b[0]), "r"(b[1]));
}

// ================= split pre-pass kernels ===================================
__global__ void fsplit_kernel(const float4* __restrict__ F,
                              uint2* __restrict__ Fh, uint2* __restrict__ Fl)
{
    long i = (long)blockIdx.x * 256 + threadIdx.x;
    float4 v = F[i];
    __nv_bfloat162 h01 = __floats2bfloat162_rn(v.x, v.y);
    __nv_bfloat162 h23 = __floats2bfloat162_rn(v.z, v.w);
    float2 f01 = __bfloat1622float2(h01);
    float2 f23 = __bfloat1622float2(h23);
    __nv_bfloat162 l01 = __floats2bfloat162_rn(v.x - f01.x, v.y - f01.y);
    __nv_bfloat162 l23 = __floats2bfloat162_rn(v.z - f23.x, v.w - f23.y);
    uint2 ho, lo;
    ho.x = *(uint32_t*)&h01; ho.y = *(uint32_t*)&h23;
    lo.x = *(uint32_t*)&l01; lo.y = *(uint32_t*)&l23;
    Fh[i] = ho; Fl[i] = lo;
}

// generic transpose-split: in [R,Cc] fp32 -> out [Cc,R] bf16 h/l. grid(Cc/32, R/32), block(32,8)
__global__ void tsplit_kernel(const float* __restrict__ in,
                              __nv_bfloat16* __restrict__ oh,
                              __nv_bfloat16* __restrict__ ol,
                              int R, int Cc)
{
    __shared__ float t[32][33];
    int bx = blockIdx.x * 32;   // col
    int by = blockIdx.y * 32;   // row
    for (int i = threadIdx.y; i < 32; i += 8)
        t[i][threadIdx.x] = in[(long)(by + i) * Cc + bx + threadIdx.x];
    __syncthreads();
    for (int i = threadIdx.y; i < 32; i += 8) {
        float v = t[threadIdx.x][i];
        __nv_bfloat16 h = __float2bfloat16(v);
        __nv_bfloat16 l = __float2bfloat16(v - __bfloat162float(h));
        long o = (long)(bx + i) * R + by + threadIdx.x;
        oh[o] = h; ol[o] = l;
    }
}

// element-wise pair split (float2 granularity). grid*256 float2s must cover input.
__global__ void pairsplit_kernel(const float2* __restrict__ E,
                                 uint32_t* __restrict__ Eh, uint32_t* __restrict__ El)
{
    long i = (long)blockIdx.x * 256 + threadIdx.x;
    float2 v = E[i];
    __nv_bfloat162 h = __floats2bfloat162_rn(v.x, v.y);
    float2 hf = __bfloat1622float2(h);
    __nv_bfloat162 l = __floats2bfloat162_rn(v.x - hf.x, v.y - hf.y);
    Eh[i] = *(uint32_t*)&h;
    El[i] = *(uint32_t*)&l;
}

// ================= GEMM1 (HMMA): C[8192,256] = F_ @ X, bf16x3 ==============
#define G1_SA     80
#define G1_BUF    (128 * G1_SA)
#define G1_STAGE  (4 * G1_BUF)
#define G1_SMEM   (4 * G1_STAGE)

__global__ void __launch_bounds__(256, 1) gemm1_mma(
    const __nv_bfloat16* __restrict__ Ah_, const __nv_bfloat16* __restrict__ Al_,
    const __nv_bfloat16* __restrict__ Bh_, const __nv_bfloat16* __restrict__ Bl_,
    float* __restrict__ C)
{
    extern __shared__ char smem[];
    const uint32_t sb = smem_to_u32(smem);
    const int tid = threadIdx.x, lane = tid & 31, wid = tid >> 5;
    const int wm = wid >> 2, wn = wid & 3;
    const int mg0 = blockIdx.y * 128, ng0 = blockIdx.x * 128;

    const uint32_t aRow = wm * 64 + (lane & 7) + ((lane >> 3) & 1) * 8;
    const uint32_t aCol = (lane >> 4) * 16;
    const uint32_t bRow = wn * 32 + (lane & 7);
    const uint32_t bCol = ((lane >> 3) & 1) * 16;

    float acc[4][4][4];
#pragma unroll
    for (int mt = 0; mt < 4; mt++)
#pragma unroll
        for (int nt = 0; nt < 4; nt++)
#pragma unroll
            for (int q = 0; q < 4; q++) acc[mt][nt][q] = 0.f;

    auto load_stage = [&](int s) {
        uint32_t base = sb + (s & 3) * G1_STAGE;
        long k0 = (long)s * 32;
#pragma unroll
        for (int h = 0; h < 2; h++) {
            int c = tid + h * 256;
            int row = c >> 2, seg = c & 3;
            uint32_t d = base + row * G1_SA + seg * 16;
            long ga = (long)(mg0 + row) * NN + k0 + seg * 8;
            long gb = (long)(ng0 + row) * NN + k0 + seg * 8;
            cpasync16(d,              Ah_ + ga);
            cpasync16(d + G1_BUF,     Al_ + ga);
            cpasync16(d + 2 * G1_BUF, Bh_ + gb);
            cpasync16(d + 3 * G1_BUF, Bl_ + gb);
        }
        CPASYNC_COMMIT();
    };

    load_stage(0); load_stage(1); load_stage(2);

    const int nStages = NN / 32;
    for (int it = 0; it < nStages; it++) {
        CPASYNC_WAIT(2);
        __syncthreads();
        if (it + 3 < nStages) load_stage(it + 3);
        else CPASYNC_COMMIT();                      // keep wait-group invariant at tail

        const uint32_t base = sb + (it & 3) * G1_STAGE;
#pragma unroll
        for (int ks = 0; ks < 2; ks++) {
            uint32_t bh[4][2], bl[4][2];
#pragma unroll
            for (int nt = 0; nt < 4; nt++) {
                uint32_t bo = base + 2 * G1_BUF + (bRow + nt * 8) * G1_SA + ks * 32 + bCol;
                ldsm_x2(bh[nt], bo);
                ldsm_x2(bl[nt], bo + G1_BUF);
            }
#pragma unroll
            for (int mt = 0; mt < 4; mt++) {
                uint32_t ah[4], al[4];
                uint32_t ao = base + (aRow + mt * 16) * G1_SA + ks * 32 + aCol;
                ldsm_x4(ah, ao);
                ldsm_x4(al, ao + G1_BUF);
#pragma unroll
                for (int nt = 0; nt < 4; nt++) {
                    mma16816(acc[mt][nt], ah, bh[nt]);
                    mma16816(acc[mt][nt], ah, bl[nt]);
                    mma16816(acc[mt][nt], al, bh[nt]);
                }
            }
        }
    }

    const int r0 = mg0 + wm * 64 + (lane >> 2);
    const int c0 = ng0 + wn * 32 + (lane & 3) * 2;
#pragma unroll
    for (int mt = 0; mt < 4; mt++) {
#pragma unroll
        for (int nt = 0; nt < 4; nt++) {
            long r = r0 + mt * 16;
            int  col = c0 + nt * 8;
            *(float2*)&C[r * 256 + col]       = make_float2(acc[mt][nt][0], acc[mt][nt][1]);
            *(float2*)&C[(r + 8) * 256 + col] = make_float2(acc[mt][nt][2], acc[mt][nt][3]);
        }
    }
}

// ================= encoder GEMM (HMMA, bf16x3, fused act + split epilogue) ==
// tile 128 x (32*NT), BK=32, 4-stage pipeline, 8 warps (2m x 4n).
// ACT: 0=identity, 1=tanh. WRITE_F: write fp32 C. WRITE_HL: write bf16 h/l split.
template<int NT, int ACT, int WRITE_F, int WRITE_HL>
__global__ void __launch_bounds__(256, 1) enc_mma(
    const __nv_bfloat16* __restrict__ Ah_, const __nv_bfloat16* __restrict__ Al_,
    const __nv_bfloat16* __restrict__ Bh_, const __nv_bfloat16* __restrict__ Bl_,
    const float* __restrict__ bias,
    float* __restrict__ Cf, __nv_bfloat16* __restrict__ Ch, __nv_bfloat16* __restrict__ Cl,
    int Ksz, int lda, int ldb, int ldc)
{
    constexpr int BN     = 32 * NT;
    constexpr int EB_A   = 128 * 80;            // A operand buffer bytes
    constexpr int EB_B   = BN * 80;             // B operand buffer bytes
    constexpr int ESTAGE = 2 * EB_A + 2 * EB_B;
    constexpr int B_IT   = (BN * 4) / 256;      // B chunk iterations (2 or 1)

    extern __shared__ char smem[];
    const uint32_t sb = smem_to_u32(smem);
    const int tid = threadIdx.x, lane = tid & 31, wid = tid >> 5;
    const int wm = wid >> 2, wn = wid & 3;
    const int mg0 = blockIdx.y * 128, ng0 = blockIdx.x * BN;

    const uint32_t aRow = wm * 64 + (lane & 7) + ((lane >> 3) & 1) * 8;
    const uint32_t aCol = (lane >> 4) * 16;
    const uint32_t bRow = wn * (8 * NT) + (lane & 7);
    const uint32_t bCol = ((lane >> 3) & 1) * 16;

    float acc[4][NT][4];
#pragma unroll
    for (int mt = 0; mt < 4; mt++)
#pragma unroll
        for (int nt = 0; nt < NT; nt++)
#pragma unroll
            for (int q = 0; q < 4; q++) acc[mt][nt][q] = 0.f;

    auto load_stage = [&](int s) {
        uint32_t base = sb + (s & 3) * ESTAGE;
        long k0 = (long)s * 32;
#pragma unroll
        for (int h = 0; h < 2; h++) {
            int c = tid + h * 256;
            int row = c >> 2, seg = c & 3;
            uint32_t d = base + row * 80 + seg * 16;
            long ga = (long)(mg0 + row) * lda + k0 + seg * 8;
            cpasync16(d,        Ah_ + ga);
            cpasync16(d + EB_A, Al_ + ga);
        }
#pragma unroll
        for (int h = 0; h < B_IT; h++) {
            int c = tid + h * 256;
            int row = c >> 2, seg = c & 3;
            uint32_t d = base + 2 * EB_A + row * 80 + seg * 16;
            long gb = (long)(ng0 + row) * ldb + k0 + seg * 8;
            cpasync16(d,        Bh_ + gb);
            cpasync16(d + EB_B, Bl_ + gb);
        }
        CPASYNC_COMMIT();
    };

    load_stage(0); load_stage(1); load_stage(2);

    const int nStages = Ksz / 32;
    for (int it = 0; it < nStages; it++) {
        CPASYNC_WAIT(2);
        __syncthreads();
        if (it + 3 < nStages) load_stage(it + 3);
        else CPASYNC_COMMIT();

        const uint32_t base = sb + (it & 3) * ESTAGE;
#pragma unroll
        for (int ks = 0; ks < 2; ks++) {
            uint32_t bh[NT][2], bl[NT][2];
#pragma unroll
            for (int nt = 0; nt < NT; nt++) {
                uint32_t bo = base + 2 * EB_A + (bRow + nt * 8) * 80 + ks * 32 + bCol;
                ldsm_x2(bh[nt], bo);
                ldsm_x2(bl[nt], bo + EB_B);
            }
#pragma unroll
            for (int mt = 0; mt < 4; mt++) {
                uint32_t ah[4], al[4];
                uint32_t ao = base + (aRow + mt * 16) * 80 + ks * 32 + aCol;
                ldsm_x4(ah, ao);
                ldsm_x4(al, ao + EB_A);
#pragma unroll
                for (int nt = 0; nt < NT; nt++) {
                    mma16816(acc[mt][nt], ah, bh[nt]);
                    mma16816(acc[mt][nt], ah, bl[nt]);
                    mma16816(acc[mt][nt], al, bh[nt]);
                }
            }
        }
    }

    const int r0 = mg0 + wm * 64 + (lane >> 2);
    const int c0 = ng0 + wn * (8 * NT) + (lane & 3) * 2;
#pragma unroll
    for (int mt = 0; mt < 4; mt++) {
#pragma unroll
        for (int nt = 0; nt < NT; nt++) {
            int col = c0 + nt * 8;
            float b0 = bias ? bias[col] : 0.f, b1 = bias ? bias[col + 1] : 0.f;
            float v[4] = { acc[mt][nt][0] + b0, acc[mt][nt][1] + b1,
                           acc[mt][nt][2] + b0, acc[mt][nt][3] + b1 };
            if (ACT == 1) {
#pragma unroll
                for (int q = 0; q < 4; q++) v[q] = tanhf(v[q]);
            }
            long r = r0 + mt * 16;
            if (WRITE_F) {
                *(float2*)&Cf[r * ldc + col]       = make_float2(v[0], v[1]);
                *(float2*)&Cf[(r + 8) * ldc + col] = make_float2(v[2], v[3]);
            }
            if (WRITE_HL) {
                __nv_bfloat162 h0 = __floats2bfloat162_rn(v[0], v[1]);
                __nv_bfloat162 h1 = __floats2bfloat162_rn(v[2], v[3]);
                float2 f0 = __bfloat1622float2(h0), f1 = __bfloat1622float2(h1);
                __nv_bfloat162 l0 = __floats2bfloat162_rn(v[0] - f0.x, v[1] - f0.y);
                __nv_bfloat162 l1 = __floats2bfloat162_rn(v[2] - f1.x, v[3] - f1.y);
                *(__nv_bfloat162*)&Ch[r * ldc + col]       = h0;
                *(__nv_bfloat162*)&Ch[(r + 8) * ldc + col] = h1;
                *(__nv_bfloat162*)&Cl[r * ldc + col]       = l0;
                *(__nv_bfloat162*)&Cl[(r + 8) * ldc + col] = l1;
            }
        }
    }
}

// ================= dist (HMMA): force = sqrt(n2i+n2j-2*E@E^T)+ * pf =========
#define DS_SA    144
#define DS_BUF   (128 * DS_SA)
#define DS_SMEM  (4 * DS_BUF)

__global__ void __launch_bounds__(256, 1) dist_mma(
    const __nv_bfloat16* __restrict__ Eh, const __nv_bfloat16* __restrict__ El,
    const float* __restrict__ n2, const float* __restrict__ pf,
    float* __restrict__ Fo)
{
    extern __shared__ char smem[];
    const uint32_t sb = smem_to_u32(smem);
    const int tid = threadIdx.x, lane = tid & 31, wid = tid >> 5;
    const int wm = wid >> 2, wn = wid & 3;
    const int i0 = blockIdx.y * 128, j0 = blockIdx.x * 128;

#pragma unroll
    for (int h = 0; h < 4; h++) {
        int c = tid + h * 256;
        int row = c >> 3, seg = c & 7;
        uint32_t d = sb + row * DS_SA + seg * 16;
        long gi = (long)(i0 + row) * 64 + seg * 8;
        long gj = (long)(j0 + row) * 64 + seg * 8;
        cpasync16(d,              Eh + gi);
        cpasync16(d + DS_BUF,     El + gi);
        cpasync16(d + 2 * DS_BUF, Eh + gj);
        cpasync16(d + 3 * DS_BUF, El + gj);
    }
    CPASYNC_COMMIT();
    CPASYNC_WAIT(0);
    __syncthreads();

    const uint32_t aRow = wm * 64 + (lane & 7) + ((lane >> 3) & 1) * 8;
    const uint32_t aCol = (lane >> 4) * 16;
    const uint32_t bRow = wn * 32 + (lane & 7);
    const uint32_t bCol = ((lane >> 3) & 1) * 16;

    float acc[4][4][4];
#pragma unroll
    for (int mt = 0; mt < 4; mt++)
#pragma unroll
        for (int nt = 0; nt < 4; nt++)
#pragma unroll
            for (int q = 0; q < 4; q++) acc[mt][nt][q] = 0.f;

#pragma unroll
    for (int ks = 0; ks < 4; ks++) {
        uint32_t bh[4][2], bl[4][2];
#pragma unroll
        for (int nt = 0; nt < 4; nt++) {
            uint32_t bo = sb + 2 * DS_BUF + (bRow + nt * 8) * DS_SA + ks * 32 + bCol;
            ldsm_x2(bh[nt], bo);
            ldsm_x2(bl[nt], bo + DS_BUF);
        }
#pragma unroll
        for (int mt = 0; mt < 4; mt++) {
            uint32_t ah[4], al[4];
            uint32_t ao = sb + (aRow + mt * 16) * DS_SA + ks * 32 + aCol;
            ldsm_x4(ah, ao);
            ldsm_x4(al, ao + DS_BUF);
#pragma unroll
            for (int nt = 0; nt < 4; nt++) {
                mma16816(acc[mt][nt], ah, bh[nt]);
                mma16816(acc[mt][nt], ah, bl[nt]);
                mma16816(acc[mt][nt], al, bh[nt]);
            }
        }
    }

    const int ri = i0 + wm * 64 + (lane >> 2);
    const int cj = j0 + wn * 32 + (lane & 3) * 2;
#pragma unroll
    for (int mt = 0; mt < 4; mt++) {
        int ia = ri + mt * 16;
        float n2a = n2[ia], n2b = n2[ia + 8];
#pragma unroll
        for (int nt = 0; nt < 4; nt++) {
            int j = cj + nt * 8;
            float nj0 = n2[j], nj1 = n2[j + 1];
            float2 p0 = *(const float2*)&pf[(long)ia * NN + j];
            float2 p1 = *(const float2*)&pf[(long)(ia + 8) * NN + j];
            float* a = acc[mt][nt];
            float s00 = n2a + nj0 - 2.f * a[0];
            float s01 = n2a + nj1 - 2.f * a[1];
            float s10 = n2b + nj0 - 2.f * a[2];
            float s11 = n2b + nj1 - 2.f * a[3];
            float d00 = (s00 > 0.f) ? sqrtf(s00) : 0.f;
            float d01 = (s01 > 0.f) ? sqrtf(s01) : 0.f;
            float d10 = (s10 > 0.f) ? sqrtf(s10) : 0.f;
            float d11 = (s11 > 0.f) ? sqrtf(s11) : 0.f;
            *(float2*)&Fo[(long)ia * NN + j]       = make_float2(d00 * p0.x, d01 * p0.y);
            *(float2*)&Fo[(long)(ia + 8) * NN + j] = make_float2(d10 * p1.x, d11 * p1.y);
        }
    }
}

// ---------------- row-wise squared norms of E [NN,64] -----------------------
__global__ void n2_kernel(const float* __restrict__ E, float* __restrict__ n2)
{
    int row  = blockIdx.x * 8 + threadIdx.x / 32;
    int lane = threadIdx.x % 32;
    const float* e = E + (long)row * 64;
    float a = e[lane], b = e[lane + 32];
    float v = a * a + b * b;
#pragma unroll
    for (int off = 16; off; off >>= 1)
        v += __shfl_down_sync(0xffffffffu, v, off);
    if (lane == 0) n2[row] = v;
}

// ---------------- Fg = Fo @ members : 128 blocks x 64 rows ------------------
__global__ void fg_kernel(const float* __restrict__ Fo,
                          const float* __restrict__ members,
                          float* __restrict__ Fg)
{
    const int lane = threadIdx.x & 31, wid = threadIdx.x >> 5;
    const int r0 = blockIdx.x * 64 + wid * 8;     // 8 rows per warp

    float acc[8][8];
#pragma unroll
    for (int rr = 0; rr < 8; rr++)
#pragma unroll
        for (int k = 0; k < 8; k++) acc[rr][k] = 0.f;

    for (int j = lane * 4; j < NN; j += 128) {
        // members rows j..j+3 (each 8 floats)
        float4 m[4][2];
#pragma unroll
        for (int jj = 0; jj < 4; jj++) {
            m[jj][0] = *(const float4*)&members[(long)(j + jj) * 8];
            m[jj][1] = *(const float4*)&members[(long)(j + jj) * 8 + 4];
        }
#pragma unroll
        for (int rr = 0; rr < 8; rr++) {
            float4 f = *(const float4*)&Fo[(long)(r0 + rr) * NN + j];
            float fv[4] = { f.x, f.y, f.z, f.w };
#pragma unroll
            for (int jj = 0; jj < 4; jj++) {
                acc[rr][0] = fmaf(fv[jj], m[jj][0].x, acc[rr][0]);
                acc[rr][1] = fmaf(fv[jj], m[jj][0].y, acc[rr][1]);
                acc[rr][2] = fmaf(fv[jj], m[jj][0].z, acc[rr][2]);
                acc[rr][3] = fmaf(fv[jj], m[jj][0].w, acc[rr][3]);
                acc[rr][4] = fmaf(fv[jj], m[jj][1].x, acc[rr][4]);
                acc[rr][5] = fmaf(fv[jj], m[jj][1].y, acc[rr][5]);
                acc[rr][6] = fmaf(fv[jj], m[jj][1].z, acc[rr][6]);
                acc[rr][7] = fmaf(fv[jj], m[jj][1].w, acc[rr][7]);
            }
        }
    }
#pragma unroll
    for (int rr = 0; rr < 8; rr++) {
#pragma unroll
        for (int k = 0; k < 8; k++) {
            float v = acc[rr][k];
#pragma unroll
            for (int off = 16; off; off >>= 1)
                v += __shfl_down_sync(0xffffffffu, v, off);
            if (lane == 0) Fg[(long)(r0 + rr) * 8 + k] = v;
        }
    }
}

// ---------------- d0 GEMV split-K -------------------------------------------
__global__ void d0_partial_kernel(const float* __restrict__ Fg,
                                  const float* __restrict__ W,
                                  float* __restrict__ part)
{
    __shared__ float sF[256];
    const int c = blockIdx.x;
    const int t = threadIdx.x;
    sF[t] = Fg[c * 256 + t];
    __syncthreads();

    float4 acc = make_float4(0.f, 0.f, 0.f, 0.f);
    const float4* Wv = (const float4*)W + (long)(c * 256) * 256 + t;
    for (int r = 0; r < 256; r++) {
        float f = sF[r];
        float4 w = Wv[(long)r * 256];
        acc.x = fmaf(f, w.x, acc.x);
        acc.y = fmaf(f, w.y, acc.y);
        acc.z = fmaf(f, w.z, acc.z);
        acc.w = fmaf(f, w.w, acc.w);
    }
    ((float4*)part)[c * 256 + t] = acc;
}

__global__ void d0_reduce_kernel(const float* __restrict__ part,
                                 const float* __restrict__ bias,
                                 float* __restrict__ d0)
{
    const int col = threadIdx.x;
    float v = 0.f;
    for (int c = 0; c < 256; c++) v += part[c * 1024 + col];
    v += bias[col];
    d0[col] = fmaxf(v, 0.f);
}

// ---------------- d1 = relu(d0 @ W_d1 + b_d1) --------------------------------
__global__ void d1_kernel(const float* __restrict__ d0,
                          const float* __restrict__ W,
                          const float* __restrict__ bias,
                          float* __restrict__ d1)
{
    const int col = blockIdx.x * 32 + threadIdx.x % 32;
    const int rg  = threadIdx.x / 32;
    float acc = 0.f;
    for (int r = rg; r < 1024; r += 8)
        acc = fmaf(d0[r], W[r * 256 + col], acc);
    __shared__ float s[8][32];
    s[rg][threadIdx.x % 32] = acc;
    __syncthreads();
    if (rg == 0) {
        float v = acc;
#pragma unroll
        for (int g = 1; g < 8; g++) v += s[g][threadIdx.x];
        v += bias[col];
        d1[col] = fmaxf(v, 0.f);
    }
}

// ---------------- final: softmax(d1 @ W_d2) ----------------------------------
__global__ void final_kernel(const float* __restrict__ d1,
                             const float* __restrict__ W,
                             float* __restrict__ out)
{
    const int lane = threadIdx.x;
    float acc[8];
#pragma unroll
    for (int k = 0; k < 8; k++) acc[k] = 0.f;
    for (int r = lane; r < 256; r += 32) {
        float v = d1[r];
        const float* w = W + r * 8;
#pragma unroll
        for (int k = 0; k < 8; k++) acc[k] = fmaf(v, w[k], acc[k]);
    }
#pragma unroll
    for (int k = 0; k < 8; k++)
#pragma unroll
        for (int off = 16; off; off >>= 1)
            acc[k] += __shfl_down_sync(0xffffffffu, acc[k], off);
    if (lane == 0) {
        float mx = acc[0];
#pragma unroll
        for (int k = 1; k < 8; k++) mx = fmaxf(mx, acc[k]);
        float e[8], s = 0.f;
#pragma unroll
        for (int k = 0; k < 8; k++) { e[k] = expf(acc[k] - mx); s += e[k]; }
#pragma unroll
        for (int k = 0; k < 8; k++) out[k] = e[k] / s;
    }
}

// ---------------- launch ----------------------------------------------------
extern "C" void kernel_launch(void* const* d_in, const int* in_sizes, int n_in,
                              void* d_out, int out_size)
{
    const float* F_    = (const float*)d_in[0];
    const float* X     = (const float*)d_in[1];
    const float* W_e0  = (const float*)d_in[2];
    const float* b_e0  = (const float*)d_in[3];
    const float* W_e1  = (const float*)d_in[4];
    const float* b_e1  = (const float*)d_in[5];
    const float* W_e2  = (const float*)d_in[6];
    const float* b_e2  = (const float*)d_in[7];
    const float* W_d0  = (const float*)d_in[8];
    const float* b_d0  = (const float*)d_in[9];
    const float* W_d1  = (const float*)d_in[10];
    const float* b_d1  = (const float*)d_in[11];
    const float* W_d2  = (const float*)d_in[12];
    const float* pf    = (const float*)d_in[13];
    const float* memb  = (const float*)d_in[14];

    float* out    = (float*)d_out;
    float* E_out  = out;
    float* F_out  = out + (long)NN * 64;
    float* O_out  = out + (long)NN * 64 + (long)NN * NN;

    float *p_inp, *p_n2, *p_Fg, *p_part, *p_d0, *p_d1;
    __nv_bfloat16 *p_Fh, *p_Fl, *p_Xth, *p_Xtl, *p_Eh, *p_El;
    __nv_bfloat16 *p_ih, *p_il, *p_h0h, *p_h0l, *p_h1h, *p_h1l;
    __nv_bfloat16 *p_W0h, *p_W0l, *p_W1h, *p_W1l, *p_W2h, *p_W2l;
    cudaGetSymbolAddress((void**)&p_inp,  g_inp);
    cudaGetSymbolAddress((void**)&p_n2,   g_n2);
    cudaGetSymbolAddress((void**)&p_Fg,   g_Fg);
    cudaGetSymbolAddress((void**)&p_part, g_part);
    cudaGetSymbolAddress((void**)&p_d0,   g_d0);
    cudaGetSymbolAddress((void**)&p_d1,   g_d1);
    cudaGetSymbolAddress((void**)&p_Fh,   g_Fh);
    cudaGetSymbolAddress((void**)&p_Fl,   g_Fl);
    cudaGetSymbolAddress((void**)&p_Xth,  g_Xth);
    cudaGetSymbolAddress((void**)&p_Xtl,  g_Xtl);
    cudaGetSymbolAddress((void**)&p_Eh,   g_Eh);
    cudaGetSymbolAddress((void**)&p_El,   g_El);
    cudaGetSymbolAddress((void**)&p_ih,   g_ih);
    cudaGetSymbolAddress((void**)&p_il,   g_il);
    cudaGetSymbolAddress((void**)&p_h0h,  g_h0h);
    cudaGetSymbolAddress((void**)&p_h0l,  g_h0l);
    cudaGetSymbolAddress((void**)&p_h1h,  g_h1h);
    cudaGetSymbolAddress((void**)&p_h1l,  g_h1l);
    cudaGetSymbolAddress((void**)&p_W0h,  g_W0h);
    cudaGetSymbolAddress((void**)&p_W0l,  g_W0l);
    cudaGetSymbolAddress((void**)&p_W1h,  g_W1h);
    cudaGetSymbolAddress((void**)&p_W1l,  g_W1l);
    cudaGetSymbolAddress((void**)&p_W2h,  g_W2h);
    cudaGetSymbolAddress((void**)&p_W2l,  g_W2l);

    cudaFuncSetAttribute(gemm1_mma, cudaFuncAttributeMaxDynamicSharedMemorySize, G1_SMEM);
    cudaFuncSetAttribute(dist_mma,  cudaFuncAttributeMaxDynamicSharedMemorySize, DS_SMEM);
    cudaFuncSetAttribute(enc_mma<4,1,0,1>, cudaFuncAttributeMaxDynamicSharedMemorySize, 163840);
    cudaFuncSetAttribute(enc_mma<2,0,1,1>, cudaFuncAttributeMaxDynamicSharedMemorySize, 122880);

    // 0) bf16 hi/lo splits of inputs
    fsplit_kernel<<<65536, 256>>>((const float4*)F_, (uint2*)p_Fh, (uint2*)p_Fl);
    tsplit_kernel<<<dim3(8, 256), dim3(32, 8)>>>(X, p_Xth, p_Xtl, NN, 256);      // X^T
    tsplit_kernel<<<dim3(8, 8),  dim3(32, 8)>>>(W_e0, p_W0h, p_W0l, 256, 256);   // W0^T
    tsplit_kernel<<<dim3(4, 8),  dim3(32, 8)>>>(W_e1, p_W1h, p_W1l, 256, 128);   // W1^T
    tsplit_kernel<<<dim3(2, 4),  dim3(32, 8)>>>(W_e2, p_W2h, p_W2l, 128, 64);    // W2^T

    // 1) inp = F_ @ X (HMMA) -> fp32, then split
    gemm1_mma<<<dim3(2, 64), 256, G1_SMEM>>>(p_Fh, p_Fl, p_Xth, p_Xtl, p_inp);
    pairsplit_kernel<<<4096, 256>>>((const float2*)p_inp, (uint32_t*)p_ih, (uint32_t*)p_il);

    // 2) h0 = tanh(inp @ W_e0 + b) (HMMA, split epilogue)
    enc_mma<4,1,0,1><<<dim3(2, 64), 256, 163840>>>(
        p_ih, p_il, p_W0h, p_W0l, b_e0, nullptr, p_h0h, p_h0l, 256, 256, 256, 256);
    // 3) h1 = tanh(h0 @ W_e1 + b)
    enc_mma<4,1,0,1><<<dim3(1, 64), 256, 163840>>>(
        p_h0h, p_h0l, p_W1h, p_W1l, b_e1, nullptr, p_h1h, p_h1l, 256, 256, 256, 128);
    // 4) E = h1 @ W_e2 + b -> fp32 to d_out + splits
    enc_mma<2,0,1,1><<<dim3(1, 64), 256, 122880>>>(
        p_h1h, p_h1l, p_W2h, p_W2l, b_e2, E_out, p_Eh, p_El, 128, 128, 128, 64);

    // 5) row norms
    n2_kernel<<<NN / 8, 256>>>(E_out, p_n2);
    // 6) new_force = dist(E) * pf (HMMA) -> d_out
    dist_mma<<<dim3(NN / 128, NN / 128), 256, DS_SMEM>>>(p_Eh, p_El, p_n2, pf, F_out);
    // 7) Fg = new_force @ members
    fg_kernel<<<NN / 64, 256>>>(F_out, memb, p_Fg);
    // 8) d0 = relu(Fg @ W_d0 + b_d0)
    d0_partial_kernel<<<256, 256>>>(p_Fg, W_d0, p_part);
    d0_reduce_kernel<<<1, 1024>>>(p_part, b_d0, p_d0);
    // 9) d1 = relu(d0 @ W_d1 + b_d1)
    d1_kernel<<<8, 256>>>(p_d0, W_d1, b_d1, p_d1);
    // 10) out = softmax(d1 @ W_d2)
    final_kernel<<<1, 32>>>(p_d1, W_d2, O_out);
}

// round 11
// speedup vs baseline: 2.2145x; 1.0578x over previous
#include <cuda_runtime.h>
#include <cuda_bf16.h>
#include <math.h>
#include <stdint.h>

#define NN   8192
#define KC   8

// ---------------- scratch (device globals; no allocation allowed) ----------
__device__ float g_n2 [NN];
__device__ float g_Fg [NN * KC];
__device__ float g_part[256 * 1024];
__device__ float g_d0 [1024];
__device__ float g_d1 [256];
// bf16 hi/lo splits
__device__ __nv_bfloat16 g_Fh[(long)NN * NN];
__device__ __nv_bfloat16 g_Fl[(long)NN * NN];
__device__ __nv_bfloat16 g_Xth[256 * NN];   // X^T hi  [256, 8192]
__device__ __nv_bfloat16 g_Xtl[256 * NN];   // X^T lo
__device__ __nv_bfloat16 g_ih [NN * 256];   // inp splits (written by gemm1 epilogue)
__device__ __nv_bfloat16 g_il [NN * 256];
__device__ __nv_bfloat16 g_h0h[NN * 256];
__device__ __nv_bfloat16 g_h0l[NN * 256];
__device__ __nv_bfloat16 g_h1h[NN * 128];
__device__ __nv_bfloat16 g_h1l[NN * 128];
__device__ __nv_bfloat16 g_Eh [NN * 64];
__device__ __nv_bfloat16 g_El [NN * 64];
// transposed weight splits [N,K]
__device__ __nv_bfloat16 g_W0h[256 * 256], g_W0l[256 * 256];
__device__ __nv_bfloat16 g_W1h[128 * 256], g_W1l[128 * 256];
__device__ __nv_bfloat16 g_W2h[64 * 128],  g_W2l[64 * 128];

// ================= PTX helpers (baseline PTX only) ==========================
__device__ __forceinline__ uint32_t smem_to_u32(const void* p) {
    uint32_t a;
    asm("{ .reg .u64 t; cvta.to.shared.u64 t, %1; cvt.u32.u64 %0, t; }"
        : "=r"(a) : "l"(p));
    return a;
}
__device__ __forceinline__ void cpasync16(uint32_t dst, const void* src) {
    asm volatile("cp.async.cg.shared.global [%0], [%1], 16;" :: "r"(dst), "l"(src));
}
#define CPASYNC_COMMIT()    asm volatile("cp.async.commit_group;" ::: "memory")
#define CPASYNC_WAIT(n)     asm volatile("cp.async.wait_group %0;" :: "n"(n) : "memory")

__device__ __forceinline__ void ldsm_x4(uint32_t* r, uint32_t addr) {
    asm volatile("ldmatrix.sync.aligned.m8n8.x4.shared.b16 {%0,%1,%2,%3}, [%4];"
                 : "=r"(r[0]), "=r"(r[1]), "=r"(r[2]), "=r"(r[3]) : "r"(addr));
}
__device__ __forceinline__ void ldsm_x2(uint32_t* r, uint32_t addr) {
    asm volatile("ldmatrix.sync.aligned.m8n8.x2.shared.b16 {%0,%1}, [%2];"
                 : "=r"(r[0]), "=r"(r[1]) : "r"(addr));
}
__device__ __forceinline__ void mma16816(float* c, const uint32_t* a, const uint32_t* b) {
    asm volatile("mma.sync.aligned.m16n8k16.row.col.f32.bf16.bf16.f32 "
                 "{%0,%1,%2,%3}, {%4,%5,%6,%7}, {%8,%9}, {%0,%1,%2,%3};"
                 : "+f"(c[0]), "+f"(c[1]), "+f"(c[2]), "+f"(c[3])
                 : "r"(a[0]), "r"(a[1]), "r"(a[2]), "r"(a[3]), "r"(b[0]), "r"(b[1]));
}

// ================= split pre-pass kernels ===================================
__global__ void fsplit_kernel(const float4* __restrict__ F,
                              uint2* __restrict__ Fh, uint2* __restrict__ Fl)
{
    long i = (long)blockIdx.x * 256 + threadIdx.x;
    float4 v = F[i];
    __nv_bfloat162 h01 = __floats2bfloat162_rn(v.x, v.y);
    __nv_bfloat162 h23 = __floats2bfloat162_rn(v.z, v.w);
    float2 f01 = __bfloat1622float2(h01);
    float2 f23 = __bfloat1622float2(h23);
    __nv_bfloat162 l01 = __floats2bfloat162_rn(v.x - f01.x, v.y - f01.y);
    __nv_bfloat162 l23 = __floats2bfloat162_rn(v.z - f23.x, v.w - f23.y);
    uint2 ho, lo;
    ho.x = *(uint32_t*)&h01; ho.y = *(uint32_t*)&h23;
    lo.x = *(uint32_t*)&l01; lo.y = *(uint32_t*)&l23;
    Fh[i] = ho; Fl[i] = lo;
}

// generic transpose-split: in [R,Cc] fp32 -> out [Cc,R] bf16 h/l
__global__ void tsplit_kernel(const float* __restrict__ in,
                              __nv_bfloat16* __restrict__ oh,
                              __nv_bfloat16* __restrict__ ol,
                              int R, int Cc)
{
    __shared__ float t[32][33];
    int bx = blockIdx.x * 32;
    int by = blockIdx.y * 32;
    for (int i = threadIdx.y; i < 32; i += 8)
        t[i][threadIdx.x] = in[(long)(by + i) * Cc + bx + threadIdx.x];
    __syncthreads();
    for (int i = threadIdx.y; i < 32; i += 8) {
        float v = t[threadIdx.x][i];
        __nv_bfloat16 h = __float2bfloat16(v);
        __nv_bfloat16 l = __float2bfloat16(v - __bfloat162float(h));
        long o = (long)(bx + i) * R + by + threadIdx.x;
        oh[o] = h; ol[o] = l;
    }
}

// ================= GEMM1 (HMMA): ih/il[8192,256] = split(F_ @ X), bf16x3 ====
#define G1_SA     80
#define G1_BUF    (128 * G1_SA)
#define G1_STAGE  (4 * G1_BUF)
#define G1_SMEM   (4 * G1_STAGE)

__global__ void __launch_bounds__(256, 1) gemm1_mma(
    const __nv_bfloat16* __restrict__ Ah_, const __nv_bfloat16* __restrict__ Al_,
    const __nv_bfloat16* __restrict__ Bh_, const __nv_bfloat16* __restrict__ Bl_,
    __nv_bfloat16* __restrict__ Ch, __nv_bfloat16* __restrict__ Cl)
{
    extern __shared__ char smem[];
    const uint32_t sb = smem_to_u32(smem);
    const int tid = threadIdx.x, lane = tid & 31, wid = tid >> 5;
    const int wm = wid >> 2, wn = wid & 3;
    const int mg0 = blockIdx.y * 128, ng0 = blockIdx.x * 128;

    const uint32_t aRow = wm * 64 + (lane & 7) + ((lane >> 3) & 1) * 8;
    const uint32_t aCol = (lane >> 4) * 16;
    const uint32_t bRow = wn * 32 + (lane & 7);
    const uint32_t bCol = ((lane >> 3) & 1) * 16;

    float acc[4][4][4];
#pragma unroll
    for (int mt = 0; mt < 4; mt++)
#pragma unroll
        for (int nt = 0; nt < 4; nt++)
#pragma unroll
            for (int q = 0; q < 4; q++) acc[mt][nt][q] = 0.f;

    auto load_stage = [&](int s) {
        uint32_t base = sb + (s & 3) * G1_STAGE;
        long k0 = (long)s * 32;
#pragma unroll
        for (int h = 0; h < 2; h++) {
            int c = tid + h * 256;
            int row = c >> 2, seg = c & 3;
            uint32_t d = base + row * G1_SA + seg * 16;
            long ga = (long)(mg0 + row) * NN + k0 + seg * 8;
            long gb = (long)(ng0 + row) * NN + k0 + seg * 8;
            cpasync16(d,              Ah_ + ga);
            cpasync16(d + G1_BUF,     Al_ + ga);
            cpasync16(d + 2 * G1_BUF, Bh_ + gb);
            cpasync16(d + 3 * G1_BUF, Bl_ + gb);
        }
        CPASYNC_COMMIT();
    };

    load_stage(0); load_stage(1); load_stage(2);

    const int nStages = NN / 32;
    for (int it = 0; it < nStages; it++) {
        CPASYNC_WAIT(2);
        __syncthreads();
        if (it + 3 < nStages) load_stage(it + 3);
        else CPASYNC_COMMIT();

        const uint32_t base = sb + (it & 3) * G1_STAGE;
#pragma unroll
        for (int ks = 0; ks < 2; ks++) {
            uint32_t bh[4][2], bl[4][2];
#pragma unroll
            for (int nt = 0; nt < 4; nt++) {
                uint32_t bo = base + 2 * G1_BUF + (bRow + nt * 8) * G1_SA + ks * 32 + bCol;
                ldsm_x2(bh[nt], bo);
                ldsm_x2(bl[nt], bo + G1_BUF);
            }
#pragma unroll
            for (int mt = 0; mt < 4; mt++) {
                uint32_t ah[4], al[4];
                uint32_t ao = base + (aRow + mt * 16) * G1_SA + ks * 32 + aCol;
                ldsm_x4(ah, ao);
                ldsm_x4(al, ao + G1_BUF);
#pragma unroll
                for (int nt = 0; nt < 4; nt++) {
                    mma16816(acc[mt][nt], ah, bh[nt]);
                    mma16816(acc[mt][nt], ah, bl[nt]);
                    mma16816(acc[mt][nt], al, bh[nt]);
                }
            }
        }
    }

    // epilogue: hi/lo-split bf16 write (inp fp32 never materialized)
    const int r0 = mg0 + wm * 64 + (lane >> 2);
    const int c0 = ng0 + wn * 32 + (lane & 3) * 2;
#pragma unroll
    for (int mt = 0; mt < 4; mt++) {
#pragma unroll
        for (int nt = 0; nt < 4; nt++) {
            long r = r0 + mt * 16;
            int  col = c0 + nt * 8;
            float* v = acc[mt][nt];
            __nv_bfloat162 h0 = __floats2bfloat162_rn(v[0], v[1]);
            __nv_bfloat162 h1 = __floats2bfloat162_rn(v[2], v[3]);
            float2 f0 = __bfloat1622float2(h0), f1 = __bfloat1622float2(h1);
            __nv_bfloat162 l0 = __floats2bfloat162_rn(v[0] - f0.x, v[1] - f0.y);
            __nv_bfloat162 l1 = __floats2bfloat162_rn(v[2] - f1.x, v[3] - f1.y);
            *(__nv_bfloat162*)&Ch[r * 256 + col]       = h0;
            *(__nv_bfloat162*)&Ch[(r + 8) * 256 + col] = h1;
            *(__nv_bfloat162*)&Cl[r * 256 + col]       = l0;
            *(__nv_bfloat162*)&Cl[(r + 8) * 256 + col] = l1;
        }
    }
}

// ================= encoder GEMM (HMMA, bf16x3, fused act + split epilogue) ==
template<int NT, int ACT, int WRITE_F, int WRITE_HL>
__global__ void __launch_bounds__(256, 1) enc_mma(
    const __nv_bfloat16* __restrict__ Ah_, const __nv_bfloat16* __restrict__ Al_,
    const __nv_bfloat16* __restrict__ Bh_, const __nv_bfloat16* __restrict__ Bl_,
    const float* __restrict__ bias,
    float* __restrict__ Cf, __nv_bfloat16* __restrict__ Ch, __nv_bfloat16* __restrict__ Cl,
    int Ksz, int lda, int ldb, int ldc)
{
    constexpr int BN     = 32 * NT;
    constexpr int EB_A   = 128 * 80;
    constexpr int EB_B   = BN * 80;
    constexpr int ESTAGE = 2 * EB_A + 2 * EB_B;
    constexpr int B_IT   = (BN * 4) / 256;

    extern __shared__ char smem[];
    const uint32_t sb = smem_to_u32(smem);
    const int tid = threadIdx.x, lane = tid & 31, wid = tid >> 5;
    const int wm = wid >> 2, wn = wid & 3;
    const int mg0 = blockIdx.y * 128, ng0 = blockIdx.x * BN;

    const uint32_t aRow = wm * 64 + (lane & 7) + ((lane >> 3) & 1) * 8;
    const uint32_t aCol = (lane >> 4) * 16;
    const uint32_t bRow = wn * (8 * NT) + (lane & 7);
    const uint32_t bCol = ((lane >> 3) & 1) * 16;

    float acc[4][NT][4];
#pragma unroll
    for (int mt = 0; mt < 4; mt++)
#pragma unroll
        for (int nt = 0; nt < NT; nt++)
#pragma unroll
            for (int q = 0; q < 4; q++) acc[mt][nt][q] = 0.f;

    auto load_stage = [&](int s) {
        uint32_t base = sb + (s & 3) * ESTAGE;
        long k0 = (long)s * 32;
#pragma unroll
        for (int h = 0; h < 2; h++) {
            int c = tid + h * 256;
            int row = c >> 2, seg = c & 3;
            uint32_t d = base + row * 80 + seg * 16;
            long ga = (long)(mg0 + row) * lda + k0 + seg * 8;
            cpasync16(d,        Ah_ + ga);
            cpasync16(d + EB_A, Al_ + ga);
        }
#pragma unroll
        for (int h = 0; h < B_IT; h++) {
            int c = tid + h * 256;
            int row = c >> 2, seg = c & 3;
            uint32_t d = base + 2 * EB_A + row * 80 + seg * 16;
            long gb = (long)(ng0 + row) * ldb + k0 + seg * 8;
            cpasync16(d,        Bh_ + gb);
            cpasync16(d + EB_B, Bl_ + gb);
        }
        CPASYNC_COMMIT();
    };

    load_stage(0); load_stage(1); load_stage(2);

    const int nStages = Ksz / 32;
    for (int it = 0; it < nStages; it++) {
        CPASYNC_WAIT(2);
        __syncthreads();
        if (it + 3 < nStages) load_stage(it + 3);
        else CPASYNC_COMMIT();

        const uint32_t base = sb + (it & 3) * ESTAGE;
#pragma unroll
        for (int ks = 0; ks < 2; ks++) {
            uint32_t bh[NT][2], bl[NT][2];
#pragma unroll
            for (int nt = 0; nt < NT; nt++) {
                uint32_t bo = base + 2 * EB_A + (bRow + nt * 8) * 80 + ks * 32 + bCol;
                ldsm_x2(bh[nt], bo);
                ldsm_x2(bl[nt], bo + EB_B);
            }
#pragma unroll
            for (int mt = 0; mt < 4; mt++) {
                uint32_t ah[4], al[4];
                uint32_t ao = base + (aRow + mt * 16) * 80 + ks * 32 + aCol;
                ldsm_x4(ah, ao);
                ldsm_x4(al, ao + EB_A);
#pragma unroll
                for (int nt = 0; nt < NT; nt++) {
                    mma16816(acc[mt][nt], ah, bh[nt]);
                    mma16816(acc[mt][nt], ah, bl[nt]);
                    mma16816(acc[mt][nt], al, bh[nt]);
                }
            }
        }
    }

    const int r0 = mg0 + wm * 64 + (lane >> 2);
    const int c0 = ng0 + wn * (8 * NT) + (lane & 3) * 2;
#pragma unroll
    for (int mt = 0; mt < 4; mt++) {
#pragma unroll
        for (int nt = 0; nt < NT; nt++) {
            int col = c0 + nt * 8;
            float b0 = bias ? bias[col] : 0.f, b1 = bias ? bias[col + 1] : 0.f;
            float v[4] = { acc[mt][nt][0] + b0, acc[mt][nt][1] + b1,
                           acc[mt][nt][2] + b0, acc[mt][nt][3] + b1 };
            if (ACT == 1) {
#pragma unroll
                for (int q = 0; q < 4; q++) v[q] = tanhf(v[q]);
            }
            long r = r0 + mt * 16;
            if (WRITE_F) {
                *(float2*)&Cf[r * ldc + col]       = make_float2(v[0], v[1]);
                *(float2*)&Cf[(r + 8) * ldc + col] = make_float2(v[2], v[3]);
            }
            if (WRITE_HL) {
                __nv_bfloat162 h0 = __floats2bfloat162_rn(v[0], v[1]);
                __nv_bfloat162 h1 = __floats2bfloat162_rn(v[2], v[3]);
                float2 f0 = __bfloat1622float2(h0), f1 = __bfloat1622float2(h1);
                __nv_bfloat162 l0 = __floats2bfloat162_rn(v[0] - f0.x, v[1] - f0.y);
                __nv_bfloat162 l1 = __floats2bfloat162_rn(v[2] - f1.x, v[3] - f1.y);
                *(__nv_bfloat162*)&Ch[r * ldc + col]       = h0;
                *(__nv_bfloat162*)&Ch[(r + 8) * ldc + col] = h1;
                *(__nv_bfloat162*)&Cl[r * ldc + col]       = l0;
                *(__nv_bfloat162*)&Cl[(r + 8) * ldc + col] = l1;
            }
        }
    }
}

// ================= dist (HMMA): force = sqrt(n2i+n2j-2*E@E^T)+ * pf =========
#define DS_SA    144
#define DS_BUF   (128 * DS_SA)
#define DS_SMEM  (4 * DS_BUF)        // 73728 B -> 2 CTAs/SM

__global__ void __launch_bounds__(256, 2) dist_mma(
    const __nv_bfloat16* __restrict__ Eh, const __nv_bfloat16* __restrict__ El,
    const float* __restrict__ n2, const float* __restrict__ pf,
    float* __restrict__ Fo)
{
    extern __shared__ char smem[];
    const uint32_t sb = smem_to_u32(smem);
    const int tid = threadIdx.x, lane = tid & 31, wid = tid >> 5;
    const int wm = wid >> 2, wn = wid & 3;
    const int i0 = blockIdx.y * 128, j0 = blockIdx.x * 128;

#pragma unroll
    for (int h = 0; h < 4; h++) {
        int c = tid + h * 256;
        int row = c >> 3, seg = c & 7;
        uint32_t d = sb + row * DS_SA + seg * 16;
        long gi = (long)(i0 + row) * 64 + seg * 8;
        long gj = (long)(j0 + row) * 64 + seg * 8;
        cpasync16(d,              Eh + gi);
        cpasync16(d + DS_BUF,     El + gi);
        cpasync16(d + 2 * DS_BUF, Eh + gj);
        cpasync16(d + 3 * DS_BUF, El + gj);
    }
    CPASYNC_COMMIT();
    CPASYNC_WAIT(0);
    __syncthreads();

    const uint32_t aRow = wm * 64 + (lane & 7) + ((lane >> 3) & 1) * 8;
    const uint32_t aCol = (lane >> 4) * 16;
    const uint32_t bRow = wn * 32 + (lane & 7);
    const uint32_t bCol = ((lane >> 3) & 1) * 16;

    float acc[4][4][4];
#pragma unroll
    for (int mt = 0; mt < 4; mt++)
#pragma unroll
        for (int nt = 0; nt < 4; nt++)
#pragma unroll
            for (int q = 0; q < 4; q++) acc[mt][nt][q] = 0.f;

#pragma unroll
    for (int ks = 0; ks < 4; ks++) {
        uint32_t bh[4][2], bl[4][2];
#pragma unroll
        for (int nt = 0; nt < 4; nt++) {
            uint32_t bo = sb + 2 * DS_BUF + (bRow + nt * 8) * DS_SA + ks * 32 + bCol;
            ldsm_x2(bh[nt], bo);
            ldsm_x2(bl[nt], bo + DS_BUF);
        }
#pragma unroll
        for (int mt = 0; mt < 4; mt++) {
            uint32_t ah[4], al[4];
            uint32_t ao = sb + (aRow + mt * 16) * DS_SA + ks * 32 + aCol;
            ldsm_x4(ah, ao);
            ldsm_x4(al, ao + DS_BUF);
#pragma unroll
            for (int nt = 0; nt < 4; nt++) {
                mma16816(acc[mt][nt], ah, bh[nt]);
                mma16816(acc[mt][nt], ah, bl[nt]);
                mma16816(acc[mt][nt], al, bh[nt]);
            }
        }
    }

    const int ri = i0 + wm * 64 + (lane >> 2);
    const int cj = j0 + wn * 32 + (lane & 3) * 2;
#pragma unroll
    for (int mt = 0; mt < 4; mt++) {
        int ia = ri + mt * 16;
        float n2a = n2[ia], n2b = n2[ia + 8];
#pragma unroll
        for (int nt = 0; nt < 4; nt++) {
            int j = cj + nt * 8;
            float nj0 = n2[j], nj1 = n2[j + 1];
            float2 p0 = *(const float2*)&pf[(long)ia * NN + j];
            float2 p1 = *(const float2*)&pf[(long)(ia + 8) * NN + j];
            float* a = acc[mt][nt];
            float s00 = n2a + nj0 - 2.f * a[0];
            float s01 = n2a + nj1 - 2.f * a[1];
            float s10 = n2b + nj0 - 2.f * a[2];
            float s11 = n2b + nj1 - 2.f * a[3];
            float d00 = (s00 > 0.f) ? sqrtf(s00) : 0.f;
            float d01 = (s01 > 0.f) ? sqrtf(s01) : 0.f;
            float d10 = (s10 > 0.f) ? sqrtf(s10) : 0.f;
            float d11 = (s11 > 0.f) ? sqrtf(s11) : 0.f;
            *(float2*)&Fo[(long)ia * NN + j]       = make_float2(d00 * p0.x, d01 * p0.y);
            *(float2*)&Fo[(long)(ia + 8) * NN + j] = make_float2(d10 * p1.x, d11 * p1.y);
        }
    }
}

// ---------------- row-wise squared norms of E [NN,64] -----------------------
__global__ void n2_kernel(const float* __restrict__ E, float* __restrict__ n2)
{
    int row  = blockIdx.x * 8 + threadIdx.x / 32;
    int lane = threadIdx.x % 32;
    const float* e = E + (long)row * 64;
    float a = e[lane], b = e[lane + 32];
    float v = a * a + b * b;
#pragma unroll
    for (int off = 16; off; off >>= 1)
        v += __shfl_down_sync(0xffffffffu, v, off);
    if (lane == 0) n2[row] = v;
}

// ---------------- Fg = Fo @ members : 256 blocks x 32 rows ------------------
__global__ void fg_kernel(const float* __restrict__ Fo,
                          const float* __restrict__ members,
                          float* __restrict__ Fg)
{
    const int lane = threadIdx.x & 31, wid = threadIdx.x >> 5;
    const int r0 = blockIdx.x * 32 + wid * 4;     // 4 rows per warp

    float acc[4][8];
#pragma unroll
    for (int rr = 0; rr < 4; rr++)
#pragma unroll
        for (int k = 0; k < 8; k++) acc[rr][k] = 0.f;

    for (int j = lane * 4; j < NN; j += 128) {
        float4 m[4][2];
#pragma unroll
        for (int jj = 0; jj < 4; jj++) {
            m[jj][0] = *(const float4*)&members[(long)(j + jj) * 8];
            m[jj][1] = *(const float4*)&members[(long)(j + jj) * 8 + 4];
        }
#pragma unroll
        for (int rr = 0; rr < 4; rr++) {
            float4 f = *(const float4*)&Fo[(long)(r0 + rr) * NN + j];
            float fv[4] = { f.x, f.y, f.z, f.w };
#pragma unroll
            for (int jj = 0; jj < 4; jj++) {
                acc[rr][0] = fmaf(fv[jj], m[jj][0].x, acc[rr][0]);
                acc[rr][1] = fmaf(fv[jj], m[jj][0].y, acc[rr][1]);
                acc[rr][2] = fmaf(fv[jj], m[jj][0].z, acc[rr][2]);
                acc[rr][3] = fmaf(fv[jj], m[jj][0].w, acc[rr][3]);
                acc[rr][4] = fmaf(fv[jj], m[jj][1].x, acc[rr][4]);
                acc[rr][5] = fmaf(fv[jj], m[jj][1].y, acc[rr][5]);
                acc[rr][6] = fmaf(fv[jj], m[jj][1].z, acc[rr][6]);
                acc[rr][7] = fmaf(fv[jj], m[jj][1].w, acc[rr][7]);
            }
        }
    }
#pragma unroll
    for (int rr = 0; rr < 4; rr++) {
#pragma unroll
        for (int k = 0; k < 8; k++) {
            float v = acc[rr][k];
#pragma unroll
            for (int off = 16; off; off >>= 1)
                v += __shfl_down_sync(0xffffffffu, v, off);
            if (lane == 0) Fg[(long)(r0 + rr) * 8 + k] = v;
        }
    }
}

// ---------------- d0 GEMV split-K -------------------------------------------
__global__ void d0_partial_kernel(const float* __restrict__ Fg,
                                  const float* __restrict__ W,
                                  float* __restrict__ part)
{
    __shared__ float sF[256];
    const int c = blockIdx.x;
    const int t = threadIdx.x;
    sF[t] = Fg[c * 256 + t];
    __syncthreads();

    float4 acc = make_float4(0.f, 0.f, 0.f, 0.f);
    const float4* Wv = (const float4*)W + (long)(c * 256) * 256 + t;
#pragma unroll 4
    for (int r = 0; r < 256; r++) {
        float f = sF[r];
        float4 w = Wv[(long)r * 256];
        acc.x = fmaf(f, w.x, acc.x);
        acc.y = fmaf(f, w.y, acc.y);
        acc.z = fmaf(f, w.z, acc.z);
        acc.w = fmaf(f, w.w, acc.w);
    }
    ((float4*)part)[c * 256 + t] = acc;
}

__global__ void d0_reduce_kernel(const float* __restrict__ part,
                                 const float* __restrict__ bias,
                                 float* __restrict__ d0)
{
    const int col = threadIdx.x;
    float v = 0.f;
    for (int c = 0; c < 256; c++) v += part[c * 1024 + col];
    v += bias[col];
    d0[col] = fmaxf(v, 0.f);
}

// ---------------- d1 = relu(d0 @ W_d1 + b_d1) --------------------------------
__global__ void d1_kernel(const float* __restrict__ d0,
                          const float* __restrict__ W,
                          const float* __restrict__ bias,
                          float* __restrict__ d1)
{
    const int col = blockIdx.x * 32 + threadIdx.x % 32;
    const int rg  = threadIdx.x / 32;
    float acc = 0.f;
    for (int r = rg; r < 1024; r += 8)
        acc = fmaf(d0[r], W[r * 256 + col], acc);
    __shared__ float s[8][32];
    s[rg][threadIdx.x % 32] = acc;
    __syncthreads();
    if (rg == 0) {
        float v = acc;
#pragma unroll
        for (int g = 1; g < 8; g++) v += s[g][threadIdx.x];
        v += bias[col];
        d1[col] = fmaxf(v, 0.f);
    }
}

// ---------------- final: softmax(d1 @ W_d2) ----------------------------------
__global__ void final_kernel(const float* __restrict__ d1,
                             const float* __restrict__ W,
                             float* __restrict__ out)
{
    const int lane = threadIdx.x;
    float acc[8];
#pragma unroll
    for (int k = 0; k < 8; k++) acc[k] = 0.f;
    for (int r = lane; r < 256; r += 32) {
        float v = d1[r];
        const float* w = W + r * 8;
#pragma unroll
        for (int k = 0; k < 8; k++) acc[k] = fmaf(v, w[k], acc[k]);
    }
#pragma unroll
    for (int k = 0; k < 8; k++)
#pragma unroll
        for (int off = 16; off; off >>= 1)
            acc[k] += __shfl_down_sync(0xffffffffu, acc[k], off);
    if (lane == 0) {
        float mx = acc[0];
#pragma unroll
        for (int k = 1; k < 8; k++) mx = fmaxf(mx, acc[k]);
        float e[8], s = 0.f;
#pragma unroll
        for (int k = 0; k < 8; k++) { e[k] = expf(acc[k] - mx); s += e[k]; }
#pragma unroll
        for (int k = 0; k < 8; k++) out[k] = e[k] / s;
    }
}

// ---------------- launch ----------------------------------------------------
extern "C" void kernel_launch(void* const* d_in, const int* in_sizes, int n_in,
                              void* d_out, int out_size)
{
    const float* F_    = (const float*)d_in[0];
    const float* X     = (const float*)d_in[1];
    const float* W_e0  = (const float*)d_in[2];
    const float* b_e0  = (const float*)d_in[3];
    const float* W_e1  = (const float*)d_in[4];
    const float* b_e1  = (const float*)d_in[5];
    const float* W_e2  = (const float*)d_in[6];
    const float* b_e2  = (const float*)d_in[7];
    const float* W_d0  = (const float*)d_in[8];
    const float* b_d0  = (const float*)d_in[9];
    const float* W_d1  = (const float*)d_in[10];
    const float* b_d1  = (const float*)d_in[11];
    const float* W_d2  = (const float*)d_in[12];
    const float* pf    = (const float*)d_in[13];
    const float* memb  = (const float*)d_in[14];

    float* out    = (float*)d_out;
    float* E_out  = out;
    float* F_out  = out + (long)NN * 64;
    float* O_out  = out + (long)NN * 64 + (long)NN * NN;

    float *p_n2, *p_Fg, *p_part, *p_d0, *p_d1;
    __nv_bfloat16 *p_Fh, *p_Fl, *p_Xth, *p_Xtl, *p_Eh, *p_El;
    __nv_bfloat16 *p_ih, *p_il, *p_h0h, *p_h0l, *p_h1h, *p_h1l;
    __nv_bfloat16 *p_W0h, *p_W0l, *p_W1h, *p_W1l, *p_W2h, *p_W2l;
    cudaGetSymbolAddress((void**)&p_n2,   g_n2);
    cudaGetSymbolAddress((void**)&p_Fg,   g_Fg);
    cudaGetSymbolAddress((void**)&p_part, g_part);
    cudaGetSymbolAddress((void**)&p_d0,   g_d0);
    cudaGetSymbolAddress((void**)&p_d1,   g_d1);
    cudaGetSymbolAddress((void**)&p_Fh,   g_Fh);
    cudaGetSymbolAddress((void**)&p_Fl,   g_Fl);
    cudaGetSymbolAddress((void**)&p_Xth,  g_Xth);
    cudaGetSymbolAddress((void**)&p_Xtl,  g_Xtl);
    cudaGetSymbolAddress((void**)&p_Eh,   g_Eh);
    cudaGetSymbolAddress((void**)&p_El,   g_El);
    cudaGetSymbolAddress((void**)&p_ih,   g_ih);
    cudaGetSymbolAddress((void**)&p_il,   g_il);
    cudaGetSymbolAddress((void**)&p_h0h,  g_h0h);
    cudaGetSymbolAddress((void**)&p_h0l,  g_h0l);
    cudaGetSymbolAddress((void**)&p_h1h,  g_h1h);
    cudaGetSymbolAddress((void**)&p_h1l,  g_h1l);
    cudaGetSymbolAddress((void**)&p_W0h,  g_W0h);
    cudaGetSymbolAddress((void**)&p_W0l,  g_W0l);
    cudaGetSymbolAddress((void**)&p_W1h,  g_W1h);
    cudaGetSymbolAddress((void**)&p_W1l,  g_W1l);
    cudaGetSymbolAddress((void**)&p_W2h,  g_W2h);
    cudaGetSymbolAddress((void**)&p_W2l,  g_W2l);

    cudaFuncSetAttribute(gemm1_mma, cudaFuncAttributeMaxDynamicSharedMemorySize, G1_SMEM);
    cudaFuncSetAttribute(dist_mma,  cudaFuncAttributeMaxDynamicSharedMemorySize, DS_SMEM);
    cudaFuncSetAttribute(enc_mma<4,1,0,1>, cudaFuncAttributeMaxDynamicSharedMemorySize, 163840);
    cudaFuncSetAttribute(enc_mma<2,0,1,1>, cudaFuncAttributeMaxDynamicSharedMemorySize, 122880);

    // 0) bf16 hi/lo splits of inputs
    fsplit_kernel<<<65536, 256>>>((const float4*)F_, (uint2*)p_Fh, (uint2*)p_Fl);
    tsplit_kernel<<<dim3(8, 256), dim3(32, 8)>>>(X, p_Xth, p_Xtl, NN, 256);
    tsplit_kernel<<<dim3(8, 8),  dim3(32, 8)>>>(W_e0, p_W0h, p_W0l, 256, 256);
    tsplit_kernel<<<dim3(4, 8),  dim3(32, 8)>>>(W_e1, p_W1h, p_W1l, 256, 128);
    tsplit_kernel<<<dim3(2, 4),  dim3(32, 8)>>>(W_e2, p_W2h, p_W2l, 128, 64);

    // 1) inp = F_ @ X (HMMA), split epilogue -> ih/il directly
    gemm1_mma<<<dim3(2, 64), 256, G1_SMEM>>>(p_Fh, p_Fl, p_Xth, p_Xtl, p_ih, p_il);

    // 2) h0 = tanh(inp @ W_e0 + b)
    enc_mma<4,1,0,1><<<dim3(2, 64), 256, 163840>>>(
        p_ih, p_il, p_W0h, p_W0l, b_e0, nullptr, p_h0h, p_h0l, 256, 256, 256, 256);
    // 3) h1 = tanh(h0 @ W_e1 + b)
    enc_mma<4,1,0,1><<<dim3(1, 64), 256, 163840>>>(
        p_h0h, p_h0l, p_W1h, p_W1l, b_e1, nullptr, p_h1h, p_h1l, 256, 256, 256, 128);
    // 4) E = h1 @ W_e2 + b -> fp32 to d_out + splits
    enc_mma<2,0,1,1><<<dim3(1, 64), 256, 122880>>>(
        p_h1h, p_h1l, p_W2h, p_W2l, b_e2, E_out, p_Eh, p_El, 128, 128, 128, 64);

    // 5) row norms
    n2_kernel<<<NN / 8, 256>>>(E_out, p_n2);
    // 6) new_force = dist(E) * pf (HMMA, occ 2) -> d_out
    dist_mma<<<dim3(NN / 128, NN / 128), 256, DS_SMEM>>>(p_Eh, p_El, p_n2, pf, F_out);
    // 7) Fg = new_force @ members
    fg_kernel<<<NN / 32, 256>>>(F_out, memb, p_Fg);
    // 8) d0 = relu(Fg @ W_d0 + b_d0)
    d0_partial_kernel<<<256, 256>>>(p_Fg, W_d0, p_part);
    d0_reduce_kernel<<<1, 1024>>>(p_part, b_d0, p_d0);
    // 9) d1 = relu(d0 @ W_d1 + b_d1)
    d1_kernel<<<8, 256>>>(p_d0, W_d1, b_d1, p_d1);
    // 10) out = softmax(d1 @ W_d2)
    final_kernel<<<1, 32>>>(p_d1, W_d2, O_out);
}

// round 12
// speedup vs baseline: 2.3111x; 1.0436x over previous
#include <cuda_runtime.h>
#include <cuda_bf16.h>
#include <math.h>
#include <stdint.h>

#define NN   8192
#define KC   8

// ---------------- scratch (device globals; no allocation allowed) ----------
__device__ float g_n2 [NN];
__device__ float g_Fg [NN * KC];
__device__ float g_part[512 * 1024];
__device__ float g_d0 [1024];
__device__ float g_d1 [256];
// bf16 hi/lo splits
__device__ __nv_bfloat16 g_Xth[256 * NN];   // X^T hi  [256, 8192]
__device__ __nv_bfloat16 g_Xtl[256 * NN];   // X^T lo
__device__ __nv_bfloat16 g_ih [NN * 256];   // inp splits (written by gemm1 epilogue)
__device__ __nv_bfloat16 g_il [NN * 256];
__device__ __nv_bfloat16 g_h0h[NN * 256];
__device__ __nv_bfloat16 g_h0l[NN * 256];
__device__ __nv_bfloat16 g_h1h[NN * 128];
__device__ __nv_bfloat16 g_h1l[NN * 128];
__device__ __nv_bfloat16 g_Eh [NN * 64];
__device__ __nv_bfloat16 g_El [NN * 64];
// transposed weight splits [N,K]
__device__ __nv_bfloat16 g_W0h[256 * 256], g_W0l[256 * 256];
__device__ __nv_bfloat16 g_W1h[128 * 256], g_W1l[128 * 256];
__device__ __nv_bfloat16 g_W2h[64 * 128],  g_W2l[64 * 128];

// ================= PTX helpers (baseline PTX only) ==========================
__device__ __forceinline__ uint32_t smem_to_u32(const void* p) {
    uint32_t a;
    asm("{ .reg .u64 t; cvta.to.shared.u64 t, %1; cvt.u32.u64 %0, t; }"
        : "=r"(a) : "l"(p));
    return a;
}
__device__ __forceinline__ void cpasync16(uint32_t dst, const void* src) {
    asm volatile("cp.async.cg.shared.global [%0], [%1], 16;" :: "r"(dst), "l"(src));
}
#define CPASYNC_COMMIT()    asm volatile("cp.async.commit_group;" ::: "memory")
#define CPASYNC_WAIT(n)     asm volatile("cp.async.wait_group %0;" :: "n"(n) : "memory")

__device__ __forceinline__ void ldsm_x4(uint32_t* r, uint32_t addr) {
    asm volatile("ldmatrix.sync.aligned.m8n8.x4.shared.b16 {%0,%1,%2,%3}, [%4];"
                 : "=r"(r[0]), "=r"(r[1]), "=r"(r[2]), "=r"(r[3]) : "r"(addr));
}
__device__ __forceinline__ void ldsm_x2(uint32_t* r, uint32_t addr) {
    asm volatile("ldmatrix.sync.aligned.m8n8.x2.shared.b16 {%0,%1}, [%2];"
                 : "=r"(r[0]), "=r"(r[1]) : "r"(addr));
}
__device__ __forceinline__ void mma16816(float* c, const uint32_t* a, const uint32_t* b) {
    asm volatile("mma.sync.aligned.m16n8k16.row.col.f32.bf16.bf16.f32 "
                 "{%0,%1,%2,%3}, {%4,%5,%6,%7}, {%8,%9}, {%0,%1,%2,%3};"
                 : "+f"(c[0]), "+f"(c[1]), "+f"(c[2]), "+f"(c[3])
                 : "r"(a[0]), "r"(a[1]), "r"(a[2]), "r"(a[3]), "r"(b[0]), "r"(b[1]));
}

// ================= split pre-pass kernels ===================================
// generic transpose-split: in [R,Cc] fp32 -> out [Cc,R] bf16 h/l
__global__ void tsplit_kernel(const float* __restrict__ in,
                              __nv_bfloat16* __restrict__ oh,
                              __nv_bfloat16* __restrict__ ol,
                              int R, int Cc)
{
    __shared__ float t[32][33];
    int bx = blockIdx.x * 32;
    int by = blockIdx.y * 32;
    for (int i = threadIdx.y; i < 32; i += 8)
        t[i][threadIdx.x] = in[(long)(by + i) * Cc + bx + threadIdx.x];
    __syncthreads();
    for (int i = threadIdx.y; i < 32; i += 8) {
        float v = t[threadIdx.x][i];
        __nv_bfloat16 h = __float2bfloat16(v);
        __nv_bfloat16 l = __float2bfloat16(v - __bfloat162float(h));
        long o = (long)(bx + i) * R + by + threadIdx.x;
        oh[o] = h; ol[o] = l;
    }
}

// ================= GEMM1 (HMMA): ih/il = split(F_ @ X), bf16x3 ==============
// A = F_ fp32 loaded directly; in-kernel hi/lo conversion (fsplit fused).
// 128x128 tile, BK=32, 4-stage cp.async pipeline, 8 warps (2m x 4n).
#define G2_AFS    144                       // fp32 A row stride (128B + 16 pad)
#define G2_AFB    (128 * G2_AFS)            // 18432 fp32 A buffer
#define G2_BB     (128 * 80)                // 10240 per B operand
#define G2_STAGE  (G2_AFB + 2 * G2_BB)      // 38912
#define G2_AHL    (128 * 80)                // 10240 per converted-A buffer
#define G2_SMEM   (4 * G2_STAGE + 4 * G2_AHL)  // 196608

__global__ void __launch_bounds__(256, 1) gemm1_mma(
    const float* __restrict__ A_,
    const __nv_bfloat16* __restrict__ Bh_, const __nv_bfloat16* __restrict__ Bl_,
    __nv_bfloat16* __restrict__ Ch, __nv_bfloat16* __restrict__ Cl)
{
    extern __shared__ char smem[];
    const uint32_t sb = smem_to_u32(smem);
    const uint32_t ahl0 = sb + 4 * G2_STAGE;
    const int tid = threadIdx.x, lane = tid & 31, wid = tid >> 5;
    const int wm = wid >> 2, wn = wid & 3;
    const int mg0 = blockIdx.y * 128, ng0 = blockIdx.x * 128;

    const uint32_t aRow = wm * 64 + (lane & 7) + ((lane >> 3) & 1) * 8;
    const uint32_t aCol = (lane >> 4) * 16;
    const uint32_t bRow = wn * 32 + (lane & 7);
    const uint32_t bCol = ((lane >> 3) & 1) * 16;

    float acc[4][4][4];
#pragma unroll
    for (int mt = 0; mt < 4; mt++)
#pragma unroll
        for (int nt = 0; nt < 4; nt++)
#pragma unroll
            for (int q = 0; q < 4; q++) acc[mt][nt][q] = 0.f;

    auto load_stage = [&](int s) {
        uint32_t base = sb + (s & 3) * G2_STAGE;
        long k0 = (long)s * 32;
        // A fp32: 128 rows x 128B = 1024 chunks of 16B
#pragma unroll
        for (int h = 0; h < 4; h++) {
            int c = tid + h * 256;
            int row = c >> 3, seg = c & 7;
            cpasync16(base + row * G2_AFS + seg * 16,
                      A_ + (long)(mg0 + row) * NN + k0 + seg * 4);
        }
        // B bf16 h/l: 128 rows x 64B = 512 chunks each
#pragma unroll
        for (int h = 0; h < 2; h++) {
            int c = tid + h * 256;
            int row = c >> 2, seg = c & 3;
            uint32_t d = base + G2_AFB + row * 80 + seg * 16;
            long gb = (long)(ng0 + row) * NN + k0 + seg * 8;
            cpasync16(d,         Bh_ + gb);
            cpasync16(d + G2_BB, Bl_ + gb);
        }
        CPASYNC_COMMIT();
    };

    load_stage(0); load_stage(1); load_stage(2);

    const int nStages = NN / 32;
    for (int it = 0; it < nStages; it++) {
        CPASYNC_WAIT(2);
        __syncthreads();
        if (it + 3 < nStages) load_stage(it + 3);
        else CPASYNC_COMMIT();

        // convert fp32 A stage (it&3) -> bf16 hi/lo buffers (it&1)
        {
            const char* afb = smem + (it & 3) * G2_STAGE;
            char* ah = smem + 4 * G2_STAGE + (it & 1) * 2 * G2_AHL;
            char* al = ah + G2_AHL;
#pragma unroll
            for (int h = 0; h < 4; h++) {
                int c = tid + h * 256;
                int row = c >> 3, seg = c & 7;
                float4 v = *(const float4*)(afb + row * G2_AFS + seg * 16);
                __nv_bfloat162 h01 = __floats2bfloat162_rn(v.x, v.y);
                __nv_bfloat162 h23 = __floats2bfloat162_rn(v.z, v.w);
                float2 f01 = __bfloat1622float2(h01);
                float2 f23 = __bfloat1622float2(h23);
                __nv_bfloat162 l01 = __floats2bfloat162_rn(v.x - f01.x, v.y - f01.y);
                __nv_bfloat162 l23 = __floats2bfloat162_rn(v.z - f23.x, v.w - f23.y);
                uint2 ho, lo;
                ho.x = *(uint32_t*)&h01; ho.y = *(uint32_t*)&h23;
                lo.x = *(uint32_t*)&l01; lo.y = *(uint32_t*)&l23;
                *(uint2*)(ah + row * 80 + seg * 8) = ho;
                *(uint2*)(al + row * 80 + seg * 8) = lo;
            }
        }
        __syncthreads();

        const uint32_t base = sb + (it & 3) * G2_STAGE;
        const uint32_t ahb  = ahl0 + (it & 1) * 2 * G2_AHL;
#pragma unroll
        for (int ks = 0; ks < 2; ks++) {
            uint32_t bh[4][2], bl[4][2];
#pragma unroll
            for (int nt = 0; nt < 4; nt++) {
                uint32_t bo = base + G2_AFB + (bRow + nt * 8) * 80 + ks * 32 + bCol;
                ldsm_x2(bh[nt], bo);
                ldsm_x2(bl[nt], bo + G2_BB);
            }
#pragma unroll
            for (int mt = 0; mt < 4; mt++) {
                uint32_t ah[4], al[4];
                uint32_t ao = ahb + (aRow + mt * 16) * 80 + ks * 32 + aCol;
                ldsm_x4(ah, ao);
                ldsm_x4(al, ao + G2_AHL);
#pragma unroll
                for (int nt = 0; nt < 4; nt++) {
                    mma16816(acc[mt][nt], ah, bh[nt]);
                    mma16816(acc[mt][nt], ah, bl[nt]);
                    mma16816(acc[mt][nt], al, bh[nt]);
                }
            }
        }
    }

    // epilogue: hi/lo-split bf16 write
    const int r0 = mg0 + wm * 64 + (lane >> 2);
    const int c0 = ng0 + wn * 32 + (lane & 3) * 2;
#pragma unroll
    for (int mt = 0; mt < 4; mt++) {
#pragma unroll
        for (int nt = 0; nt < 4; nt++) {
            long r = r0 + mt * 16;
            int  col = c0 + nt * 8;
            float* v = acc[mt][nt];
            __nv_bfloat162 h0 = __floats2bfloat162_rn(v[0], v[1]);
            __nv_bfloat162 h1 = __floats2bfloat162_rn(v[2], v[3]);
            float2 f0 = __bfloat1622float2(h0), f1 = __bfloat1622float2(h1);
            __nv_bfloat162 l0 = __floats2bfloat162_rn(v[0] - f0.x, v[1] - f0.y);
            __nv_bfloat162 l1 = __floats2bfloat162_rn(v[2] - f1.x, v[3] - f1.y);
            *(__nv_bfloat162*)&Ch[r * 256 + col]       = h0;
            *(__nv_bfloat162*)&Ch[(r + 8) * 256 + col] = h1;
            *(__nv_bfloat162*)&Cl[r * 256 + col]       = l0;
            *(__nv_bfloat162*)&Cl[(r + 8) * 256 + col] = l1;
        }
    }
}

// ================= encoder GEMM (HMMA, bf16x3, fused act + split epilogue) ==
template<int NT, int ACT, int WRITE_F, int WRITE_HL>
__global__ void __launch_bounds__(256, 1) enc_mma(
    const __nv_bfloat16* __restrict__ Ah_, const __nv_bfloat16* __restrict__ Al_,
    const __nv_bfloat16* __restrict__ Bh_, const __nv_bfloat16* __restrict__ Bl_,
    const float* __restrict__ bias,
    float* __restrict__ Cf, __nv_bfloat16* __restrict__ Ch, __nv_bfloat16* __restrict__ Cl,
    int Ksz, int lda, int ldb, int ldc)
{
    constexpr int BN     = 32 * NT;
    constexpr int EB_A   = 128 * 80;
    constexpr int EB_B   = BN * 80;
    constexpr int ESTAGE = 2 * EB_A + 2 * EB_B;
    constexpr int B_IT   = (BN * 4) / 256;

    extern __shared__ char smem[];
    const uint32_t sb = smem_to_u32(smem);
    const int tid = threadIdx.x, lane = tid & 31, wid = tid >> 5;
    const int wm = wid >> 2, wn = wid & 3;
    const int mg0 = blockIdx.y * 128, ng0 = blockIdx.x * BN;

    const uint32_t aRow = wm * 64 + (lane & 7) + ((lane >> 3) & 1) * 8;
    const uint32_t aCol = (lane >> 4) * 16;
    const uint32_t bRow = wn * (8 * NT) + (lane & 7);
    const uint32_t bCol = ((lane >> 3) & 1) * 16;

    float acc[4][NT][4];
#pragma unroll
    for (int mt = 0; mt < 4; mt++)
#pragma unroll
        for (int nt = 0; nt < NT; nt++)
#pragma unroll
            for (int q = 0; q < 4; q++) acc[mt][nt][q] = 0.f;

    auto load_stage = [&](int s) {
        uint32_t base = sb + (s & 3) * ESTAGE;
        long k0 = (long)s * 32;
#pragma unroll
        for (int h = 0; h < 2; h++) {
            int c = tid + h * 256;
            int row = c >> 2, seg = c & 3;
            uint32_t d = base + row * 80 + seg * 16;
            long ga = (long)(mg0 + row) * lda + k0 + seg * 8;
            cpasync16(d,        Ah_ + ga);
            cpasync16(d + EB_A, Al_ + ga);
        }
#pragma unroll
        for (int h = 0; h < B_IT; h++) {
            int c = tid + h * 256;
            int row = c >> 2, seg = c & 3;
            uint32_t d = base + 2 * EB_A + row * 80 + seg * 16;
            long gb = (long)(ng0 + row) * ldb + k0 + seg * 8;
            cpasync16(d,        Bh_ + gb);
            cpasync16(d + EB_B, Bl_ + gb);
        }
        CPASYNC_COMMIT();
    };

    load_stage(0); load_stage(1); load_stage(2);

    const int nStages = Ksz / 32;
    for (int it = 0; it < nStages; it++) {
        CPASYNC_WAIT(2);
        __syncthreads();
        if (it + 3 < nStages) load_stage(it + 3);
        else CPASYNC_COMMIT();

        const uint32_t base = sb + (it & 3) * ESTAGE;
#pragma unroll
        for (int ks = 0; ks < 2; ks++) {
            uint32_t bh[NT][2], bl[NT][2];
#pragma unroll
            for (int nt = 0; nt < NT; nt++) {
                uint32_t bo = base + 2 * EB_A + (bRow + nt * 8) * 80 + ks * 32 + bCol;
                ldsm_x2(bh[nt], bo);
                ldsm_x2(bl[nt], bo + EB_B);
            }
#pragma unroll
            for (int mt = 0; mt < 4; mt++) {
                uint32_t ah[4], al[4];
                uint32_t ao = base + (aRow + mt * 16) * 80 + ks * 32 + aCol;
                ldsm_x4(ah, ao);
                ldsm_x4(al, ao + EB_A);
#pragma unroll
                for (int nt = 0; nt < NT; nt++) {
                    mma16816(acc[mt][nt], ah, bh[nt]);
                    mma16816(acc[mt][nt], ah, bl[nt]);
                    mma16816(acc[mt][nt], al, bh[nt]);
                }
            }
        }
    }

    const int r0 = mg0 + wm * 64 + (lane >> 2);
    const int c0 = ng0 + wn * (8 * NT) + (lane & 3) * 2;
#pragma unroll
    for (int mt = 0; mt < 4; mt++) {
#pragma unroll
        for (int nt = 0; nt < NT; nt++) {
            int col = c0 + nt * 8;
            float b0 = bias ? bias[col] : 0.f, b1 = bias ? bias[col + 1] : 0.f;
            float v[4] = { acc[mt][nt][0] + b0, acc[mt][nt][1] + b1,
                           acc[mt][nt][2] + b0, acc[mt][nt][3] + b1 };
            if (ACT == 1) {
#pragma unroll
                for (int q = 0; q < 4; q++) v[q] = tanhf(v[q]);
            }
            long r = r0 + mt * 16;
            if (WRITE_F) {
                *(float2*)&Cf[r * ldc + col]       = make_float2(v[0], v[1]);
                *(float2*)&Cf[(r + 8) * ldc + col] = make_float2(v[2], v[3]);
            }
            if (WRITE_HL) {
                __nv_bfloat162 h0 = __floats2bfloat162_rn(v[0], v[1]);
                __nv_bfloat162 h1 = __floats2bfloat162_rn(v[2], v[3]);
                float2 f0 = __bfloat1622float2(h0), f1 = __bfloat1622float2(h1);
                __nv_bfloat162 l0 = __floats2bfloat162_rn(v[0] - f0.x, v[1] - f0.y);
                __nv_bfloat162 l1 = __floats2bfloat162_rn(v[2] - f1.x, v[3] - f1.y);
                *(__nv_bfloat162*)&Ch[r * ldc + col]       = h0;
                *(__nv_bfloat162*)&Ch[(r + 8) * ldc + col] = h1;
                *(__nv_bfloat162*)&Cl[r * ldc + col]       = l0;
                *(__nv_bfloat162*)&Cl[(r + 8) * ldc + col] = l1;
            }
        }
    }
}

// ================= dist (HMMA): force = sqrt(n2i+n2j-2*E@E^T)+ * pf =========
#define DS_SA    144
#define DS_BUF   (128 * DS_SA)
#define DS_SMEM  (4 * DS_BUF)        // 73728 B -> 2 CTAs/SM

__global__ void __launch_bounds__(256, 2) dist_mma(
    const __nv_bfloat16* __restrict__ Eh, const __nv_bfloat16* __restrict__ El,
    const float* __restrict__ n2, const float* __restrict__ pf,
    float* __restrict__ Fo)
{
    extern __shared__ char smem[];
    const uint32_t sb = smem_to_u32(smem);
    const int tid = threadIdx.x, lane = tid & 31, wid = tid >> 5;
    const int wm = wid >> 2, wn = wid & 3;
    const int i0 = blockIdx.y * 128, j0 = blockIdx.x * 128;

#pragma unroll
    for (int h = 0; h < 4; h++) {
        int c = tid + h * 256;
        int row = c >> 3, seg = c & 7;
        uint32_t d = sb + row * DS_SA + seg * 16;
        long gi = (long)(i0 + row) * 64 + seg * 8;
        long gj = (long)(j0 + row) * 64 + seg * 8;
        cpasync16(d,              Eh + gi);
        cpasync16(d + DS_BUF,     El + gi);
        cpasync16(d + 2 * DS_BUF, Eh + gj);
        cpasync16(d + 3 * DS_BUF, El + gj);
    }
    CPASYNC_COMMIT();
    CPASYNC_WAIT(0);
    __syncthreads();

    const uint32_t aRow = wm * 64 + (lane & 7) + ((lane >> 3) & 1) * 8;
    const uint32_t aCol = (lane >> 4) * 16;
    const uint32_t bRow = wn * 32 + (lane & 7);
    const uint32_t bCol = ((lane >> 3) & 1) * 16;

    float acc[4][4][4];
#pragma unroll
    for (int mt = 0; mt < 4; mt++)
#pragma unroll
        for (int nt = 0; nt < 4; nt++)
#pragma unroll
            for (int q = 0; q < 4; q++) acc[mt][nt][q] = 0.f;

#pragma unroll
    for (int ks = 0; ks < 4; ks++) {
        uint32_t bh[4][2], bl[4][2];
#pragma unroll
        for (int nt = 0; nt < 4; nt++) {
            uint32_t bo = sb + 2 * DS_BUF + (bRow + nt * 8) * DS_SA + ks * 32 + bCol;
            ldsm_x2(bh[nt], bo);
            ldsm_x2(bl[nt], bo + DS_BUF);
        }
#pragma unroll
        for (int mt = 0; mt < 4; mt++) {
            uint32_t ah[4], al[4];
            uint32_t ao = sb + (aRow + mt * 16) * DS_SA + ks * 32 + aCol;
            ldsm_x4(ah, ao);
            ldsm_x4(al, ao + DS_BUF);
#pragma unroll
            for (int nt = 0; nt < 4; nt++) {
                mma16816(acc[mt][nt], ah, bh[nt]);
                mma16816(acc[mt][nt], ah, bl[nt]);
                mma16816(acc[mt][nt], al, bh[nt]);
            }
        }
    }

    const int ri = i0 + wm * 64 + (lane >> 2);
    const int cj = j0 + wn * 32 + (lane & 3) * 2;
#pragma unroll
    for (int mt = 0; mt < 4; mt++) {
        int ia = ri + mt * 16;
        float n2a = n2[ia], n2b = n2[ia + 8];
#pragma unroll
        for (int nt = 0; nt < 4; nt++) {
            int j = cj + nt * 8;
            float nj0 = n2[j], nj1 = n2[j + 1];
            float2 p0 = *(const float2*)&pf[(long)ia * NN + j];
            float2 p1 = *(const float2*)&pf[(long)(ia + 8) * NN + j];
            float* a = acc[mt][nt];
            float s00 = n2a + nj0 - 2.f * a[0];
            float s01 = n2a + nj1 - 2.f * a[1];
            float s10 = n2b + nj0 - 2.f * a[2];
            float s11 = n2b + nj1 - 2.f * a[3];
            float d00 = (s00 > 0.f) ? sqrtf(s00) : 0.f;
            float d01 = (s01 > 0.f) ? sqrtf(s01) : 0.f;
            float d10 = (s10 > 0.f) ? sqrtf(s10) : 0.f;
            float d11 = (s11 > 0.f) ? sqrtf(s11) : 0.f;
            *(float2*)&Fo[(long)ia * NN + j]       = make_float2(d00 * p0.x, d01 * p0.y);
            *(float2*)&Fo[(long)(ia + 8) * NN + j] = make_float2(d10 * p1.x, d11 * p1.y);
        }
    }
}

// ---------------- row-wise squared norms of E [NN,64] -----------------------
__global__ void n2_kernel(const float* __restrict__ E, float* __restrict__ n2)
{
    int row  = blockIdx.x * 8 + threadIdx.x / 32;
    int lane = threadIdx.x % 32;
    const float* e = E + (long)row * 64;
    float a = e[lane], b = e[lane + 32];
    float v = a * a + b * b;
#pragma unroll
    for (int off = 16; off; off >>= 1)
        v += __shfl_down_sync(0xffffffffu, v, off);
    if (lane == 0) n2[row] = v;
}

// ---------------- Fg = Fo @ members : 256 blocks x 32 rows ------------------
__global__ void fg_kernel(const float* __restrict__ Fo,
                          const float* __restrict__ members,
                          float* __restrict__ Fg)
{
    const int lane = threadIdx.x & 31, wid = threadIdx.x >> 5;
    const int r0 = blockIdx.x * 32 + wid * 4;

    float acc[4][8];
#pragma unroll
    for (int rr = 0; rr < 4; rr++)
#pragma unroll
        for (int k = 0; k < 8; k++) acc[rr][k] = 0.f;

    for (int j = lane * 4; j < NN; j += 128) {
        float4 m[4][2];
#pragma unroll
        for (int jj = 0; jj < 4; jj++) {
            m[jj][0] = *(const float4*)&members[(long)(j + jj) * 8];
            m[jj][1] = *(const float4*)&members[(long)(j + jj) * 8 + 4];
        }
#pragma unroll
        for (int rr = 0; rr < 4; rr++) {
            float4 f = *(const float4*)&Fo[(long)(r0 + rr) * NN + j];
            float fv[4] = { f.x, f.y, f.z, f.w };
#pragma unroll
            for (int jj = 0; jj < 4; jj++) {
                acc[rr][0] = fmaf(fv[jj], m[jj][0].x, acc[rr][0]);
                acc[rr][1] = fmaf(fv[jj], m[jj][0].y, acc[rr][1]);
                acc[rr][2] = fmaf(fv[jj], m[jj][0].z, acc[rr][2]);
                acc[rr][3] = fmaf(fv[jj], m[jj][0].w, acc[rr][3]);
                acc[rr][4] = fmaf(fv[jj], m[jj][1].x, acc[rr][4]);
                acc[rr][5] = fmaf(fv[jj], m[jj][1].y, acc[rr][5]);
                acc[rr][6] = fmaf(fv[jj], m[jj][1].z, acc[rr][6]);
                acc[rr][7] = fmaf(fv[jj], m[jj][1].w, acc[rr][7]);
            }
        }
    }
#pragma unroll
    for (int rr = 0; rr < 4; rr++) {
#pragma unroll
        for (int k = 0; k < 8; k++) {
            float v = acc[rr][k];
#pragma unroll
            for (int off = 16; off; off >>= 1)
                v += __shfl_down_sync(0xffffffffu, v, off);
            if (lane == 0) Fg[(long)(r0 + rr) * 8 + k] = v;
        }
    }
}

// ---------------- d0 GEMV split-K: 512 chunks of 128 rows -------------------
__global__ void d0_partial_kernel(const float* __restrict__ Fg,
                                  const float* __restrict__ W,
                                  float* __restrict__ part)
{
    __shared__ float sF[128];
    const int c = blockIdx.x;
    const int t = threadIdx.x;
    if (t < 128) sF[t] = Fg[c * 128 + t];
    __syncthreads();

    float4 acc = make_float4(0.f, 0.f, 0.f, 0.f);
    const float4* Wv = (const float4*)W + (long)(c * 128) * 256 + t;
#pragma unroll 8
    for (int r = 0; r < 128; r++) {
        float f = sF[r];
        float4 w = Wv[(long)r * 256];
        acc.x = fmaf(f, w.x, acc.x);
        acc.y = fmaf(f, w.y, acc.y);
        acc.z = fmaf(f, w.z, acc.z);
        acc.w = fmaf(f, w.w, acc.w);
    }
    ((float4*)part)[c * 256 + t] = acc;
}

__global__ void d0_reduce_kernel(const float* __restrict__ part,
                                 const float* __restrict__ bias,
                                 float* __restrict__ d0)
{
    const int col = threadIdx.x;
    float v = 0.f;
    for (int c = 0; c < 512; c++) v += part[c * 1024 + col];
    v += bias[col];
    d0[col] = fmaxf(v, 0.f);
}

// ---------------- d1 = relu(d0 @ W_d1 + b_d1) --------------------------------
__global__ void d1_kernel(const float* __restrict__ d0,
                          const float* __restrict__ W,
                          const float* __restrict__ bias,
                          float* __restrict__ d1)
{
    const int col = blockIdx.x * 32 + threadIdx.x % 32;
    const int rg  = threadIdx.x / 32;
    float acc = 0.f;
    for (int r = rg; r < 1024; r += 8)
        acc = fmaf(d0[r], W[r * 256 + col], acc);
    __shared__ float s[8][32];
    s[rg][threadIdx.x % 32] = acc;
    __syncthreads();
    if (rg == 0) {
        float v = acc;
#pragma unroll
        for (int g = 1; g < 8; g++) v += s[g][threadIdx.x];
        v += bias[col];
        d1[col] = fmaxf(v, 0.f);
    }
}

// ---------------- final: softmax(d1 @ W_d2) ----------------------------------
__global__ void final_kernel(const float* __restrict__ d1,
                             const float* __restrict__ W,
                             float* __restrict__ out)
{
    const int lane = threadIdx.x;
    float acc[8];
#pragma unroll
    for (int k = 0; k < 8; k++) acc[k] = 0.f;
    for (int r = lane; r < 256; r += 32) {
        float v = d1[r];
        const float* w = W + r * 8;
#pragma unroll
        for (int k = 0; k < 8; k++) acc[k] = fmaf(v, w[k], acc[k]);
    }
#pragma unroll
    for (int k = 0; k < 8; k++)
#pragma unroll
        for (int off = 16; off; off >>= 1)
            acc[k] += __shfl_down_sync(0xffffffffu, acc[k], off);
    if (lane == 0) {
        float mx = acc[0];
#pragma unroll
        for (int k = 1; k < 8; k++) mx = fmaxf(mx, acc[k]);
        float e[8], s = 0.f;
#pragma unroll
        for (int k = 0; k < 8; k++) { e[k] = expf(acc[k] - mx); s += e[k]; }
#pragma unroll
        for (int k = 0; k < 8; k++) out[k] = e[k] / s;
    }
}

// ---------------- launch ----------------------------------------------------
extern "C" void kernel_launch(void* const* d_in, const int* in_sizes, int n_in,
                              void* d_out, int out_size)
{
    const float* F_    = (const float*)d_in[0];
    const float* X     = (const float*)d_in[1];
    const float* W_e0  = (const float*)d_in[2];
    const float* b_e0  = (const float*)d_in[3];
    const float* W_e1  = (const float*)d_in[4];
    const float* b_e1  = (const float*)d_in[5];
    const float* W_e2  = (const float*)d_in[6];
    const float* b_e2  = (const float*)d_in[7];
    const float* W_d0  = (const float*)d_in[8];
    const float* b_d0  = (const float*)d_in[9];
    const float* W_d1  = (const float*)d_in[10];
    const float* b_d1  = (const float*)d_in[11];
    const float* W_d2  = (const float*)d_in[12];
    const float* pf    = (const float*)d_in[13];
    const float* memb  = (const float*)d_in[14];

    float* out    = (float*)d_out;
    float* E_out  = out;
    float* F_out  = out + (long)NN * 64;
    float* O_out  = out + (long)NN * 64 + (long)NN * NN;

    float *p_n2, *p_Fg, *p_part, *p_d0, *p_d1;
    __nv_bfloat16 *p_Xth, *p_Xtl, *p_Eh, *p_El;
    __nv_bfloat16 *p_ih, *p_il, *p_h0h, *p_h0l, *p_h1h, *p_h1l;
    __nv_bfloat16 *p_W0h, *p_W0l, *p_W1h, *p_W1l, *p_W2h, *p_W2l;
    cudaGetSymbolAddress((void**)&p_n2,   g_n2);
    cudaGetSymbolAddress((void**)&p_Fg,   g_Fg);
    cudaGetSymbolAddress((void**)&p_part, g_part);
    cudaGetSymbolAddress((void**)&p_d0,   g_d0);
    cudaGetSymbolAddress((void**)&p_d1,   g_d1);
    cudaGetSymbolAddress((void**)&p_Xth,  g_Xth);
    cudaGetSymbolAddress((void**)&p_Xtl,  g_Xtl);
    cudaGetSymbolAddress((void**)&p_Eh,   g_Eh);
    cudaGetSymbolAddress((void**)&p_El,   g_El);
    cudaGetSymbolAddress((void**)&p_ih,   g_ih);
    cudaGetSymbolAddress((void**)&p_il,   g_il);
    cudaGetSymbolAddress((void**)&p_h0h,  g_h0h);
    cudaGetSymbolAddress((void**)&p_h0l,  g_h0l);
    cudaGetSymbolAddress((void**)&p_h1h,  g_h1h);
    cudaGetSymbolAddress((void**)&p_h1l,  g_h1l);
    cudaGetSymbolAddress((void**)&p_W0h,  g_W0h);
    cudaGetSymbolAddress((void**)&p_W0l,  g_W0l);
    cudaGetSymbolAddress((void**)&p_W1h,  g_W1h);
    cudaGetSymbolAddress((void**)&p_W1l,  g_W1l);
    cudaGetSymbolAddress((void**)&p_W2h,  g_W2h);
    cudaGetSymbolAddress((void**)&p_W2l,  g_W2l);

    cudaFuncSetAttribute(gemm1_mma, cudaFuncAttributeMaxDynamicSharedMemorySize, G2_SMEM);
    cudaFuncSetAttribute(dist_mma,  cudaFuncAttributeMaxDynamicSharedMemorySize, DS_SMEM);
    cudaFuncSetAttribute(enc_mma<4,1,0,1>, cudaFuncAttributeMaxDynamicSharedMemorySize, 163840);
    cudaFuncSetAttribute(enc_mma<2,0,1,1>, cudaFuncAttributeMaxDynamicSharedMemorySize, 122880);

    // launch index 3 = gemm1_mma (ncu captures the 4th launch)
    tsplit_kernel<<<dim3(8, 256), dim3(32, 8)>>>(X, p_Xth, p_Xtl, NN, 256);      // 0
    tsplit_kernel<<<dim3(8, 8),  dim3(32, 8)>>>(W_e0, p_W0h, p_W0l, 256, 256);   // 1
    tsplit_kernel<<<dim3(4, 8),  dim3(32, 8)>>>(W_e1, p_W1h, p_W1l, 256, 128);   // 2
    // 1) inp = F_ @ X (HMMA, in-kernel F split), split epilogue -> ih/il
    gemm1_mma<<<dim3(2, 64), 256, G2_SMEM>>>(F_, p_Xth, p_Xtl, p_ih, p_il);      // 3
    tsplit_kernel<<<dim3(2, 4),  dim3(32, 8)>>>(W_e2, p_W2h, p_W2l, 128, 64);    // 4

    // 2) h0 = tanh(inp @ W_e0 + b)
    enc_mma<4,1,0,1><<<dim3(2, 64), 256, 163840>>>(
        p_ih, p_il, p_W0h, p_W0l, b_e0, nullptr, p_h0h, p_h0l, 256, 256, 256, 256);
    // 3) h1 = tanh(h0 @ W_e1 + b)
    enc_mma<4,1,0,1><<<dim3(1, 64), 256, 163840>>>(
        p_h0h, p_h0l, p_W1h, p_W1l, b_e1, nullptr, p_h1h, p_h1l, 256, 256, 256, 128);
    // 4) E = h1 @ W_e2 + b -> fp32 to d_out + splits
    enc_mma<2,0,1,1><<<dim3(1, 64), 256, 122880>>>(
        p_h1h, p_h1l, p_W2h, p_W2l, b_e2, E_out, p_Eh, p_El, 128, 128, 128, 64);

    // 5) row norms
    n2_kernel<<<NN / 8, 256>>>(E_out, p_n2);
    // 6) new_force = dist(E) * pf (HMMA, occ 2) -> d_out
    dist_mma<<<dim3(NN / 128, NN / 128), 256, DS_SMEM>>>(p_Eh, p_El, p_n2, pf, F_out);
    // 7) Fg = new_force @ members
    fg_kernel<<<NN / 32, 256>>>(F_out, memb, p_Fg);
    // 8) d0 = relu(Fg @ W_d0 + b_d0)
    d0_partial_kernel<<<512, 256>>>(p_Fg, W_d0, p_part);
    d0_reduce_kernel<<<1, 1024>>>(p_part, b_d0, p_d0);
    // 9) d1 = relu(d0 @ W_d1 + b_d1)
    d1_kernel<<<8, 256>>>(p_d0, W_d1, b_d1, p_d1);
    // 10) out = softmax(d1 @ W_d2)
    final_kernel<<<1, 32>>>(p_d1, W_d2, O_out);
}

// round 14
// speedup vs baseline: 2.4595x; 1.0642x over previous
#include <cuda_runtime.h>
#include <cuda_bf16.h>
#include <math.h>
#include <stdint.h>

#define NN   8192
#define KC   8

// ---------------- scratch (device globals; no allocation allowed) ----------
__device__ float g_n2 [NN];
__device__ float g_Fg [NN * KC];
__device__ float g_part[512 * 1024];
__device__ float g_d0 [1024];
__device__ float g_d1 [256];
// bf16 hi/lo splits
__device__ __nv_bfloat16 g_Xth[256 * NN];   // X^T hi  [256, 8192]
__device__ __nv_bfloat16 g_Xtl[256 * NN];   // X^T lo
__device__ __nv_bfloat16 g_ih [NN * 256];   // inp splits (written by gemm1 epilogue)
__device__ __nv_bfloat16 g_il [NN * 256];
__device__ __nv_bfloat16 g_h0h[NN * 256];
__device__ __nv_bfloat16 g_h0l[NN * 256];
__device__ __nv_bfloat16 g_h1h[NN * 128];
__device__ __nv_bfloat16 g_h1l[NN * 128];
__device__ __nv_bfloat16 g_Eh [NN * 64];
__device__ __nv_bfloat16 g_El [NN * 64];
// transposed weight splits [N,K]
__device__ __nv_bfloat16 g_W0h[256 * 256], g_W0l[256 * 256];
__device__ __nv_bfloat16 g_W1h[128 * 256], g_W1l[128 * 256];
__device__ __nv_bfloat16 g_W2h[64 * 128],  g_W2l[64 * 128];

// ================= PTX helpers (baseline PTX only) ==========================
__device__ __forceinline__ uint32_t smem_to_u32(const void* p) {
    uint32_t a;
    asm("{ .reg .u64 t; cvta.to.shared.u64 t, %1; cvt.u32.u64 %0, t; }"
        : "=r"(a) : "l"(p));
    return a;
}
__device__ __forceinline__ void cpasync16(uint32_t dst, const void* src) {
    asm volatile("cp.async.cg.shared.global [%0], [%1], 16;" :: "r"(dst), "l"(src));
}
#define CPASYNC_COMMIT()    asm volatile("cp.async.commit_group;" ::: "memory")
#define CPASYNC_WAIT(n)     asm volatile("cp.async.wait_group %0;" :: "n"(n) : "memory")

__device__ __forceinline__ void ldsm_x4(uint32_t* r, uint32_t addr) {
    asm volatile("ldmatrix.sync.aligned.m8n8.x4.shared.b16 {%0,%1,%2,%3}, [%4];"
                 : "=r"(r[0]), "=r"(r[1]), "=r"(r[2]), "=r"(r[3]) : "r"(addr));
}
__device__ __forceinline__ void ldsm_x2(uint32_t* r, uint32_t addr) {
    asm volatile("ldmatrix.sync.aligned.m8n8.x2.shared.b16 {%0,%1}, [%2];"
                 : "=r"(r[0]), "=r"(r[1]) : "r"(addr));
}
__device__ __forceinline__ void mma16816(float* c, const uint32_t* a, const uint32_t* b) {
    asm volatile("mma.sync.aligned.m16n8k16.row.col.f32.bf16.bf16.f32 "
                 "{%0,%1,%2,%3}, {%4,%5,%6,%7}, {%8,%9}, {%0,%1,%2,%3};"
                 : "+f"(c[0]), "+f"(c[1]), "+f"(c[2]), "+f"(c[3])
                 : "r"(a[0]), "r"(a[1]), "r"(a[2]), "r"(a[3]), "r"(b[0]), "r"(b[1]));
}

// ================= split pre-pass kernels ===================================
// generic transpose-split: in [R,Cc] fp32 -> out [Cc,R] bf16 h/l
__global__ void tsplit_kernel(const float* __restrict__ in,
                              __nv_bfloat16* __restrict__ oh,
                              __nv_bfloat16* __restrict__ ol,
                              int R, int Cc)
{
    __shared__ float t[32][33];
    int bx = blockIdx.x * 32;
    int by = blockIdx.y * 32;
    for (int i = threadIdx.y; i < 32; i += 8)
        t[i][threadIdx.x] = in[(long)(by + i) * Cc + bx + threadIdx.x];
    __syncthreads();
    for (int i = threadIdx.y; i < 32; i += 8) {
        float v = t[threadIdx.x][i];
        __nv_bfloat16 h = __float2bfloat16(v);
        __nv_bfloat16 l = __float2bfloat16(v - __bfloat162float(h));
        long o = (long)(bx + i) * R + by + threadIdx.x;
        oh[o] = h; ol[o] = l;
    }
}

// ================= GEMM1 (HMMA): ih/il = split(F_ @ X), bf16x3 ==============
// A = F_ fp32 loaded directly; in-kernel hi/lo conversion (fsplit fused).
// BM=64, BN=128 tile, BK=32, 3-stage cp.async pipeline, 2 CTAs/SM.
// 8 warps as 2m x 4n; warp tile 32x32 (mt=2, nt=4).
#define G3_AFS    144                       // fp32 A row stride (128B + 16 pad)
#define G3_AFB    (64 * G3_AFS)             // 9216 fp32 A buffer
#define G3_BB     (128 * 80)                // 10240 per B operand
#define G3_STAGE  (G3_AFB + 2 * G3_BB)      // 29696
#define G3_AHL    (64 * 80)                 // 5120 per converted-A buffer
#define G3_SMEM   (3 * G3_STAGE + 4 * G3_AHL)  // 109568 -> 2 CTAs/SM

__global__ void __launch_bounds__(256, 2) gemm1_mma(
    const float* __restrict__ A_,
    const __nv_bfloat16* __restrict__ Bh_, const __nv_bfloat16* __restrict__ Bl_,
    __nv_bfloat16* __restrict__ Ch, __nv_bfloat16* __restrict__ Cl)
{
    extern __shared__ char smem[];
    const uint32_t sb = smem_to_u32(smem);
    const uint32_t ahl0 = sb + 3 * G3_STAGE;
    const int tid = threadIdx.x, lane = tid & 31, wid = tid >> 5;
    const int wm = wid >> 2, wn = wid & 3;
    const int mg0 = blockIdx.y * 64, ng0 = blockIdx.x * 128;

    const uint32_t aRow = wm * 32 + (lane & 7) + ((lane >> 3) & 1) * 8; // + mt*16
    const uint32_t aCol = (lane >> 4) * 16;                             // + ks*32
    const uint32_t bRow = wn * 32 + (lane & 7);                         // + nt*8
    const uint32_t bCol = ((lane >> 3) & 1) * 16;                       // + ks*32

    float acc[2][4][4];
#pragma unroll
    for (int mt = 0; mt < 2; mt++)
#pragma unroll
        for (int nt = 0; nt < 4; nt++)
#pragma unroll
            for (int q = 0; q < 4; q++) acc[mt][nt][q] = 0.f;

    auto load_stage = [&](int s) {
        uint32_t base = sb + (s % 3) * G3_STAGE;
        long k0 = (long)s * 32;
        // A fp32: 64 rows x 128B = 512 chunks of 16B
#pragma unroll
        for (int h = 0; h < 2; h++) {
            int c = tid + h * 256;
            int row = c >> 3, seg = c & 7;
            cpasync16(base + row * G3_AFS + seg * 16,
                      A_ + (long)(mg0 + row) * NN + k0 + seg * 4);
        }
        // B bf16 h/l: 128 rows x 64B = 512 chunks each
#pragma unroll
        for (int h = 0; h < 2; h++) {
            int c = tid + h * 256;
            int row = c >> 2, seg = c & 3;
            uint32_t d = base + G3_AFB + row * 80 + seg * 16;
            long gb = (long)(ng0 + row) * NN + k0 + seg * 8;
            cpasync16(d,         Bh_ + gb);
            cpasync16(d + G3_BB, Bl_ + gb);
        }
        CPASYNC_COMMIT();
    };

    load_stage(0); load_stage(1);

    const int nStages = NN / 32;
    for (int it = 0; it < nStages; it++) {
        CPASYNC_WAIT(1);
        __syncthreads();
        if (it + 2 < nStages) load_stage(it + 2);
        else CPASYNC_COMMIT();

        // convert fp32 A stage (it%3) -> bf16 hi/lo buffers (it&1)
        {
            const char* afb = smem + (it % 3) * G3_STAGE;
            char* ah = smem + 3 * G3_STAGE + (it & 1) * 2 * G3_AHL;
            char* al = ah + G3_AHL;
#pragma unroll
            for (int h = 0; h < 2; h++) {
                int c = tid + h * 256;
                int row = c >> 3, seg = c & 7;
                float4 v = *(const float4*)(afb + row * G3_AFS + seg * 16);
                __nv_bfloat162 h01 = __floats2bfloat162_rn(v.x, v.y);
                __nv_bfloat162 h23 = __floats2bfloat162_rn(v.z, v.w);
                float2 f01 = __bfloat1622float2(h01);
                float2 f23 = __bfloat1622float2(h23);
                __nv_bfloat162 l01 = __floats2bfloat162_rn(v.x - f01.x, v.y - f01.y);
                __nv_bfloat162 l23 = __floats2bfloat162_rn(v.z - f23.x, v.w - f23.y);
                uint2 ho, lo;
                ho.x = *(uint32_t*)&h01; ho.y = *(uint32_t*)&h23;
                lo.x = *(uint32_t*)&l01; lo.y = *(uint32_t*)&l23;
                *(uint2*)(ah + row * 80 + seg * 8) = ho;
                *(uint2*)(al + row * 80 + seg * 8) = lo;
            }
        }
        __syncthreads();

        const uint32_t base = sb + (it % 3) * G3_STAGE;
        const uint32_t ahb  = ahl0 + (it & 1) * 2 * G3_AHL;
#pragma unroll
        for (int ks = 0; ks < 2; ks++) {
            uint32_t bh[4][2], bl[4][2];
#pragma unroll
            for (int nt = 0; nt < 4; nt++) {
                uint32_t bo = base + G3_AFB + (bRow + nt * 8) * 80 + ks * 32 + bCol;
                ldsm_x2(bh[nt], bo);
                ldsm_x2(bl[nt], bo + G3_BB);
            }
#pragma unroll
            for (int mt = 0; mt < 2; mt++) {
                uint32_t ah[4], al[4];
                uint32_t ao = ahb + (aRow + mt * 16) * 80 + ks * 32 + aCol;
                ldsm_x4(ah, ao);
                ldsm_x4(al, ao + G3_AHL);
#pragma unroll
                for (int nt = 0; nt < 4; nt++) {
                    mma16816(acc[mt][nt], ah, bh[nt]);
                    mma16816(acc[mt][nt], ah, bl[nt]);
                    mma16816(acc[mt][nt], al, bh[nt]);
                }
            }
        }
    }

    // epilogue: hi/lo-split bf16 write
    const int r0 = mg0 + wm * 32 + (lane >> 2);
    const int c0 = ng0 + wn * 32 + (lane & 3) * 2;
#pragma unroll
    for (int mt = 0; mt < 2; mt++) {
#pragma unroll
        for (int nt = 0; nt < 4; nt++) {
            long r = r0 + mt * 16;
            int  col = c0 + nt * 8;
            float* v = acc[mt][nt];
            __nv_bfloat162 h0 = __floats2bfloat162_rn(v[0], v[1]);
            __nv_bfloat162 h1 = __floats2bfloat162_rn(v[2], v[3]);
            float2 f0 = __bfloat1622float2(h0), f1 = __bfloat1622float2(h1);
            __nv_bfloat162 l0 = __floats2bfloat162_rn(v[0] - f0.x, v[1] - f0.y);
            __nv_bfloat162 l1 = __floats2bfloat162_rn(v[2] - f1.x, v[3] - f1.y);
            *(__nv_bfloat162*)&Ch[r * 256 + col]       = h0;
            *(__nv_bfloat162*)&Ch[(r + 8) * 256 + col] = h1;
            *(__nv_bfloat162*)&Cl[r * 256 + col]       = l0;
            *(__nv_bfloat162*)&Cl[(r + 8) * 256 + col] = l1;
        }
    }
}

// ================= encoder GEMM (HMMA, bf16x3, fused act + split epilogue) ==
template<int NT, int ACT, int WRITE_F, int WRITE_HL>
__global__ void __launch_bounds__(256, 1) enc_mma(
    const __nv_bfloat16* __restrict__ Ah_, const __nv_bfloat16* __restrict__ Al_,
    const __nv_bfloat16* __restrict__ Bh_, const __nv_bfloat16* __restrict__ Bl_,
    const float* __restrict__ bias,
    float* __restrict__ Cf, __nv_bfloat16* __restrict__ Ch, __nv_bfloat16* __restrict__ Cl,
    int Ksz, int lda, int ldb, int ldc)
{
    constexpr int BN     = 32 * NT;
    constexpr int EB_A   = 128 * 80;
    constexpr int EB_B   = BN * 80;
    constexpr int ESTAGE = 2 * EB_A + 2 * EB_B;
    constexpr int B_IT   = (BN * 4) / 256;

    extern __shared__ char smem[];
    const uint32_t sb = smem_to_u32(smem);
    const int tid = threadIdx.x, lane = tid & 31, wid = tid >> 5;
    const int wm = wid >> 2, wn = wid & 3;
    const int mg0 = blockIdx.y * 128, ng0 = blockIdx.x * BN;

    const uint32_t aRow = wm * 64 + (lane & 7) + ((lane >> 3) & 1) * 8;
    const uint32_t aCol = (lane >> 4) * 16;
    const uint32_t bRow = wn * (8 * NT) + (lane & 7);
    const uint32_t bCol = ((lane >> 3) & 1) * 16;

    float acc[4][NT][4];
#pragma unroll
    for (int mt = 0; mt < 4; mt++)
#pragma unroll
        for (int nt = 0; nt < NT; nt++)
#pragma unroll
            for (int q = 0; q < 4; q++) acc[mt][nt][q] = 0.f;

    auto load_stage = [&](int s) {
        uint32_t base = sb + (s & 3) * ESTAGE;
        long k0 = (long)s * 32;
#pragma unroll
        for (int h = 0; h < 2; h++) {
            int c = tid + h * 256;
            int row = c >> 2, seg = c & 3;
            uint32_t d = base + row * 80 + seg * 16;
            long ga = (long)(mg0 + row) * lda + k0 + seg * 8;
            cpasync16(d,        Ah_ + ga);
            cpasync16(d + EB_A, Al_ + ga);
        }
#pragma unroll
        for (int h = 0; h < B_IT; h++) {
            int c = tid + h * 256;
            int row = c >> 2, seg = c & 3;
            uint32_t d = base + 2 * EB_A + row * 80 + seg * 16;
            long gb = (long)(ng0 + row) * ldb + k0 + seg * 8;
            cpasync16(d,        Bh_ + gb);
            cpasync16(d + EB_B, Bl_ + gb);
        }
        CPASYNC_COMMIT();
    };

    load_stage(0); load_stage(1); load_stage(2);

    const int nStages = Ksz / 32;
    for (int it = 0; it < nStages; it++) {
        CPASYNC_WAIT(2);
        __syncthreads();
        if (it + 3 < nStages) load_stage(it + 3);
        else CPASYNC_COMMIT();

        const uint32_t base = sb + (it & 3) * ESTAGE;
#pragma unroll
        for (int ks = 0; ks < 2; ks++) {
            uint32_t bh[NT][2], bl[NT][2];
#pragma unroll
            for (int nt = 0; nt < NT; nt++) {
                uint32_t bo = base + 2 * EB_A + (bRow + nt * 8) * 80 + ks * 32 + bCol;
                ldsm_x2(bh[nt], bo);
                ldsm_x2(bl[nt], bo + EB_B);
            }
#pragma unroll
            for (int mt = 0; mt < 4; mt++) {
                uint32_t ah[4], al[4];
                uint32_t ao = base + (aRow + mt * 16) * 80 + ks * 32 + aCol;
                ldsm_x4(ah, ao);
                ldsm_x4(al, ao + EB_A);
#pragma unroll
                for (int nt = 0; nt < NT; nt++) {
                    mma16816(acc[mt][nt], ah, bh[nt]);
                    mma16816(acc[mt][nt], ah, bl[nt]);
                    mma16816(acc[mt][nt], al, bh[nt]);
                }
            }
        }
    }

    const int r0 = mg0 + wm * 64 + (lane >> 2);
    const int c0 = ng0 + wn * (8 * NT) + (lane & 3) * 2;
#pragma unroll
    for (int mt = 0; mt < 4; mt++) {
#pragma unroll
        for (int nt = 0; nt < NT; nt++) {
            int col = c0 + nt * 8;
            float b0 = bias ? bias[col] : 0.f, b1 = bias ? bias[col + 1] : 0.f;
            float v[4] = { acc[mt][nt][0] + b0, acc[mt][nt][1] + b1,
                           acc[mt][nt][2] + b0, acc[mt][nt][3] + b1 };
            if (ACT == 1) {
#pragma unroll
                for (int q = 0; q < 4; q++) v[q] = tanhf(v[q]);
            }
            long r = r0 + mt * 16;
            if (WRITE_F) {
                *(float2*)&Cf[r * ldc + col]       = make_float2(v[0], v[1]);
                *(float2*)&Cf[(r + 8) * ldc + col] = make_float2(v[2], v[3]);
            }
            if (WRITE_HL) {
                __nv_bfloat162 h0 = __floats2bfloat162_rn(v[0], v[1]);
                __nv_bfloat162 h1 = __floats2bfloat162_rn(v[2], v[3]);
                float2 f0 = __bfloat1622float2(h0), f1 = __bfloat1622float2(h1);
                __nv_bfloat162 l0 = __floats2bfloat162_rn(v[0] - f0.x, v[1] - f0.y);
                __nv_bfloat162 l1 = __floats2bfloat162_rn(v[2] - f1.x, v[3] - f1.y);
                *(__nv_bfloat162*)&Ch[r * ldc + col]       = h0;
                *(__nv_bfloat162*)&Ch[(r + 8) * ldc + col] = h1;
                *(__nv_bfloat162*)&Cl[r * ldc + col]       = l0;
                *(__nv_bfloat162*)&Cl[(r + 8) * ldc + col] = l1;
            }
        }
    }
}

// ================= dist (HMMA): force = sqrt(n2i+n2j-2*E@E^T)+ * pf =========
#define DS_SA    144
#define DS_BUF   (128 * DS_SA)
#define DS_SMEM  (4 * DS_BUF)        // 73728 B -> 2 CTAs/SM

__global__ void __launch_bounds__(256, 2) dist_mma(
    const __nv_bfloat16* __restrict__ Eh, const __nv_bfloat16* __restrict__ El,
    const float* __restrict__ n2, const float* __restrict__ pf,
    float* __restrict__ Fo)
{
    extern __shared__ char smem[];
    const uint32_t sb = smem_to_u32(smem);
    const int tid = threadIdx.x, lane = tid & 31, wid = tid >> 5;
    const int wm = wid >> 2, wn = wid & 3;
    const int i0 = blockIdx.y * 128, j0 = blockIdx.x * 128;

#pragma unroll
    for (int h = 0; h < 4; h++) {
        int c = tid + h * 256;
        int row = c >> 3, seg = c & 7;
        uint32_t d = sb + row * DS_SA + seg * 16;
        long gi = (long)(i0 + row) * 64 + seg * 8;
        long gj = (long)(j0 + row) * 64 + seg * 8;
        cpasync16(d,              Eh + gi);
        cpasync16(d + DS_BUF,     El + gi);
        cpasync16(d + 2 * DS_BUF, Eh + gj);
        cpasync16(d + 3 * DS_BUF, El + gj);
    }
    CPASYNC_COMMIT();
    CPASYNC_WAIT(0);
    __syncthreads();

    const uint32_t aRow = wm * 64 + (lane & 7) + ((lane >> 3) & 1) * 8;
    const uint32_t aCol = (lane >> 4) * 16;
    const uint32_t bRow = wn * 32 + (lane & 7);
    const uint32_t bCol = ((lane >> 3) & 1) * 16;

    float acc[4][4][4];
#pragma unroll
    for (int mt = 0; mt < 4; mt++)
#pragma unroll
        for (int nt = 0; nt < 4; nt++)
#pragma unroll
            for (int q = 0; q < 4; q++) acc[mt][nt][q] = 0.f;

#pragma unroll
    for (int ks = 0; ks < 4; ks++) {
        uint32_t bh[4][2], bl[4][2];
#pragma unroll
        for (int nt = 0; nt < 4; nt++) {
            uint32_t bo = sb + 2 * DS_BUF + (bRow + nt * 8) * DS_SA + ks * 32 + bCol;
            ldsm_x2(bh[nt], bo);
            ldsm_x2(bl[nt], bo + DS_BUF);
        }
#pragma unroll
        for (int mt = 0; mt < 4; mt++) {
            uint32_t ah[4], al[4];
            uint32_t ao = sb + (aRow + mt * 16) * DS_SA + ks * 32 + aCol;
            ldsm_x4(ah, ao);
            ldsm_x4(al, ao + DS_BUF);
#pragma unroll
            for (int nt = 0; nt < 4; nt++) {
                mma16816(acc[mt][nt], ah, bh[nt]);
                mma16816(acc[mt][nt], ah, bl[nt]);
                mma16816(acc[mt][nt], al, bh[nt]);
            }
        }
    }

    const int ri = i0 + wm * 64 + (lane >> 2);
    const int cj = j0 + wn * 32 + (lane & 3) * 2;
#pragma unroll
    for (int mt = 0; mt < 4; mt++) {
        int ia = ri + mt * 16;
        float n2a = n2[ia], n2b = n2[ia + 8];
#pragma unroll
        for (int nt = 0; nt < 4; nt++) {
            int j = cj + nt * 8;
            float nj0 = n2[j], nj1 = n2[j + 1];
            float2 p0 = *(const float2*)&pf[(long)ia * NN + j];
            float2 p1 = *(const float2*)&pf[(long)(ia + 8) * NN + j];
            float* a = acc[mt][nt];
            float s00 = n2a + nj0 - 2.f * a[0];
            float s01 = n2a + nj1 - 2.f * a[1];
            float s10 = n2b + nj0 - 2.f * a[2];
            float s11 = n2b + nj1 - 2.f * a[3];
            float d00 = (s00 > 0.f) ? sqrtf(s00) : 0.f;
            float d01 = (s01 > 0.f) ? sqrtf(s01) : 0.f;
            float d10 = (s10 > 0.f) ? sqrtf(s10) : 0.f;
            float d11 = (s11 > 0.f) ? sqrtf(s11) : 0.f;
            *(float2*)&Fo[(long)ia * NN + j]       = make_float2(d00 * p0.x, d01 * p0.y);
            *(float2*)&Fo[(long)(ia + 8) * NN + j] = make_float2(d10 * p1.x, d11 * p1.y);
        }
    }
}

// ---------------- row-wise squared norms of E [NN,64] -----------------------
__global__ void n2_kernel(const float* __restrict__ E, float* __restrict__ n2)
{
    int row  = blockIdx.x * 8 + threadIdx.x / 32;
    int lane = threadIdx.x % 32;
    const float* e = E + (long)row * 64;
    float a = e[lane], b = e[lane + 32];
    float v = a * a + b * b;
#pragma unroll
    for (int off = 16; off; off >>= 1)
        v += __shfl_down_sync(0xffffffffu, v, off);
    if (lane == 0) n2[row] = v;
}

// ---------------- Fg = Fo @ members : 256 blocks x 32 rows ------------------
__global__ void fg_kernel(const float* __restrict__ Fo,
                          const float* __restrict__ members,
                          float* __restrict__ Fg)
{
    const int lane = threadIdx.x & 31, wid = threadIdx.x >> 5;
    const int r0 = blockIdx.x * 32 + wid * 4;

    float acc[4][8];
#pragma unroll
    for (int rr = 0; rr < 4; rr++)
#pragma unroll
        for (int k = 0; k < 8; k++) acc[rr][k] = 0.f;

    for (int j = lane * 4; j < NN; j += 128) {
        float4 m[4][2];
#pragma unroll
        for (int jj = 0; jj < 4; jj++) {
            m[jj][0] = *(const float4*)&members[(long)(j + jj) * 8];
            m[jj][1] = *(const float4*)&members[(long)(j + jj) * 8 + 4];
        }
#pragma unroll
        for (int rr = 0; rr < 4; rr++) {
            float4 f = *(const float4*)&Fo[(long)(r0 + rr) * NN + j];
            float fv[4] = { f.x, f.y, f.z, f.w };
#pragma unroll
            for (int jj = 0; jj < 4; jj++) {
                acc[rr][0] = fmaf(fv[jj], m[jj][0].x, acc[rr][0]);
                acc[rr][1] = fmaf(fv[jj], m[jj][0].y, acc[rr][1]);
                acc[rr][2] = fmaf(fv[jj], m[jj][0].z, acc[rr][2]);
                acc[rr][3] = fmaf(fv[jj], m[jj][0].w, acc[rr][3]);
                acc[rr][4] = fmaf(fv[jj], m[jj][1].x, acc[rr][4]);
                acc[rr][5] = fmaf(fv[jj], m[jj][1].y, acc[rr][5]);
                acc[rr][6] = fmaf(fv[jj], m[jj][1].z, acc[rr][6]);
                acc[rr][7] = fmaf(fv[jj], m[jj][1].w, acc[rr][7]);
            }
        }
    }
#pragma unroll
    for (int rr = 0; rr < 4; rr++) {
#pragma unroll
        for (int k = 0; k < 8; k++) {
            float v = acc[rr][k];
#pragma unroll
            for (int off = 16; off; off >>= 1)
                v += __shfl_down_sync(0xffffffffu, v, off);
            if (lane == 0) Fg[(long)(r0 + rr) * 8 + k] = v;
        }
    }
}

// ---------------- d0 GEMV split-K: 512 chunks of 128 rows -------------------
__global__ void d0_partial_kernel(const float* __restrict__ Fg,
                                  const float* __restrict__ W,
                                  float* __restrict__ part)
{
    __shared__ float sF[128];
    const int c = blockIdx.x;
    const int t = threadIdx.x;
    if (t < 128) sF[t] = Fg[c * 128 + t];
    __syncthreads();

    float4 acc = make_float4(0.f, 0.f, 0.f, 0.f);
    const float4* Wv = (const float4*)W + (long)(c * 128) * 256 + t;
#pragma unroll 8
    for (int r = 0; r < 128; r++) {
        float f = sF[r];
        float4 w = Wv[(long)r * 256];
        acc.x = fmaf(f, w.x, acc.x);
        acc.y = fmaf(f, w.y, acc.y);
        acc.z = fmaf(f, w.z, acc.z);
        acc.w = fmaf(f, w.w, acc.w);
    }
    ((float4*)part)[c * 256 + t] = acc;
}

__global__ void d0_reduce_kernel(const float* __restrict__ part,
                                 const float* __restrict__ bias,
                                 float* __restrict__ d0)
{
    const int col = threadIdx.x;
    float v = 0.f;
    for (int c = 0; c < 512; c++) v += part[c * 1024 + col];
    v += bias[col];
    d0[col] = fmaxf(v, 0.f);
}

// ---------------- d1 = relu(d0 @ W_d1 + b_d1) --------------------------------
__global__ void d1_kernel(const float* __restrict__ d0,
                          const float* __restrict__ W,
                          const float* __restrict__ bias,
                          float* __restrict__ d1)
{
    const int col = blockIdx.x * 32 + threadIdx.x % 32;
    const int rg  = threadIdx.x / 32;
    float acc = 0.f;
    for (int r = rg; r < 1024; r += 8)
        acc = fmaf(d0[r], W[r * 256 + col], acc);
    __shared__ float s[8][32];
    s[rg][threadIdx.x % 32] = acc;
    __syncthreads();
    if (rg == 0) {
        float v = acc;
#pragma unroll
        for (int g = 1; g < 8; g++) v += s[g][threadIdx.x];
        v += bias[col];
        d1[col] = fmaxf(v, 0.f);
    }
}

// ---------------- final: softmax(d1 @ W_d2) ----------------------------------
__global__ void final_kernel(const float* __restrict__ d1,
                             const float* __restrict__ W,
                             float* __restrict__ out)
{
    const int lane = threadIdx.x;
    float acc[8];
#pragma unroll
    for (int k = 0; k < 8; k++) acc[k] = 0.f;
    for (int r = lane; r < 256; r += 32) {
        float v = d1[r];
        const float* w = W + r * 8;
#pragma unroll
        for (int k = 0; k < 8; k++) acc[k] = fmaf(v, w[k], acc[k]);
    }
#pragma unroll
    for (int k = 0; k < 8; k++)
#pragma unroll
        for (int off = 16; off; off >>= 1)
            acc[k] += __shfl_down_sync(0xffffffffu, acc[k], off);
    if (lane == 0) {
        float mx = acc[0];
#pragma unroll
        for (int k = 1; k < 8; k++) mx = fmaxf(mx, acc[k]);
        float e[8], s = 0.f;
#pragma unroll
        for (int k = 0; k < 8; k++) { e[k] = expf(acc[k] - mx); s += e[k]; }
#pragma unroll
        for (int k = 0; k < 8; k++) out[k] = e[k] / s;
    }
}

// ---------------- launch ----------------------------------------------------
extern "C" void kernel_launch(void* const* d_in, const int* in_sizes, int n_in,
                              void* d_out, int out_size)
{
    const float* F_    = (const float*)d_in[0];
    const float* X     = (const float*)d_in[1];
    const float* W_e0  = (const float*)d_in[2];
    const float* b_e0  = (const float*)d_in[3];
    const float* W_e1  = (const float*)d_in[4];
    const float* b_e1  = (const float*)d_in[5];
    const float* W_e2  = (const float*)d_in[6];
    const float* b_e2  = (const float*)d_in[7];
    const float* W_d0  = (const float*)d_in[8];
    const float* b_d0  = (const float*)d_in[9];
    const float* W_d1  = (const float*)d_in[10];
    const float* b_d1  = (const float*)d_in[11];
    const float* W_d2  = (const float*)d_in[12];
    const float* pf    = (const float*)d_in[13];
    const float* memb  = (const float*)d_in[14];

    float* out    = (float*)d_out;
    float* E_out  = out;
    float* F_out  = out + (long)NN * 64;
    float* O_out  = out + (long)NN * 64 + (long)NN * NN;

    float *p_n2, *p_Fg, *p_part, *p_d0, *p_d1;
    __nv_bfloat16 *p_Xth, *p_Xtl, *p_Eh, *p_El;
    __nv_bfloat16 *p_ih, *p_il, *p_h0h, *p_h0l, *p_h1h, *p_h1l;
    __nv_bfloat16 *p_W0h, *p_W0l, *p_W1h, *p_W1l, *p_W2h, *p_W2l;
    cudaGetSymbolAddress((void**)&p_n2,   g_n2);
    cudaGetSymbolAddress((void**)&p_Fg,   g_Fg);
    cudaGetSymbolAddress((void**)&p_part, g_part);
    cudaGetSymbolAddress((void**)&p_d0,   g_d0);
    cudaGetSymbolAddress((void**)&p_d1,   g_d1);
    cudaGetSymbolAddress((void**)&p_Xth,  g_Xth);
    cudaGetSymbolAddress((void**)&p_Xtl,  g_Xtl);
    cudaGetSymbolAddress((void**)&p_Eh,   g_Eh);
    cudaGetSymbolAddress((void**)&p_El,   g_El);
    cudaGetSymbolAddress((void**)&p_ih,   g_ih);
    cudaGetSymbolAddress((void**)&p_il,   g_il);
    cudaGetSymbolAddress((void**)&p_h0h,  g_h0h);
    cudaGetSymbolAddress((void**)&p_h0l,  g_h0l);
    cudaGetSymbolAddress((void**)&p_h1h,  g_h1h);
    cudaGetSymbolAddress((void**)&p_h1l,  g_h1l);
    cudaGetSymbolAddress((void**)&p_W0h,  g_W0h);
    cudaGetSymbolAddress((void**)&p_W0l,  g_W0l);
    cudaGetSymbolAddress((void**)&p_W1h,  g_W1h);
    cudaGetSymbolAddress((void**)&p_W1l,  g_W1l);
    cudaGetSymbolAddress((void**)&p_W2h,  g_W2h);
    cudaGetSymbolAddress((void**)&p_W2l,  g_W2l);

    cudaFuncSetAttribute(gemm1_mma, cudaFuncAttributeMaxDynamicSharedMemorySize, G3_SMEM);
    cudaFuncSetAttribute(dist_mma,  cudaFuncAttributeMaxDynamicSharedMemorySize, DS_SMEM);
    cudaFuncSetAttribute(enc_mma<4,1,0,1>, cudaFuncAttributeMaxDynamicSharedMemorySize, 163840);
    cudaFuncSetAttribute(enc_mma<2,0,1,1>, cudaFuncAttributeMaxDynamicSharedMemorySize, 122880);

    // launch index 3 = gemm1_mma (ncu captures the 4th launch)
    tsplit_kernel<<<dim3(8, 256), dim3(32, 8)>>>(X, p_Xth, p_Xtl, NN, 256);      // 0
    tsplit_kernel<<<dim3(8, 8),  dim3(32, 8)>>>(W_e0, p_W0h, p_W0l, 256, 256);   // 1
    tsplit_kernel<<<dim3(4, 8),  dim3(32, 8)>>>(W_e1, p_W1h, p_W1l, 256, 128);   // 2
    // 1) inp = F_ @ X (HMMA, in-kernel F split, occ 2), split epilogue -> ih/il
    gemm1_mma<<<dim3(2, 128), 256, G3_SMEM>>>(F_, p_Xth, p_Xtl, p_ih, p_il);     // 3
    tsplit_kernel<<<dim3(2, 4),  dim3(32, 8)>>>(W_e2, p_W2h, p_W2l, 128, 64);    // 4

    // 2) h0 = tanh(inp @ W_e0 + b)
    enc_mma<4,1,0,1><<<dim3(2, 64), 256, 163840>>>(
        p_ih, p_il, p_W0h, p_W0l, b_e0, nullptr, p_h0h, p_h0l, 256, 256, 256, 256);
    // 3) h1 = tanh(h0 @ W_e1 + b)
    enc_mma<4,1,0,1><<<dim3(1, 64), 256, 163840>>>(
        p_h0h, p_h0l, p_W1h, p_W1l, b_e1, nullptr, p_h1h, p_h1l, 256, 256, 256, 128);
    // 4) E = h1 @ W_e2 + b -> fp32 to d_out + splits
    enc_mma<2,0,1,1><<<dim3(1, 64), 256, 122880>>>(
        p_h1h, p_h1l, p_W2h, p_W2l, b_e2, E_out, p_Eh, p_El, 128, 128, 128, 64);

    // 5) row norms
    n2_kernel<<<NN / 8, 256>>>(E_out, p_n2);
    // 6) new_force = dist(E) * pf (HMMA, occ 2) -> d_out
    dist_mma<<<dim3(NN / 128, NN / 128), 256, DS_SMEM>>>(p_Eh, p_El, p_n2, pf, F_out);
    // 7) Fg = new_force @ members
    fg_kernel<<<NN / 32, 256>>>(F_out, memb, p_Fg);
    // 8) d0 = relu(Fg @ W_d0 + b_d0)
    d0_partial_kernel<<<512, 256>>>(p_Fg, W_d0, p_part);
    d0_reduce_kernel<<<1, 1024>>>(p_part, b_d0, p_d0);
    // 9) d1 = relu(d0 @ W_d1 + b_d1)
    d1_kernel<<<8, 256>>>(p_d0, W_d1, b_d1, p_d1);
    // 10) out = softmax(d1 @ W_d2)
    final_kernel<<<1, 32>>>(p_d1, W_d2, O_out);
}

// round 15
// speedup vs baseline: 2.4967x; 1.0151x over previous
#include <cuda_runtime.h>
#include <cuda_bf16.h>
#include <math.h>
#include <stdint.h>

#define NN   8192
#define KC   8

// ---------------- scratch (device globals; no allocation allowed) ----------
__device__ float g_n2 [NN];
__device__ float g_Fg [NN * KC];
__device__ float g_part[512 * 1024];
__device__ float g_d0 [1024];
__device__ float g_d1 [256];
// bf16 hi/lo splits
__device__ __nv_bfloat16 g_Xth[256 * NN];
__device__ __nv_bfloat16 g_Xtl[256 * NN];
__device__ __nv_bfloat16 g_ih [NN * 256];
__device__ __nv_bfloat16 g_il [NN * 256];
__device__ __nv_bfloat16 g_h0h[NN * 256];
__device__ __nv_bfloat16 g_h0l[NN * 256];
__device__ __nv_bfloat16 g_h1h[NN * 128];
__device__ __nv_bfloat16 g_h1l[NN * 128];
__device__ __nv_bfloat16 g_Eh [NN * 64];
__device__ __nv_bfloat16 g_El [NN * 64];
// transposed weight splits [N,K]
__device__ __nv_bfloat16 g_W0h[256 * 256], g_W0l[256 * 256];
__device__ __nv_bfloat16 g_W1h[128 * 256], g_W1l[128 * 256];
__device__ __nv_bfloat16 g_W2h[64 * 128],  g_W2l[64 * 128];

// ================= PTX helpers (baseline PTX only) ==========================
__device__ __forceinline__ uint32_t smem_to_u32(const void* p) {
    uint32_t a;
    asm("{ .reg .u64 t; cvta.to.shared.u64 t, %1; cvt.u32.u64 %0, t; }"
        : "=r"(a) : "l"(p));
    return a;
}
__device__ __forceinline__ void cpasync16(uint32_t dst, const void* src) {
    asm volatile("cp.async.cg.shared.global [%0], [%1], 16;" :: "r"(dst), "l"(src));
}
#define CPASYNC_COMMIT()    asm volatile("cp.async.commit_group;" ::: "memory")
#define CPASYNC_WAIT(n)     asm volatile("cp.async.wait_group %0;" :: "n"(n) : "memory")

__device__ __forceinline__ void ldsm_x4(uint32_t* r, uint32_t addr) {
    asm volatile("ldmatrix.sync.aligned.m8n8.x4.shared.b16 {%0,%1,%2,%3}, [%4];"
                 : "=r"(r[0]), "=r"(r[1]), "=r"(r[2]), "=r"(r[3]) : "r"(addr));
}
__device__ __forceinline__ void mma16816(float* c, const uint32_t* a, const uint32_t* b) {
    asm volatile("mma.sync.aligned.m16n8k16.row.col.f32.bf16.bf16.f32 "
                 "{%0,%1,%2,%3}, {%4,%5,%6,%7}, {%8,%9}, {%0,%1,%2,%3};"
                 : "+f"(c[0]), "+f"(c[1]), "+f"(c[2]), "+f"(c[3])
                 : "r"(a[0]), "r"(a[1]), "r"(a[2]), "r"(a[3]), "r"(b[0]), "r"(b[1]));
}

// ================= split pre-pass kernels ===================================
__global__ void tsplit_kernel(const float* __restrict__ in,
                              __nv_bfloat16* __restrict__ oh,
                              __nv_bfloat16* __restrict__ ol,
                              int R, int Cc)
{
    __shared__ float t[32][33];
    int bx = blockIdx.x * 32;
    int by = blockIdx.y * 32;
    for (int i = threadIdx.y; i < 32; i += 8)
        t[i][threadIdx.x] = in[(long)(by + i) * Cc + bx + threadIdx.x];
    __syncthreads();
    for (int i = threadIdx.y; i < 32; i += 8) {
        float v = t[threadIdx.x][i];
        __nv_bfloat16 h = __float2bfloat16(v);
        __nv_bfloat16 l = __float2bfloat16(v - __bfloat162float(h));
        long o = (long)(bx + i) * R + by + threadIdx.x;
        oh[o] = h; ol[o] = l;
    }
}

// ================= GEMM1 (HMMA): ih/il = split(F_ @ X), bf16x3 ==============
// BM=64, BN=128, BK=32, 3-stage cp.async, occ 2, fused fp32->bf16 A conversion.
#define G3_AFS    144
#define G3_AFB    (64 * G3_AFS)
#define G3_BB     (128 * 80)
#define G3_STAGE  (G3_AFB + 2 * G3_BB)
#define G3_AHL    (64 * 80)
#define G3_SMEM   (3 * G3_STAGE + 4 * G3_AHL)   // 109568

__global__ void __launch_bounds__(256, 2) gemm1_mma(
    const float* __restrict__ A_,
    const __nv_bfloat16* __restrict__ Bh_, const __nv_bfloat16* __restrict__ Bl_,
    __nv_bfloat16* __restrict__ Ch, __nv_bfloat16* __restrict__ Cl)
{
    extern __shared__ char smem[];
    const uint32_t sb = smem_to_u32(smem);
    const uint32_t ahl0 = sb + 3 * G3_STAGE;
    const int tid = threadIdx.x, lane = tid & 31, wid = tid >> 5;
    const int wm = wid >> 2, wn = wid & 3;
    const int mg0 = blockIdx.y * 64, ng0 = blockIdx.x * 128;

    const uint32_t aRow = wm * 32 + (lane & 7) + ((lane >> 3) & 1) * 8;
    const uint32_t aCol = (lane >> 4) * 16;
    // merged-x4 B addressing: lanes 16-31 take the second nt of the pair
    const uint32_t bRow2 = wn * 32 + (lane & 7) + ((lane >> 4) & 1) * 8;
    const uint32_t bCol2 = ((lane >> 3) & 1) * 16;

    float acc[2][4][4];
#pragma unroll
    for (int mt = 0; mt < 2; mt++)
#pragma unroll
        for (int nt = 0; nt < 4; nt++)
#pragma unroll
            for (int q = 0; q < 4; q++) acc[mt][nt][q] = 0.f;

    auto load_stage = [&](int s) {
        uint32_t base = sb + (s % 3) * G3_STAGE;
        long k0 = (long)s * 32;
#pragma unroll
        for (int h = 0; h < 2; h++) {
            int c = tid + h * 256;
            int row = c >> 3, seg = c & 7;
            cpasync16(base + row * G3_AFS + seg * 16,
                      A_ + (long)(mg0 + row) * NN + k0 + seg * 4);
        }
#pragma unroll
        for (int h = 0; h < 2; h++) {
            int c = tid + h * 256;
            int row = c >> 2, seg = c & 3;
            uint32_t d = base + G3_AFB + row * 80 + seg * 16;
            long gb = (long)(ng0 + row) * NN + k0 + seg * 8;
            cpasync16(d,         Bh_ + gb);
            cpasync16(d + G3_BB, Bl_ + gb);
        }
        CPASYNC_COMMIT();
    };

    load_stage(0); load_stage(1);

    const int nStages = NN / 32;
    for (int it = 0; it < nStages; it++) {
        CPASYNC_WAIT(1);
        __syncthreads();
        if (it + 2 < nStages) load_stage(it + 2);
        else CPASYNC_COMMIT();

        // convert fp32 A stage (it%3) -> bf16 hi/lo buffers (it&1), vectorized
        {
            const char* afb = smem + (it % 3) * G3_STAGE;
            char* ah = smem + 3 * G3_STAGE + (it & 1) * 2 * G3_AHL;
            char* al = ah + G3_AHL;
            int row = tid >> 2, seg = tid & 3;     // 32B fp32 -> 16B bf16 per thread
            const char* src = afb + row * G3_AFS + seg * 32;
            float4 v0 = *(const float4*)(src);
            float4 v1 = *(const float4*)(src + 16);
            __nv_bfloat162 h01 = __floats2bfloat162_rn(v0.x, v0.y);
            __nv_bfloat162 h23 = __floats2bfloat162_rn(v0.z, v0.w);
            __nv_bfloat162 h45 = __floats2bfloat162_rn(v1.x, v1.y);
            __nv_bfloat162 h67 = __floats2bfloat162_rn(v1.z, v1.w);
            float2 f01 = __bfloat1622float2(h01), f23 = __bfloat1622float2(h23);
            float2 f45 = __bfloat1622float2(h45), f67 = __bfloat1622float2(h67);
            __nv_bfloat162 l01 = __floats2bfloat162_rn(v0.x - f01.x, v0.y - f01.y);
            __nv_bfloat162 l23 = __floats2bfloat162_rn(v0.z - f23.x, v0.w - f23.y);
            __nv_bfloat162 l45 = __floats2bfloat162_rn(v1.x - f45.x, v1.y - f45.y);
            __nv_bfloat162 l67 = __floats2bfloat162_rn(v1.z - f67.x, v1.w - f67.y);
            uint4 ho, lo;
            ho.x = *(uint32_t*)&h01; ho.y = *(uint32_t*)&h23;
            ho.z = *(uint32_t*)&h45; ho.w = *(uint32_t*)&h67;
            lo.x = *(uint32_t*)&l01; lo.y = *(uint32_t*)&l23;
            lo.z = *(uint32_t*)&l45; lo.w = *(uint32_t*)&l67;
            *(uint4*)(ah + row * 80 + seg * 16) = ho;
            *(uint4*)(al + row * 80 + seg * 16) = lo;
        }
        __syncthreads();

        const uint32_t base = sb + (it % 3) * G3_STAGE;
        const uint32_t ahb  = ahl0 + (it & 1) * 2 * G3_AHL;
#pragma unroll
        for (int ks = 0; ks < 2; ks++) {
            uint32_t bh[4][2], bl[4][2];
#pragma unroll
            for (int ntp = 0; ntp < 2; ntp++) {     // x4 loads two nt at once
                uint32_t bo = base + G3_AFB + (bRow2 + ntp * 16) * 80 + ks * 32 + bCol2;
                uint32_t r[4];
                ldsm_x4(r, bo);
                bh[ntp*2][0] = r[0]; bh[ntp*2][1] = r[1];
                bh[ntp*2+1][0] = r[2]; bh[ntp*2+1][1] = r[3];
                ldsm_x4(r, bo + G3_BB);
                bl[ntp*2][0] = r[0]; bl[ntp*2][1] = r[1];
                bl[ntp*2+1][0] = r[2]; bl[ntp*2+1][1] = r[3];
            }
#pragma unroll
            for (int mt = 0; mt < 2; mt++) {
                uint32_t ah[4], al[4];
                uint32_t ao = ahb + (aRow + mt * 16) * 80 + ks * 32 + aCol;
                ldsm_x4(ah, ao);
                ldsm_x4(al, ao + G3_AHL);
#pragma unroll
                for (int nt = 0; nt < 4; nt++) {
                    mma16816(acc[mt][nt], ah, bh[nt]);
                    mma16816(acc[mt][nt], ah, bl[nt]);
                    mma16816(acc[mt][nt], al, bh[nt]);
                }
            }
        }
    }

    const int r0 = mg0 + wm * 32 + (lane >> 2);
    const int c0 = ng0 + wn * 32 + (lane & 3) * 2;
#pragma unroll
    for (int mt = 0; mt < 2; mt++) {
#pragma unroll
        for (int nt = 0; nt < 4; nt++) {
            long r = r0 + mt * 16;
            int  col = c0 + nt * 8;
            float* v = acc[mt][nt];
            __nv_bfloat162 h0 = __floats2bfloat162_rn(v[0], v[1]);
            __nv_bfloat162 h1 = __floats2bfloat162_rn(v[2], v[3]);
            float2 f0 = __bfloat1622float2(h0), f1 = __bfloat1622float2(h1);
            __nv_bfloat162 l0 = __floats2bfloat162_rn(v[0] - f0.x, v[1] - f0.y);
            __nv_bfloat162 l1 = __floats2bfloat162_rn(v[2] - f1.x, v[3] - f1.y);
            *(__nv_bfloat162*)&Ch[r * 256 + col]       = h0;
            *(__nv_bfloat162*)&Ch[(r + 8) * 256 + col] = h1;
            *(__nv_bfloat162*)&Cl[r * 256 + col]       = l0;
            *(__nv_bfloat162*)&Cl[(r + 8) * 256 + col] = l1;
        }
    }
}

// ================= encoder GEMM (HMMA, bf16x3, BM=64, occ 2) ================
template<int NT, int ACT, int WRITE_F, int WRITE_HL>
__global__ void __launch_bounds__(256, 2) enc_mma(
    const __nv_bfloat16* __restrict__ Ah_, const __nv_bfloat16* __restrict__ Al_,
    const __nv_bfloat16* __restrict__ Bh_, const __nv_bfloat16* __restrict__ Bl_,
    const float* __restrict__ bias,
    float* __restrict__ Cf, __nv_bfloat16* __restrict__ Ch, __nv_bfloat16* __restrict__ Cl,
    int Ksz, int lda, int ldb, int ldc)
{
    constexpr int BN     = 32 * NT;
    constexpr int EB_A   = 64 * 80;             // 5120
    constexpr int EB_B   = BN * 80;
    constexpr int ESTAGE = 2 * EB_A + 2 * EB_B;
    constexpr int B_IT   = (BN * 4) / 256;      // 2 or 1

    extern __shared__ char smem[];
    const uint32_t sb = smem_to_u32(smem);
    const int tid = threadIdx.x, lane = tid & 31, wid = tid >> 5;
    const int wm = wid >> 2, wn = wid & 3;
    const int mg0 = blockIdx.y * 64, ng0 = blockIdx.x * BN;

    const uint32_t aRow = wm * 32 + (lane & 7) + ((lane >> 3) & 1) * 8;
    const uint32_t aCol = (lane >> 4) * 16;
    const uint32_t bRow2 = wn * (8 * NT) + (lane & 7) + ((lane >> 4) & 1) * 8;
    const uint32_t bCol2 = ((lane >> 3) & 1) * 16;

    float acc[2][NT][4];
#pragma unroll
    for (int mt = 0; mt < 2; mt++)
#pragma unroll
        for (int nt = 0; nt < NT; nt++)
#pragma unroll
            for (int q = 0; q < 4; q++) acc[mt][nt][q] = 0.f;

    auto load_stage = [&](int s) {
        uint32_t base = sb + (s % 3) * ESTAGE;
        long k0 = (long)s * 32;
        {
            int c = tid;                     // 64 rows x 4 seg = 256 chunks
            int row = c >> 2, seg = c & 3;
            uint32_t d = base + row * 80 + seg * 16;
            long ga = (long)(mg0 + row) * lda + k0 + seg * 8;
            cpasync16(d,        Ah_ + ga);
            cpasync16(d + EB_A, Al_ + ga);
        }
#pragma unroll
        for (int h = 0; h < B_IT; h++) {
            int c = tid + h * 256;
            int row = c >> 2, seg = c & 3;
            uint32_t d = base + 2 * EB_A + row * 80 + seg * 16;
            long gb = (long)(ng0 + row) * ldb + k0 + seg * 8;
            cpasync16(d,        Bh_ + gb);
            cpasync16(d + EB_B, Bl_ + gb);
        }
        CPASYNC_COMMIT();
    };

    load_stage(0); load_stage(1);

    const int nStages = Ksz / 32;
    for (int it = 0; it < nStages; it++) {
        CPASYNC_WAIT(1);
        __syncthreads();
        if (it + 2 < nStages) load_stage(it + 2);
        else CPASYNC_COMMIT();

        const uint32_t base = sb + (it % 3) * ESTAGE;
#pragma unroll
        for (int ks = 0; ks < 2; ks++) {
            uint32_t bh[NT][2], bl[NT][2];
#pragma unroll
            for (int ntp = 0; ntp < NT / 2; ntp++) {
                uint32_t bo = base + 2 * EB_A + (bRow2 + ntp * 16) * 80 + ks * 32 + bCol2;
                uint32_t r[4];
                ldsm_x4(r, bo);
                bh[ntp*2][0] = r[0]; bh[ntp*2][1] = r[1];
                bh[ntp*2+1][0] = r[2]; bh[ntp*2+1][1] = r[3];
                ldsm_x4(r, bo + EB_B);
                bl[ntp*2][0] = r[0]; bl[ntp*2][1] = r[1];
                bl[ntp*2+1][0] = r[2]; bl[ntp*2+1][1] = r[3];
            }
#pragma unroll
            for (int mt = 0; mt < 2; mt++) {
                uint32_t ah[4], al[4];
                uint32_t ao = base + (aRow + mt * 16) * 80 + ks * 32 + aCol;
                ldsm_x4(ah, ao);
                ldsm_x4(al, ao + EB_A);
#pragma unroll
                for (int nt = 0; nt < NT; nt++) {
                    mma16816(acc[mt][nt], ah, bh[nt]);
                    mma16816(acc[mt][nt], ah, bl[nt]);
                    mma16816(acc[mt][nt], al, bh[nt]);
                }
            }
        }
        __syncthreads();
    }

    const int r0 = mg0 + wm * 32 + (lane >> 2);
    const int c0 = ng0 + wn * (8 * NT) + (lane & 3) * 2;
#pragma unroll
    for (int mt = 0; mt < 2; mt++) {
#pragma unroll
        for (int nt = 0; nt < NT; nt++) {
            int col = c0 + nt * 8;
            float b0 = bias ? bias[col] : 0.f, b1 = bias ? bias[col + 1] : 0.f;
            float v[4] = { acc[mt][nt][0] + b0, acc[mt][nt][1] + b1,
                           acc[mt][nt][2] + b0, acc[mt][nt][3] + b1 };
            if (ACT == 1) {
#pragma unroll
                for (int q = 0; q < 4; q++) v[q] = tanhf(v[q]);
            }
            long r = r0 + mt * 16;
            if (WRITE_F) {
                *(float2*)&Cf[r * ldc + col]       = make_float2(v[0], v[1]);
                *(float2*)&Cf[(r + 8) * ldc + col] = make_float2(v[2], v[3]);
            }
            if (WRITE_HL) {
                __nv_bfloat162 h0 = __floats2bfloat162_rn(v[0], v[1]);
                __nv_bfloat162 h1 = __floats2bfloat162_rn(v[2], v[3]);
                float2 f0 = __bfloat1622float2(h0), f1 = __bfloat1622float2(h1);
                __nv_bfloat162 l0 = __floats2bfloat162_rn(v[0] - f0.x, v[1] - f0.y);
                __nv_bfloat162 l1 = __floats2bfloat162_rn(v[2] - f1.x, v[3] - f1.y);
                *(__nv_bfloat162*)&Ch[r * ldc + col]       = h0;
                *(__nv_bfloat162*)&Ch[(r + 8) * ldc + col] = h1;
                *(__nv_bfloat162*)&Cl[r * ldc + col]       = l0;
                *(__nv_bfloat162*)&Cl[(r + 8) * ldc + col] = l1;
            }
        }
    }
}

// ================= dist (HMMA): force = sqrt(n2i+n2j-2*E@E^T)+ * pf =========
#define DS_SA    144
#define DS_BUF   (128 * DS_SA)
#define DS_SMEM  (4 * DS_BUF)

__global__ void __launch_bounds__(256, 2) dist_mma(
    const __nv_bfloat16* __restrict__ Eh, const __nv_bfloat16* __restrict__ El,
    const float* __restrict__ n2, const float* __restrict__ pf,
    float* __restrict__ Fo)
{
    extern __shared__ char smem[];
    const uint32_t sb = smem_to_u32(smem);
    const int tid = threadIdx.x, lane = tid & 31, wid = tid >> 5;
    const int wm = wid >> 2, wn = wid & 3;
    const int i0 = blockIdx.y * 128, j0 = blockIdx.x * 128;

#pragma unroll
    for (int h = 0; h < 4; h++) {
        int c = tid + h * 256;
        int row = c >> 3, seg = c & 7;
        uint32_t d = sb + row * DS_SA + seg * 16;
        long gi = (long)(i0 + row) * 64 + seg * 8;
        long gj = (long)(j0 + row) * 64 + seg * 8;
        cpasync16(d,              Eh + gi);
        cpasync16(d + DS_BUF,     El + gi);
        cpasync16(d + 2 * DS_BUF, Eh + gj);
        cpasync16(d + 3 * DS_BUF, El + gj);
    }
    CPASYNC_COMMIT();
    CPASYNC_WAIT(0);
    __syncthreads();

    const uint32_t aRow = wm * 64 + (lane & 7) + ((lane >> 3) & 1) * 8;
    const uint32_t aCol = (lane >> 4) * 16;
    const uint32_t bRow2 = wn * 32 + (lane & 7) + ((lane >> 4) & 1) * 8;
    const uint32_t bCol2 = ((lane >> 3) & 1) * 16;

    float acc[4][4][4];
#pragma unroll
    for (int mt = 0; mt < 4; mt++)
#pragma unroll
        for (int nt = 0; nt < 4; nt++)
#pragma unroll
            for (int q = 0; q < 4; q++) acc[mt][nt][q] = 0.f;

#pragma unroll
    for (int ks = 0; ks < 4; ks++) {
        uint32_t bh[4][2], bl[4][2];
#pragma unroll
        for (int ntp = 0; ntp < 2; ntp++) {
            uint32_t bo = sb + 2 * DS_BUF + (bRow2 + ntp * 16) * DS_SA + ks * 32 + bCol2;
            uint32_t r[4];
            ldsm_x4(r, bo);
            bh[ntp*2][0] = r[0]; bh[ntp*2][1] = r[1];
            bh[ntp*2+1][0] = r[2]; bh[ntp*2+1][1] = r[3];
            ldsm_x4(r, bo + DS_BUF);
            bl[ntp*2][0] = r[0]; bl[ntp*2][1] = r[1];
            bl[ntp*2+1][0] = r[2]; bl[ntp*2+1][1] = r[3];
        }
#pragma unroll
        for (int mt = 0; mt < 4; mt++) {
            uint32_t ah[4], al[4];
            uint32_t ao = sb + (aRow + mt * 16) * DS_SA + ks * 32 + aCol;
            ldsm_x4(ah, ao);
            ldsm_x4(al, ao + DS_BUF);
#pragma unroll
            for (int nt = 0; nt < 4; nt++) {
                mma16816(acc[mt][nt], ah, bh[nt]);
                mma16816(acc[mt][nt], ah, bl[nt]);
                mma16816(acc[mt][nt], al, bh[nt]);
            }
        }
    }

    const int ri = i0 + wm * 64 + (lane >> 2);
    const int cj = j0 + wn * 32 + (lane & 3) * 2;
#pragma unroll
    for (int mt = 0; mt < 4; mt++) {
        int ia = ri + mt * 16;
        float n2a = n2[ia], n2b = n2[ia + 8];
#pragma unroll
        for (int nt = 0; nt < 4; nt++) {
            int j = cj + nt * 8;
            float nj0 = n2[j], nj1 = n2[j + 1];
            float2 p0 = *(const float2*)&pf[(long)ia * NN + j];
            float2 p1 = *(const float2*)&pf[(long)(ia + 8) * NN + j];
            float* a = acc[mt][nt];
            float s00 = n2a + nj0 - 2.f * a[0];
            float s01 = n2a + nj1 - 2.f * a[1];
            float s10 = n2b + nj0 - 2.f * a[2];
            float s11 = n2b + nj1 - 2.f * a[3];
            float d00 = (s00 > 0.f) ? sqrtf(s00) : 0.f;
            float d01 = (s01 > 0.f) ? sqrtf(s01) : 0.f;
            float d10 = (s10 > 0.f) ? sqrtf(s10) : 0.f;
            float d11 = (s11 > 0.f) ? sqrtf(s11) : 0.f;
            *(float2*)&Fo[(long)ia * NN + j]       = make_float2(d00 * p0.x, d01 * p0.y);
            *(float2*)&Fo[(long)(ia + 8) * NN + j] = make_float2(d10 * p1.x, d11 * p1.y);
        }
    }
}

// ---------------- row-wise squared norms of E [NN,64] -----------------------
__global__ void n2_kernel(const float* __restrict__ E, float* __restrict__ n2)
{
    int row  = blockIdx.x * 8 + threadIdx.x / 32;
    int lane = threadIdx.x % 32;
    const float* e = E + (long)row * 64;
    float a = e[lane], b = e[lane + 32];
    float v = a * a + b * b;
#pragma unroll
    for (int off = 16; off; off >>= 1)
        v += __shfl_down_sync(0xffffffffu, v, off);
    if (lane == 0) n2[row] = v;
}

// ---------------- Fg = Fo @ members : 256 blocks x 32 rows ------------------
__global__ void fg_kernel(const float* __restrict__ Fo,
                          const float* __restrict__ members,
                          float* __restrict__ Fg)
{
    const int lane = threadIdx.x & 31, wid = threadIdx.x >> 5;
    const int r0 = blockIdx.x * 32 + wid * 4;

    float acc[4][8];
#pragma unroll
    for (int rr = 0; rr < 4; rr++)
#pragma unroll
        for (int k = 0; k < 8; k++) acc[rr][k] = 0.f;

    for (int j = lane * 4; j < NN; j += 128) {
        float4 m[4][2];
#pragma unroll
        for (int jj = 0; jj < 4; jj++) {
            m[jj][0] = *(const float4*)&members[(long)(j + jj) * 8];
            m[jj][1] = *(const float4*)&members[(long)(j + jj) * 8 + 4];
        }
#pragma unroll
        for (int rr = 0; rr < 4; rr++) {
            float4 f = *(const float4*)&Fo[(long)(r0 + rr) * NN + j];
            float fv[4] = { f.x, f.y, f.z, f.w };
#pragma unroll
            for (int jj = 0; jj < 4; jj++) {
                acc[rr][0] = fmaf(fv[jj], m[jj][0].x, acc[rr][0]);
                acc[rr][1] = fmaf(fv[jj], m[jj][0].y, acc[rr][1]);
                acc[rr][2] = fmaf(fv[jj], m[jj][0].z, acc[rr][2]);
                acc[rr][3] = fmaf(fv[jj], m[jj][0].w, acc[rr][3]);
                acc[rr][4] = fmaf(fv[jj], m[jj][1].x, acc[rr][4]);
                acc[rr][5] = fmaf(fv[jj], m[jj][1].y, acc[rr][5]);
                acc[rr][6] = fmaf(fv[jj], m[jj][1].z, acc[rr][6]);
                acc[rr][7] = fmaf(fv[jj], m[jj][1].w, acc[rr][7]);
            }
        }
    }
#pragma unroll
    for (int rr = 0; rr < 4; rr++) {
#pragma unroll
        for (int k = 0; k < 8; k++) {
            float v = acc[rr][k];
#pragma unroll
            for (int off = 16; off; off >>= 1)
                v += __shfl_down_sync(0xffffffffu, v, off);
            if (lane == 0) Fg[(long)(r0 + rr) * 8 + k] = v;
        }
    }
}

// ---------------- d0 GEMV split-K: 512 chunks of 128 rows -------------------
__global__ void d0_partial_kernel(const float* __restrict__ Fg,
                                  const float* __restrict__ W,
                                  float* __restrict__ part)
{
    __shared__ float sF[128];
    const int c = blockIdx.x;
    const int t = threadIdx.x;
    if (t < 128) sF[t] = Fg[c * 128 + t];
    __syncthreads();

    float4 acc = make_float4(0.f, 0.f, 0.f, 0.f);
    const float4* Wv = (const float4*)W + (long)(c * 128) * 256 + t;
#pragma unroll 8
    for (int r = 0; r < 128; r++) {
        float f = sF[r];
        float4 w = Wv[(long)r * 256];
        acc.x = fmaf(f, w.x, acc.x);
        acc.y = fmaf(f, w.y, acc.y);
        acc.z = fmaf(f, w.z, acc.z);
        acc.w = fmaf(f, w.w, acc.w);
    }
    ((float4*)part)[c * 256 + t] = acc;
}

__global__ void d0_reduce_kernel(const float* __restrict__ part,
                                 const float* __restrict__ bias,
                                 float* __restrict__ d0)
{
    const int col = threadIdx.x;
    float v = 0.f;
    for (int c = 0; c < 512; c++) v += part[c * 1024 + col];
    v += bias[col];
    d0[col] = fmaxf(v, 0.f);
}

// ---------------- d1 = relu(d0 @ W_d1 + b_d1) --------------------------------
__global__ void d1_kernel(const float* __restrict__ d0,
                          const float* __restrict__ W,
                          const float* __restrict__ bias,
                          float* __restrict__ d1)
{
    const int col = blockIdx.x * 32 + threadIdx.x % 32;
    const int rg  = threadIdx.x / 32;
    float acc = 0.f;
    for (int r = rg; r < 1024; r += 8)
        acc = fmaf(d0[r], W[r * 256 + col], acc);
    __shared__ float s[8][32];
    s[rg][threadIdx.x % 32] = acc;
    __syncthreads();
    if (rg == 0) {
        float v = acc;
#pragma unroll
        for (int g = 1; g < 8; g++) v += s[g][threadIdx.x];
        v += bias[col];
        d1[col] = fmaxf(v, 0.f);
    }
}

// ---------------- final: softmax(d1 @ W_d2) ----------------------------------
__global__ void final_kernel(const float* __restrict__ d1,
                             const float* __restrict__ W,
                             float* __restrict__ out)
{
    const int lane = threadIdx.x;
    float acc[8];
#pragma unroll
    for (int k = 0; k < 8; k++) acc[k] = 0.f;
    for (int r = lane; r < 256; r += 32) {
        float v = d1[r];
        const float* w = W + r * 8;
#pragma unroll
        for (int k = 0; k < 8; k++) acc[k] = fmaf(v, w[k], acc[k]);
    }
#pragma unroll
    for (int k = 0; k < 8; k++)
#pragma unroll
        for (int off = 16; off; off >>= 1)
            acc[k] += __shfl_down_sync(0xffffffffu, acc[k], off);
    if (lane == 0) {
        float mx = acc[0];
#pragma unroll
        for (int k = 1; k < 8; k++) mx = fmaxf(mx, acc[k]);
        float e[8], s = 0.f;
#pragma unroll
        for (int k = 0; k < 8; k++) { e[k] = expf(acc[k] - mx); s += e[k]; }
#pragma unroll
        for (int k = 0; k < 8; k++) out[k] = e[k] / s;
    }
}

// ---------------- launch ----------------------------------------------------
extern "C" void kernel_launch(void* const* d_in, const int* in_sizes, int n_in,
                              void* d_out, int out_size)
{
    const float* F_    = (const float*)d_in[0];
    const float* X     = (const float*)d_in[1];
    const float* W_e0  = (const float*)d_in[2];
    const float* b_e0  = (const float*)d_in[3];
    const float* W_e1  = (const float*)d_in[4];
    const float* b_e1  = (const float*)d_in[5];
    const float* W_e2  = (const float*)d_in[6];
    const float* b_e2  = (const float*)d_in[7];
    const float* W_d0  = (const float*)d_in[8];
    const float* b_d0  = (const float*)d_in[9];
    const float* W_d1  = (const float*)d_in[10];
    const float* b_d1  = (const float*)d_in[11];
    const float* W_d2  = (const float*)d_in[12];
    const float* pf    = (const float*)d_in[13];
    const float* memb  = (const float*)d_in[14];

    float* out    = (float*)d_out;
    float* E_out  = out;
    float* F_out  = out + (long)NN * 64;
    float* O_out  = out + (long)NN * 64 + (long)NN * NN;

    float *p_n2, *p_Fg, *p_part, *p_d0, *p_d1;
    __nv_bfloat16 *p_Xth, *p_Xtl, *p_Eh, *p_El;
    __nv_bfloat16 *p_ih, *p_il, *p_h0h, *p_h0l, *p_h1h, *p_h1l;
    __nv_bfloat16 *p_W0h, *p_W0l, *p_W1h, *p_W1l, *p_W2h, *p_W2l;
    cudaGetSymbolAddress((void**)&p_n2,   g_n2);
    cudaGetSymbolAddress((void**)&p_Fg,   g_Fg);
    cudaGetSymbolAddress((void**)&p_part, g_part);
    cudaGetSymbolAddress((void**)&p_d0,   g_d0);
    cudaGetSymbolAddress((void**)&p_d1,   g_d1);
    cudaGetSymbolAddress((void**)&p_Xth,  g_Xth);
    cudaGetSymbolAddress((void**)&p_Xtl,  g_Xtl);
    cudaGetSymbolAddress((void**)&p_Eh,   g_Eh);
    cudaGetSymbolAddress((void**)&p_El,   g_El);
    cudaGetSymbolAddress((void**)&p_ih,   g_ih);
    cudaGetSymbolAddress((void**)&p_il,   g_il);
    cudaGetSymbolAddress((void**)&p_h0h,  g_h0h);
    cudaGetSymbolAddress((void**)&p_h0l,  g_h0l);
    cudaGetSymbolAddress((void**)&p_h1h,  g_h1h);
    cudaGetSymbolAddress((void**)&p_h1l,  g_h1l);
    cudaGetSymbolAddress((void**)&p_W0h,  g_W0h);
    cudaGetSymbolAddress((void**)&p_W0l,  g_W0l);
    cudaGetSymbolAddress((void**)&p_W1h,  g_W1h);
    cudaGetSymbolAddress((void**)&p_W1l,  g_W1l);
    cudaGetSymbolAddress((void**)&p_W2h,  g_W2h);
    cudaGetSymbolAddress((void**)&p_W2l,  g_W2l);

    cudaFuncSetAttribute(gemm1_mma, cudaFuncAttributeMaxDynamicSharedMemorySize, G3_SMEM);
    cudaFuncSetAttribute(dist_mma,  cudaFuncAttributeMaxDynamicSharedMemorySize, DS_SMEM);
    cudaFuncSetAttribute(enc_mma<4,1,0,1>, cudaFuncAttributeMaxDynamicSharedMemorySize, 92160);
    cudaFuncSetAttribute(enc_mma<2,0,1,1>, cudaFuncAttributeMaxDynamicSharedMemorySize, 61440);

    // launch index 3 = gemm1_mma (ncu captures the 4th launch)
    tsplit_kernel<<<dim3(8, 256), dim3(32, 8)>>>(X, p_Xth, p_Xtl, NN, 256);      // 0
    tsplit_kernel<<<dim3(8, 8),  dim3(32, 8)>>>(W_e0, p_W0h, p_W0l, 256, 256);   // 1
    tsplit_kernel<<<dim3(4, 8),  dim3(32, 8)>>>(W_e1, p_W1h, p_W1l, 256, 128);   // 2
    gemm1_mma<<<dim3(2, 128), 256, G3_SMEM>>>(F_, p_Xth, p_Xtl, p_ih, p_il);     // 3
    tsplit_kernel<<<dim3(2, 4),  dim3(32, 8)>>>(W_e2, p_W2h, p_W2l, 128, 64);    // 4

    // 2) h0 = tanh(inp @ W_e0 + b)
    enc_mma<4,1,0,1><<<dim3(2, 128), 256, 92160>>>(
        p_ih, p_il, p_W0h, p_W0l, b_e0, nullptr, p_h0h, p_h0l, 256, 256, 256, 256);
    // 3) h1 = tanh(h0 @ W_e1 + b)
    enc_mma<4,1,0,1><<<dim3(1, 128), 256, 92160>>>(
        p_h0h, p_h0l, p_W1h, p_W1l, b_e1, nullptr, p_h1h, p_h1l, 256, 256, 256, 128);
    // 4) E = h1 @ W_e2 + b -> fp32 to d_out + splits
    enc_mma<2,0,1,1><<<dim3(1, 128), 256, 61440>>>(
        p_h1h, p_h1l, p_W2h, p_W2l, b_e2, E_out, p_Eh, p_El, 128, 128, 128, 64);

    // 5) row norms
    n2_kernel<<<NN / 8, 256>>>(E_out, p_n2);
    // 6) new_force = dist(E) * pf (HMMA, occ 2) -> d_out
    dist_mma<<<dim3(NN / 128, NN / 128), 256, DS_SMEM>>>(p_Eh, p_El, p_n2, pf, F_out);
    // 7) Fg = new_force @ members
    fg_kernel<<<NN / 32, 256>>>(F_out, memb, p_Fg);
    // 8) d0 = relu(Fg @ W_d0 + b_d0)
    d0_partial_kernel<<<512, 256>>>(p_Fg, W_d0, p_part);
    d0_reduce_kernel<<<1, 1024>>>(p_part, b_d0, p_d0);
    // 9) d1 = relu(d0 @ W_d1 + b_d1)
    d1_kernel<<<8, 256>>>(p_d0, W_d1, b_d1, p_d1);
    // 10) out = softmax(d1 @ W_d2)
    final_kernel<<<1, 32>>>(p_d1, W_d2, O_out);
}